// round 5
// baseline (speedup 1.0000x reference)
#include <cuda_runtime.h>
#include <cuda_bf16.h>
#include <cstdint>

// Problem dims (fixed)
#define Dm   256
#define Bsz  4
#define Sq   512
#define HWk  4096
#define NH   8
#define HD   32
#define NSPLIT 2

// Scratch (no cudaMalloc allowed)
__device__ float g_Q[Bsz * Sq * Dm];
__device__ float g_K[Bsz * HWk * Dm];
__device__ float g_V[Bsz * HWk * Dm];
__device__ float g_A[Bsz * Sq * Dm];
__device__ float g_Po[Bsz * NH * NSPLIT * Sq * HD];
__device__ float g_Pm[Bsz * NH * NSPLIT * Sq];
__device__ float g_Pl[Bsz * NH * NSPLIT * Sq];

__device__ __forceinline__ uint32_t cvt_tf32(float x) {
    uint32_t r;
    asm("cvt.rna.tf32.f32 %0, %1;" : "=r"(r) : "f"(x));
    return r;
}

__device__ __forceinline__ void mma_tf32(float c[4], const uint32_t a[4],
                                         uint32_t b0, uint32_t b1) {
    asm volatile(
        "mma.sync.aligned.m16n8k8.row.col.f32.tf32.tf32.f32 "
        "{%0,%1,%2,%3}, {%4,%5,%6,%7}, {%8,%9}, {%0,%1,%2,%3};"
        : "+f"(c[0]), "+f"(c[1]), "+f"(c[2]), "+f"(c[3])
        : "r"(a[0]), "r"(a[1]), "r"(a[2]), "r"(a[3]), "r"(b0), "r"(b1));
}

#define MPAD 132
#define WPAD 36

// ---------------------------------------------------------------------------
// FUSED KV projection: one launch, grid.z in [0,8): b = z>>1, K/V = z&1.
// C[b,m,n] = sum_k kv[b,k,m] * W[n,k] + bias[n].  Double-buffered mainloop.
// BM=128, BN=128, BK=32, 8 warps (4m x 2n), warp tile 32x64.
// ---------------------------------------------------------------------------
__global__ __launch_bounds__(256)
void gemm_kv_fused(const float* __restrict__ KVin,
                   const float* __restrict__ Wk, const float* __restrict__ bk,
                   const float* __restrict__ Wv, const float* __restrict__ bv,
                   float* __restrict__ Kout, float* __restrict__ Vout)
{
    const int z = blockIdx.z;
    const int b = z >> 1;
    const int isv = z & 1;
    const float* A    = KVin + (size_t)b * Dm * HWk;   // A[k][m], lda = HWk
    const float* W    = isv ? Wv : Wk;
    const float* bias = isv ? bv : bk;
    float* C = (isv ? Vout : Kout) + (size_t)b * HWk * Dm;

    __shared__ uint32_t As[2][32][MPAD];   // [k][m]
    __shared__ uint32_t Ws[2][128][WPAD];  // [n][k]

    const int bm = blockIdx.x * 128;
    const int bn = blockIdx.y * 128;
    const int tid  = threadIdx.x;
    const int warp = tid >> 5;
    const int lane = tid & 31;
    const int gid  = lane >> 2;
    const int tig  = lane & 3;
    const int wm = (warp >> 1) * 32;
    const int wn = (warp & 1) * 64;

    float acc[2][8][4];
#pragma unroll
    for (int mf = 0; mf < 2; mf++)
#pragma unroll
        for (int nb = 0; nb < 8; nb++)
#pragma unroll
            for (int j = 0; j < 4; j++) acc[mf][nb][j] = 0.f;

    const int kk = tid >> 3;          // 0..31 A k-row
    const int mc = (tid & 7) * 16;    // 0..120
    const int rr = tid >> 1;          // 0..127 W row
    const int kc = (tid & 1) * 16;    // 0,16

    float4 ra[4], rw[4];
    // preload tile 0
#pragma unroll
    for (int i = 0; i < 4; i++) {
        ra[i] = *(const float4*)(A + (size_t)kk * HWk + bm + mc + 4 * i);
        rw[i] = *(const float4*)(W + (size_t)(bn + rr) * Dm + kc + 4 * i);
    }
#pragma unroll
    for (int i = 0; i < 4; i++) {
        uint4 u;
        u.x = cvt_tf32(ra[i].x); u.y = cvt_tf32(ra[i].y);
        u.z = cvt_tf32(ra[i].z); u.w = cvt_tf32(ra[i].w);
        *(uint4*)&As[0][kk][mc + 4 * i] = u;
        uint4 w;
        w.x = cvt_tf32(rw[i].x); w.y = cvt_tf32(rw[i].y);
        w.z = cvt_tf32(rw[i].z); w.w = cvt_tf32(rw[i].w);
        *(uint4*)&Ws[0][rr][kc + 4 * i] = w;
    }
    __syncthreads();

#pragma unroll
    for (int it = 0; it < 8; it++) {
        const int cur = it & 1;
        const bool more = (it + 1) < 8;
        if (more) {
            const int k0n = (it + 1) * 32;
#pragma unroll
            for (int i = 0; i < 4; i++) {
                ra[i] = *(const float4*)(A + (size_t)(k0n + kk) * HWk + bm + mc + 4 * i);
                rw[i] = *(const float4*)(W + (size_t)(bn + rr) * Dm + k0n + kc + 4 * i);
            }
        }

#pragma unroll
        for (int kb = 0; kb < 4; kb++) {
            uint32_t a[2][4];
#pragma unroll
            for (int mf = 0; mf < 2; mf++) {
                a[mf][0] = As[cur][kb * 8 + tig    ][wm + mf * 16 + gid    ];
                a[mf][1] = As[cur][kb * 8 + tig    ][wm + mf * 16 + gid + 8];
                a[mf][2] = As[cur][kb * 8 + tig + 4][wm + mf * 16 + gid    ];
                a[mf][3] = As[cur][kb * 8 + tig + 4][wm + mf * 16 + gid + 8];
            }
#pragma unroll
            for (int nb = 0; nb < 8; nb++) {
                uint32_t b0 = Ws[cur][wn + nb * 8 + gid][kb * 8 + tig    ];
                uint32_t b1 = Ws[cur][wn + nb * 8 + gid][kb * 8 + tig + 4];
                mma_tf32(acc[0][nb], a[0], b0, b1);
                mma_tf32(acc[1][nb], a[1], b0, b1);
            }
        }

        if (more) {
            const int nxt = cur ^ 1;
#pragma unroll
            for (int i = 0; i < 4; i++) {
                uint4 u;
                u.x = cvt_tf32(ra[i].x); u.y = cvt_tf32(ra[i].y);
                u.z = cvt_tf32(ra[i].z); u.w = cvt_tf32(ra[i].w);
                *(uint4*)&As[nxt][kk][mc + 4 * i] = u;
                uint4 w;
                w.x = cvt_tf32(rw[i].x); w.y = cvt_tf32(rw[i].y);
                w.z = cvt_tf32(rw[i].z); w.w = cvt_tf32(rw[i].w);
                *(uint4*)&Ws[nxt][rr][kc + 4 * i] = w;
            }
        }
        __syncthreads();
    }

#pragma unroll
    for (int mf = 0; mf < 2; mf++) {
        const int row = bm + wm + mf * 16 + gid;
#pragma unroll
        for (int nb = 0; nb < 8; nb++) {
            const int col = bn + wn + nb * 8 + 2 * tig;
            const float b0 = bias[col], b1 = bias[col + 1];
            *(float2*)(C + (size_t)row * Dm + col) =
                make_float2(acc[mf][nb][0] + b0, acc[mf][nb][1] + b1);
            *(float2*)(C + (size_t)(row + 8) * Dm + col) =
                make_float2(acc[mf][nb][2] + b0, acc[mf][nb][3] + b1);
        }
    }
}

// ---------------------------------------------------------------------------
// tf32 GEMM for Q/O projections (A row-major), as in R3.
// ---------------------------------------------------------------------------
__global__ __launch_bounds__(256)
void gemm_tf32_rm(const float* __restrict__ A, const float* __restrict__ W,
                  const float* __restrict__ bias, float* __restrict__ C)
{
    __shared__ uint32_t As[32][MPAD];
    __shared__ uint32_t Ws[128][WPAD];

    const int bm = blockIdx.x * 128;
    const int bn = blockIdx.y * 128;
    const int tid  = threadIdx.x;
    const int warp = tid >> 5;
    const int lane = tid & 31;
    const int gid  = lane >> 2;
    const int tig  = lane & 3;
    const int wm = (warp >> 1) * 32;
    const int wn = (warp & 1) * 64;

    float acc[2][8][4];
#pragma unroll
    for (int mf = 0; mf < 2; mf++)
#pragma unroll
        for (int nb = 0; nb < 8; nb++)
#pragma unroll
            for (int j = 0; j < 4; j++) acc[mf][nb][j] = 0.f;

    const int rr = tid >> 1;
    const int kc = (tid & 1) * 16;

    for (int k0 = 0; k0 < Dm; k0 += 32) {
        __syncthreads();
#pragma unroll
        for (int i = 0; i < 4; i++) {
            float4 v = *(const float4*)(A + (size_t)(bm + rr) * Dm + k0 + kc + 4 * i);
            As[kc + 4 * i + 0][rr] = cvt_tf32(v.x);
            As[kc + 4 * i + 1][rr] = cvt_tf32(v.y);
            As[kc + 4 * i + 2][rr] = cvt_tf32(v.z);
            As[kc + 4 * i + 3][rr] = cvt_tf32(v.w);
            float4 w = *(const float4*)(W + (size_t)(bn + rr) * Dm + k0 + kc + 4 * i);
            uint4 u;
            u.x = cvt_tf32(w.x); u.y = cvt_tf32(w.y);
            u.z = cvt_tf32(w.z); u.w = cvt_tf32(w.w);
            *(uint4*)&Ws[rr][kc + 4 * i] = u;
        }
        __syncthreads();

#pragma unroll
        for (int kb = 0; kb < 4; kb++) {
            uint32_t a[2][4];
#pragma unroll
            for (int mf = 0; mf < 2; mf++) {
                a[mf][0] = As[kb * 8 + tig    ][wm + mf * 16 + gid    ];
                a[mf][1] = As[kb * 8 + tig    ][wm + mf * 16 + gid + 8];
                a[mf][2] = As[kb * 8 + tig + 4][wm + mf * 16 + gid    ];
                a[mf][3] = As[kb * 8 + tig + 4][wm + mf * 16 + gid + 8];
            }
#pragma unroll
            for (int nb = 0; nb < 8; nb++) {
                uint32_t b0 = Ws[wn + nb * 8 + gid][kb * 8 + tig    ];
                uint32_t b1 = Ws[wn + nb * 8 + gid][kb * 8 + tig + 4];
                mma_tf32(acc[0][nb], a[0], b0, b1);
                mma_tf32(acc[1][nb], a[1], b0, b1);
            }
        }
    }

#pragma unroll
    for (int mf = 0; mf < 2; mf++) {
        const int row = bm + wm + mf * 16 + gid;
#pragma unroll
        for (int nb = 0; nb < 8; nb++) {
            const int col = bn + wn + nb * 8 + 2 * tig;
            const float b0 = bias[col], b1 = bias[col + 1];
            *(float2*)(C + (size_t)row * Dm + col) =
                make_float2(acc[mf][nb][0] + b0, acc[mf][nb][1] + b1);
            *(float2*)(C + (size_t)(row + 8) * Dm + col) =
                make_float2(acc[mf][nb][2] + b0, acc[mf][nb][3] + b1);
        }
    }
}

// ---------------------------------------------------------------------------
// tf32 flash attention, split-KV, double-buffered K/V tiles.
// ---------------------------------------------------------------------------
#define KST 36
#define VST 36

__global__ __launch_bounds__(128)
void attn_mma(const float* __restrict__ Q, const float* __restrict__ K,
              const float* __restrict__ V, float* __restrict__ Po,
              float* __restrict__ Pm, float* __restrict__ Pl)
{
    const int h  = blockIdx.y;
    const int bz = blockIdx.z;
    const int b  = bz >> 1;
    const int sp = bz & 1;
    const int q0 = blockIdx.x * 64;

    __shared__ uint32_t Ks[2][64][KST];
    __shared__ uint32_t Vs[2][64][VST];

    const int tid  = threadIdx.x;
    const int warp = tid >> 5;
    const int lane = tid & 31;
    const int gid  = lane >> 2;
    const int tig  = lane & 3;

    const float scale = 0.17677669529663687f;

    uint32_t qa[4][4];
    {
        const float* Qb = Q + ((size_t)(b * Sq + q0 + warp * 16)) * Dm + h * HD;
#pragma unroll
        for (int kb = 0; kb < 4; kb++) {
            qa[kb][0] = cvt_tf32(Qb[(size_t)gid       * Dm + kb * 8 + tig    ] * scale);
            qa[kb][1] = cvt_tf32(Qb[(size_t)(gid + 8) * Dm + kb * 8 + tig    ] * scale);
            qa[kb][2] = cvt_tf32(Qb[(size_t)gid       * Dm + kb * 8 + tig + 4] * scale);
            qa[kb][3] = cvt_tf32(Qb[(size_t)(gid + 8) * Dm + kb * 8 + tig + 4] * scale);
        }
    }

    float m_lo = -1e30f, m_hi = -1e30f;
    float l_lo = 0.f,    l_hi = 0.f;
    float o[4][4];
#pragma unroll
    for (int nb = 0; nb < 4; nb++)
#pragma unroll
        for (int i = 0; i < 4; i++) o[nb][i] = 0.f;

    const float* Kb = K + (size_t)b * HWk * Dm + h * HD;
    const float* Vb = V + (size_t)b * HWk * Dm + h * HD;

    const int lrow = tid >> 1;
    const int lcol = (tid & 1) * 16;

    const int jbeg = sp * (HWk / NSPLIT);
    const int jend = jbeg + (HWk / NSPLIT);

    float4 rk[4], rv[4];
    // preload first tile
#pragma unroll
    for (int i = 0; i < 4; i++) {
        rk[i] = *(const float4*)(Kb + (size_t)(jbeg + lrow) * Dm + lcol + 4 * i);
        rv[i] = *(const float4*)(Vb + (size_t)(jbeg + lrow) * Dm + lcol + 4 * i);
    }
#pragma unroll
    for (int i = 0; i < 4; i++) {
        uint4 ku, vu;
        ku.x = cvt_tf32(rk[i].x); ku.y = cvt_tf32(rk[i].y);
        ku.z = cvt_tf32(rk[i].z); ku.w = cvt_tf32(rk[i].w);
        vu.x = cvt_tf32(rv[i].x); vu.y = cvt_tf32(rv[i].y);
        vu.z = cvt_tf32(rv[i].z); vu.w = cvt_tf32(rv[i].w);
        *(uint4*)&Ks[0][lrow][lcol + 4 * i] = ku;
        *(uint4*)&Vs[0][lrow][lcol + 4 * i] = vu;
    }
    __syncthreads();

    int stage = 0;
    for (int j0 = jbeg; j0 < jend; j0 += 64) {
        const bool more = (j0 + 64) < jend;
        if (more) {
#pragma unroll
            for (int i = 0; i < 4; i++) {
                rk[i] = *(const float4*)(Kb + (size_t)(j0 + 64 + lrow) * Dm + lcol + 4 * i);
                rv[i] = *(const float4*)(Vb + (size_t)(j0 + 64 + lrow) * Dm + lcol + 4 * i);
            }
        }

        // ---- S = Q K^T ----
        float s[8][4];
#pragma unroll
        for (int nb = 0; nb < 8; nb++)
#pragma unroll
            for (int i = 0; i < 4; i++) s[nb][i] = 0.f;

#pragma unroll
        for (int kb = 0; kb < 4; kb++) {
#pragma unroll
            for (int nb = 0; nb < 8; nb++) {
                uint32_t b0 = Ks[stage][nb * 8 + gid][kb * 8 + tig];
                uint32_t b1 = Ks[stage][nb * 8 + gid][kb * 8 + tig + 4];
                mma_tf32(s[nb], qa[kb], b0, b1);
            }
        }

        // ---- online softmax ----
        float tmax_lo = -1e30f, tmax_hi = -1e30f;
#pragma unroll
        for (int nb = 0; nb < 8; nb++) {
            tmax_lo = fmaxf(tmax_lo, fmaxf(s[nb][0], s[nb][1]));
            tmax_hi = fmaxf(tmax_hi, fmaxf(s[nb][2], s[nb][3]));
        }
        tmax_lo = fmaxf(tmax_lo, __shfl_xor_sync(0xffffffffu, tmax_lo, 1));
        tmax_lo = fmaxf(tmax_lo, __shfl_xor_sync(0xffffffffu, tmax_lo, 2));
        tmax_hi = fmaxf(tmax_hi, __shfl_xor_sync(0xffffffffu, tmax_hi, 1));
        tmax_hi = fmaxf(tmax_hi, __shfl_xor_sync(0xffffffffu, tmax_hi, 2));

        const float mn_lo = fmaxf(m_lo, tmax_lo);
        const float mn_hi = fmaxf(m_hi, tmax_hi);
        const float al_lo = __expf(m_lo - mn_lo);
        const float al_hi = __expf(m_hi - mn_hi);
        m_lo = mn_lo; m_hi = mn_hi;
        l_lo *= al_lo; l_hi *= al_hi;
#pragma unroll
        for (int nb = 0; nb < 4; nb++) {
            o[nb][0] *= al_lo; o[nb][1] *= al_lo;
            o[nb][2] *= al_hi; o[nb][3] *= al_hi;
        }

        // ---- exp + O += P V (c-frag as a-frag, V rows permuted) ----
#pragma unroll
        for (int kb = 0; kb < 8; kb++) {
            const float p0 = __expf(s[kb][0] - mn_lo);
            const float p1 = __expf(s[kb][1] - mn_lo);
            const float p2 = __expf(s[kb][2] - mn_hi);
            const float p3 = __expf(s[kb][3] - mn_hi);
            l_lo += p0 + p1;
            l_hi += p2 + p3;
            uint32_t pa[4];
            pa[0] = cvt_tf32(p0);
            pa[1] = cvt_tf32(p2);
            pa[2] = cvt_tf32(p1);
            pa[3] = cvt_tf32(p3);
#pragma unroll
            for (int nb = 0; nb < 4; nb++) {
                uint32_t b0 = Vs[stage][kb * 8 + 2 * tig    ][nb * 8 + gid];
                uint32_t b1 = Vs[stage][kb * 8 + 2 * tig + 1][nb * 8 + gid];
                mma_tf32(o[nb], pa, b0, b1);
            }
        }

        if (more) {
            const int nxt = stage ^ 1;
#pragma unroll
            for (int i = 0; i < 4; i++) {
                uint4 ku, vu;
                ku.x = cvt_tf32(rk[i].x); ku.y = cvt_tf32(rk[i].y);
                ku.z = cvt_tf32(rk[i].z); ku.w = cvt_tf32(rk[i].w);
                vu.x = cvt_tf32(rv[i].x); vu.y = cvt_tf32(rv[i].y);
                vu.z = cvt_tf32(rv[i].z); vu.w = cvt_tf32(rv[i].w);
                *(uint4*)&Ks[nxt][lrow][lcol + 4 * i] = ku;
                *(uint4*)&Vs[nxt][lrow][lcol + 4 * i] = vu;
            }
        }
        __syncthreads();
        stage ^= 1;
    }

    l_lo += __shfl_xor_sync(0xffffffffu, l_lo, 1);
    l_lo += __shfl_xor_sync(0xffffffffu, l_lo, 2);
    l_hi += __shfl_xor_sync(0xffffffffu, l_hi, 1);
    l_hi += __shfl_xor_sync(0xffffffffu, l_hi, 2);

    const int row0 = (((b * NH + h) * NSPLIT) + sp) * Sq + q0 + warp * 16;
#pragma unroll
    for (int nb = 0; nb < 4; nb++) {
        *(float2*)(Po + (size_t)(row0 + gid)     * HD + nb * 8 + 2 * tig) =
            make_float2(o[nb][0], o[nb][1]);
        *(float2*)(Po + (size_t)(row0 + gid + 8) * HD + nb * 8 + 2 * tig) =
            make_float2(o[nb][2], o[nb][3]);
    }
    if (tig == 0) {
        Pm[row0 + gid]     = m_lo;  Pl[row0 + gid]     = l_lo;
        Pm[row0 + gid + 8] = m_hi;  Pl[row0 + gid + 8] = l_hi;
    }
}

// ---------------------------------------------------------------------------
// combine split partials -> (B,S,D)
// ---------------------------------------------------------------------------
__global__ __launch_bounds__(256)
void attn_combine(const float* __restrict__ Po, const float* __restrict__ Pm,
                  const float* __restrict__ Pl, float* __restrict__ Aout)
{
    const int t = blockIdx.x * 256 + threadIdx.x;
    const int row = t >> 2;
    const int dc  = (t & 3) * 8;
    const int bh  = row / Sq;
    const int q   = row % Sq;
    const int b   = bh / NH;
    const int h   = bh % NH;

    const size_t i0 = (size_t)(bh * NSPLIT + 0) * Sq + q;
    const size_t i1 = (size_t)(bh * NSPLIT + 1) * Sq + q;
    const float m0 = Pm[i0], m1 = Pm[i1];
    const float l0 = Pl[i0], l1 = Pl[i1];
    const float m  = fmaxf(m0, m1);
    const float w0 = __expf(m0 - m);
    const float w1 = __expf(m1 - m);
    const float inv = 1.f / (l0 * w0 + l1 * w1);

    const float* o0 = Po + i0 * HD + dc;
    const float* o1 = Po + i1 * HD + dc;
    float* out = Aout + ((size_t)(b * Sq + q)) * Dm + h * HD + dc;
#pragma unroll
    for (int i = 0; i < 8; i += 4) {
        float4 a = *(const float4*)(o0 + i);
        float4 c = *(const float4*)(o1 + i);
        float4 r;
        r.x = (a.x * w0 + c.x * w1) * inv;
        r.y = (a.y * w0 + c.y * w1) * inv;
        r.z = (a.z * w0 + c.z * w1) * inv;
        r.w = (a.w * w0 + c.w * w1) * inv;
        *(float4*)(out + i) = r;
    }
}

// ---------------------------------------------------------------------------
// Launch
// ---------------------------------------------------------------------------
extern "C" void kernel_launch(void* const* d_in, const int* in_sizes, int n_in,
                              void* d_out, int out_size)
{
    const float* query = (const float*)d_in[0];
    const float* keyv  = (const float*)d_in[1];
    const float* Wq    = (const float*)d_in[2];
    const float* bq    = (const float*)d_in[3];
    const float* Wk    = (const float*)d_in[4];
    const float* bk    = (const float*)d_in[5];
    const float* Wv    = (const float*)d_in[6];
    const float* bv    = (const float*)d_in[7];
    const float* Wo    = (const float*)d_in[8];
    const float* bo    = (const float*)d_in[9];
    float* out = (float*)d_out;

    float *dQ, *dK, *dV, *dA, *dPo, *dPm, *dPl;
    cudaGetSymbolAddress((void**)&dQ, g_Q);
    cudaGetSymbolAddress((void**)&dK, g_K);
    cudaGetSymbolAddress((void**)&dV, g_V);
    cudaGetSymbolAddress((void**)&dA, g_A);
    cudaGetSymbolAddress((void**)&dPo, g_Po);
    cudaGetSymbolAddress((void**)&dPm, g_Pm);
    cudaGetSymbolAddress((void**)&dPl, g_Pl);

    // Q projection
    {
        dim3 grid((Bsz * Sq) / 128, Dm / 128);
        gemm_tf32_rm<<<grid, 256>>>(query, Wq, bq, dQ);
    }
    // fused K+V projections, all batches, ONE launch
    {
        dim3 grid(HWk / 128, Dm / 128, Bsz * 2);
        gemm_kv_fused<<<grid, 256>>>(keyv, Wk, bk, Wv, bv, dK, dV);
    }
    // attention (split-KV)
    {
        dim3 grid(Sq / 64, NH, Bsz * NSPLIT);
        attn_mma<<<grid, 128>>>(dQ, dK, dV, dPo, dPm, dPl);
    }
    // combine
    {
        attn_combine<<<(Bsz * NH * Sq * 4) / 256, 256>>>(dPo, dPm, dPl, dA);
    }
    // output projection -> d_out
    {
        dim3 grid((Bsz * Sq) / 128, Dm / 128);
        gemm_tf32_rm<<<grid, 256>>>(dA, Wo, bo, out);
    }
}

// round 6
// speedup vs baseline: 1.2999x; 1.2999x over previous
#include <cuda_runtime.h>
#include <cuda_fp16.h>
#include <cstdint>

// Problem dims (fixed)
#define Dm   256
#define Bsz  4
#define Sq   512
#define HWk  4096
#define NH   8
#define HD   32
#define NSPLIT 2

// Scratch (no cudaMalloc allowed)
__device__ float g_Q[Bsz * Sq * Dm];
__device__ float g_K[Bsz * HWk * Dm];
__device__ float g_V[Bsz * HWk * Dm];
__device__ float g_A[Bsz * Sq * Dm];
__device__ float g_Po[Bsz * NH * NSPLIT * Sq * HD];
__device__ float g_Pm[Bsz * NH * NSPLIT * Sq];
__device__ float g_Pl[Bsz * NH * NSPLIT * Sq];

__device__ __forceinline__ uint32_t f2h2(float x, float y) {
    __half2 h = __floats2half2_rn(x, y);
    return *reinterpret_cast<uint32_t*>(&h);
}

// mma.m16n8k16 f16 inputs, f32 accumulate
__device__ __forceinline__ void mma_f16(float c[4], const uint32_t a[4],
                                        uint32_t b0, uint32_t b1) {
    asm volatile(
        "mma.sync.aligned.m16n8k16.row.col.f32.f16.f16.f32 "
        "{%0,%1,%2,%3}, {%4,%5,%6,%7}, {%8,%9}, {%0,%1,%2,%3};"
        : "+f"(c[0]), "+f"(c[1]), "+f"(c[2]), "+f"(c[3])
        : "r"(a[0]), "r"(a[1]), "r"(a[2]), "r"(a[3]), "r"(b0), "r"(b1));
}

// stride (uint32 words) for [row][k2] operand tiles: 16 data + 4 pad
// (gid*20 + tig) mod 32 hits 32 distinct banks for gid<8, tig<4.
#define KS2 20
// stride for V-transpose tile [d][key2]: 32 data + 4 pad (36 mod 32 = 4)
#define VS2 36

// ---------------------------------------------------------------------------
// FUSED KV projection (fp16 mma): grid.z in [0,8): b = z>>1, K/V = z&1.
// C[b,m,n] = sum_k kv[b,k,m] * W[n,k] + bias[n]. Double-buffered.
// BM=128, BN=128, BK=32, 8 warps (4m x 2n), warp tile 32x64.
// ---------------------------------------------------------------------------
__global__ __launch_bounds__(256)
void gemm_kv_fused(const float* __restrict__ KVin,
                   const float* __restrict__ Wk, const float* __restrict__ bk,
                   const float* __restrict__ Wv, const float* __restrict__ bv,
                   float* __restrict__ Kout, float* __restrict__ Vout)
{
    const int z = blockIdx.z;
    const int b = z >> 1;
    const int isv = z & 1;
    const float* A    = KVin + (size_t)b * Dm * HWk;   // A[k][m], lda = HWk
    const float* W    = isv ? Wv : Wk;
    const float* bias = isv ? bv : bk;
    float* C = (isv ? Vout : Kout) + (size_t)b * HWk * Dm;

    __shared__ uint32_t As2[2][128][KS2];   // [m][k2] half2-packed
    __shared__ uint32_t Ws2[2][128][KS2];   // [n][k2]

    const int bm = blockIdx.x * 128;
    const int bn = blockIdx.y * 128;
    const int tid  = threadIdx.x;
    const int warp = tid >> 5;
    const int lane = tid & 31;
    const int gid  = lane >> 2;
    const int tig  = lane & 3;
    const int wm = (warp >> 1) * 32;
    const int wn = (warp & 1) * 64;

    float acc[2][8][4];
#pragma unroll
    for (int mf = 0; mf < 2; mf++)
#pragma unroll
        for (int nb = 0; nb < 8; nb++)
#pragma unroll
            for (int j = 0; j < 4; j++) acc[mf][nb][j] = 0.f;

    // A loader: k2 = tid>>4 (0..15), mc = (tid&15)*8
    const int k2 = tid >> 4;
    const int mc = (tid & 15) * 8;
    // W loader: rr = tid>>1 (0..127), kc = (tid&1)*16 (float offset)
    const int rr = tid >> 1;
    const int kc = (tid & 1) * 16;

    float4 ra0[2], ra1[2], rw[4];

    auto loadA = [&](int k0) {
#pragma unroll
        for (int i = 0; i < 2; i++) {
            ra0[i] = *(const float4*)(A + (size_t)(k0 + 2 * k2)     * HWk + bm + mc + 4 * i);
            ra1[i] = *(const float4*)(A + (size_t)(k0 + 2 * k2 + 1) * HWk + bm + mc + 4 * i);
        }
#pragma unroll
        for (int i = 0; i < 4; i++)
            rw[i] = *(const float4*)(W + (size_t)(bn + rr) * Dm + k0 + kc + 4 * i);
    };
    auto storeA = [&](int st) {
        const float* lo = (const float*)&ra0[0];
        const float* hi = (const float*)&ra1[0];
#pragma unroll
        for (int i = 0; i < 8; i++)
            As2[st][mc + i][k2] = f2h2(lo[i], hi[i]);
        const float* w = (const float*)&rw[0];
#pragma unroll
        for (int j = 0; j < 8; j++)
            Ws2[st][rr][(tid & 1) * 8 + j] = f2h2(w[2 * j], w[2 * j + 1]);
    };

    loadA(0);
    storeA(0);
    __syncthreads();

#pragma unroll
    for (int it = 0; it < 8; it++) {
        const int cur = it & 1;
        const bool more = (it + 1) < 8;
        if (more) loadA((it + 1) * 32);

#pragma unroll
        for (int kb = 0; kb < 2; kb++) {
            uint32_t a[2][4];
#pragma unroll
            for (int mf = 0; mf < 2; mf++) {
                const int m = wm + mf * 16 + gid;
                a[mf][0] = As2[cur][m    ][kb * 8 + tig    ];
                a[mf][1] = As2[cur][m + 8][kb * 8 + tig    ];
                a[mf][2] = As2[cur][m    ][kb * 8 + tig + 4];
                a[mf][3] = As2[cur][m + 8][kb * 8 + tig + 4];
            }
#pragma unroll
            for (int nb = 0; nb < 8; nb++) {
                uint32_t b0 = Ws2[cur][wn + nb * 8 + gid][kb * 8 + tig    ];
                uint32_t b1 = Ws2[cur][wn + nb * 8 + gid][kb * 8 + tig + 4];
                mma_f16(acc[0][nb], a[0], b0, b1);
                mma_f16(acc[1][nb], a[1], b0, b1);
            }
        }

        if (more) storeA(cur ^ 1);
        __syncthreads();
    }

#pragma unroll
    for (int mf = 0; mf < 2; mf++) {
        const int row = bm + wm + mf * 16 + gid;
#pragma unroll
        for (int nb = 0; nb < 8; nb++) {
            const int col = bn + wn + nb * 8 + 2 * tig;
            const float b0 = bias[col], b1 = bias[col + 1];
            *(float2*)(C + (size_t)row * Dm + col) =
                make_float2(acc[mf][nb][0] + b0, acc[mf][nb][1] + b1);
            *(float2*)(C + (size_t)(row + 8) * Dm + col) =
                make_float2(acc[mf][nb][2] + b0, acc[mf][nb][3] + b1);
        }
    }
}

// ---------------------------------------------------------------------------
// Q/O projection (fp16 mma): A row-major. BM=64, BN=128, 4 warps (2m x 2n).
// ---------------------------------------------------------------------------
__global__ __launch_bounds__(128)
void gemm_rm_f16(const float* __restrict__ A, const float* __restrict__ W,
                 const float* __restrict__ bias, float* __restrict__ C)
{
    __shared__ uint32_t As2[64][KS2];
    __shared__ uint32_t Ws2[128][KS2];

    const int bm = blockIdx.x * 64;
    const int bn = blockIdx.y * 128;
    const int tid  = threadIdx.x;
    const int warp = tid >> 5;
    const int lane = tid & 31;
    const int gid  = lane >> 2;
    const int tig  = lane & 3;
    const int wm = (warp >> 1) * 32;
    const int wn = (warp & 1) * 64;

    float acc[2][8][4];
#pragma unroll
    for (int mf = 0; mf < 2; mf++)
#pragma unroll
        for (int nb = 0; nb < 8; nb++)
#pragma unroll
            for (int j = 0; j < 4; j++) acc[mf][nb][j] = 0.f;

    const int ar = tid >> 1;          // 0..63
    const int ak = (tid & 1) * 16;    // float k offset

    for (int k0 = 0; k0 < Dm; k0 += 32) {
        __syncthreads();
        {
            float4 v[4];
#pragma unroll
            for (int i = 0; i < 4; i++)
                v[i] = *(const float4*)(A + (size_t)(bm + ar) * Dm + k0 + ak + 4 * i);
            const float* f = (const float*)&v[0];
#pragma unroll
            for (int j = 0; j < 8; j++)
                As2[ar][(tid & 1) * 8 + j] = f2h2(f[2 * j], f[2 * j + 1]);
        }
        {
            float4 v[8];
#pragma unroll
            for (int i = 0; i < 8; i++)
                v[i] = *(const float4*)(W + (size_t)(bn + tid) * Dm + k0 + 4 * i);
            const float* f = (const float*)&v[0];
#pragma unroll
            for (int j = 0; j < 16; j++)
                Ws2[tid][j] = f2h2(f[2 * j], f[2 * j + 1]);
        }
        __syncthreads();

#pragma unroll
        for (int kb = 0; kb < 2; kb++) {
            uint32_t a[2][4];
#pragma unroll
            for (int mf = 0; mf < 2; mf++) {
                const int m = wm + mf * 16 + gid;
                a[mf][0] = As2[m    ][kb * 8 + tig    ];
                a[mf][1] = As2[m + 8][kb * 8 + tig    ];
                a[mf][2] = As2[m    ][kb * 8 + tig + 4];
                a[mf][3] = As2[m + 8][kb * 8 + tig + 4];
            }
#pragma unroll
            for (int nb = 0; nb < 8; nb++) {
                uint32_t b0 = Ws2[wn + nb * 8 + gid][kb * 8 + tig    ];
                uint32_t b1 = Ws2[wn + nb * 8 + gid][kb * 8 + tig + 4];
                mma_f16(acc[0][nb], a[0], b0, b1);
                mma_f16(acc[1][nb], a[1], b0, b1);
            }
        }
    }

#pragma unroll
    for (int mf = 0; mf < 2; mf++) {
        const int row = bm + wm + mf * 16 + gid;
#pragma unroll
        for (int nb = 0; nb < 8; nb++) {
            const int col = bn + wn + nb * 8 + 2 * tig;
            const float b0 = bias[col], b1 = bias[col + 1];
            *(float2*)(C + (size_t)row * Dm + col) =
                make_float2(acc[mf][nb][0] + b0, acc[mf][nb][1] + b1);
            *(float2*)(C + (size_t)(row + 8) * Dm + col) =
                make_float2(acc[mf][nb][2] + b0, acc[mf][nb][3] + b1);
        }
    }
}

// ---------------------------------------------------------------------------
// fp16 flash attention, split-KV, double-buffered.
// CTA = (64-q block, head, b*2+split), 4 warps x 16 queries.
// S c-frag feeds PV a-frag directly (f16 key indices line up exactly);
// V stored key-packed transposed Vs2[d][key2].
// ---------------------------------------------------------------------------
__global__ __launch_bounds__(128)
void attn_mma(const float* __restrict__ Q, const float* __restrict__ K,
              const float* __restrict__ V, float* __restrict__ Po,
              float* __restrict__ Pm, float* __restrict__ Pl)
{
    const int h  = blockIdx.y;
    const int bz = blockIdx.z;
    const int b  = bz >> 1;
    const int sp = bz & 1;
    const int q0 = blockIdx.x * 64;

    __shared__ uint32_t Ks2[2][64][KS2];   // [key][d2]
    __shared__ uint32_t Vs2[2][32][VS2];   // [d][key2]

    const int tid  = threadIdx.x;
    const int warp = tid >> 5;
    const int lane = tid & 31;
    const int gid  = lane >> 2;
    const int tig  = lane & 3;

    const float scale = 0.17677669529663687f;  // 1/sqrt(32)

    // Q a-fragments: 2 k16 blocks x 4 regs (half2), pre-scaled
    uint32_t qa[2][4];
    {
        const float* Qb = Q + ((size_t)(b * Sq + q0 + warp * 16)) * Dm + h * HD;
#pragma unroll
        for (int kb = 0; kb < 2; kb++) {
            const int d0 = kb * 16 + 2 * tig;
            qa[kb][0] = f2h2(Qb[(size_t)gid       * Dm + d0    ] * scale,
                             Qb[(size_t)gid       * Dm + d0 + 1] * scale);
            qa[kb][1] = f2h2(Qb[(size_t)(gid + 8) * Dm + d0    ] * scale,
                             Qb[(size_t)(gid + 8) * Dm + d0 + 1] * scale);
            qa[kb][2] = f2h2(Qb[(size_t)gid       * Dm + d0 + 8] * scale,
                             Qb[(size_t)gid       * Dm + d0 + 9] * scale);
            qa[kb][3] = f2h2(Qb[(size_t)(gid + 8) * Dm + d0 + 8] * scale,
                             Qb[(size_t)(gid + 8) * Dm + d0 + 9] * scale);
        }
    }

    float m_lo = -1e30f, m_hi = -1e30f;
    float l_lo = 0.f,    l_hi = 0.f;
    float o[4][4];
#pragma unroll
    for (int nb = 0; nb < 4; nb++)
#pragma unroll
        for (int i = 0; i < 4; i++) o[nb][i] = 0.f;

    const float* Kb = K + (size_t)b * HWk * Dm + h * HD;
    const float* Vb = V + (size_t)b * HWk * Dm + h * HD;

    // K loader: key = tid>>1, dc = (tid&1)*16 floats
    const int krow = tid >> 1;
    const int kdc  = (tid & 1) * 16;
    // V loader: key2 = tid>>2 (0..31), dc = (tid&3)*8 floats
    const int vk2 = tid >> 2;
    const int vdc = (tid & 3) * 8;

    const int jbeg = sp * (HWk / NSPLIT);
    const int jend = jbeg + (HWk / NSPLIT);

    float4 rk[4], rv0[2], rv1[2];
    auto loadKV = [&](int j0) {
#pragma unroll
        for (int i = 0; i < 4; i++)
            rk[i] = *(const float4*)(Kb + (size_t)(j0 + krow) * Dm + kdc + 4 * i);
#pragma unroll
        for (int i = 0; i < 2; i++) {
            rv0[i] = *(const float4*)(Vb + (size_t)(j0 + 2 * vk2)     * Dm + vdc + 4 * i);
            rv1[i] = *(const float4*)(Vb + (size_t)(j0 + 2 * vk2 + 1) * Dm + vdc + 4 * i);
        }
    };
    auto storeKV = [&](int st) {
        const float* kf = (const float*)&rk[0];
#pragma unroll
        for (int j = 0; j < 8; j++)
            Ks2[st][krow][(tid & 1) * 8 + j] = f2h2(kf[2 * j], kf[2 * j + 1]);
        const float* vlo = (const float*)&rv0[0];
        const float* vhi = (const float*)&rv1[0];
#pragma unroll
        for (int j = 0; j < 8; j++)
            Vs2[st][vdc + j][vk2] = f2h2(vlo[j], vhi[j]);
    };

    loadKV(jbeg);
    storeKV(0);
    __syncthreads();

    int stage = 0;
    for (int j0 = jbeg; j0 < jend; j0 += 64) {
        const bool more = (j0 + 64) < jend;
        if (more) loadKV(j0 + 64);

        // ---- S = Q K^T : 8 n-blocks x 2 k16 blocks ----
        float s[8][4];
#pragma unroll
        for (int nb = 0; nb < 8; nb++)
#pragma unroll
            for (int i = 0; i < 4; i++) s[nb][i] = 0.f;

#pragma unroll
        for (int kb = 0; kb < 2; kb++) {
#pragma unroll
            for (int nb = 0; nb < 8; nb++) {
                uint32_t b0 = Ks2[stage][nb * 8 + gid][kb * 8 + tig    ];
                uint32_t b1 = Ks2[stage][nb * 8 + gid][kb * 8 + tig + 4];
                mma_f16(s[nb], qa[kb], b0, b1);
            }
        }

        // ---- online softmax ----
        float tmax_lo = -1e30f, tmax_hi = -1e30f;
#pragma unroll
        for (int nb = 0; nb < 8; nb++) {
            tmax_lo = fmaxf(tmax_lo, fmaxf(s[nb][0], s[nb][1]));
            tmax_hi = fmaxf(tmax_hi, fmaxf(s[nb][2], s[nb][3]));
        }
        tmax_lo = fmaxf(tmax_lo, __shfl_xor_sync(0xffffffffu, tmax_lo, 1));
        tmax_lo = fmaxf(tmax_lo, __shfl_xor_sync(0xffffffffu, tmax_lo, 2));
        tmax_hi = fmaxf(tmax_hi, __shfl_xor_sync(0xffffffffu, tmax_hi, 1));
        tmax_hi = fmaxf(tmax_hi, __shfl_xor_sync(0xffffffffu, tmax_hi, 2));

        const float mn_lo = fmaxf(m_lo, tmax_lo);
        const float mn_hi = fmaxf(m_hi, tmax_hi);
        const float al_lo = __expf(m_lo - mn_lo);
        const float al_hi = __expf(m_hi - mn_hi);
        m_lo = mn_lo; m_hi = mn_hi;
        l_lo *= al_lo; l_hi *= al_hi;
#pragma unroll
        for (int nb = 0; nb < 4; nb++) {
            o[nb][0] *= al_lo; o[nb][1] *= al_lo;
            o[nb][2] *= al_hi; o[nb][3] *= al_hi;
        }

        // ---- exp + O += P V : 4 k16 key-blocks x 4 d-blocks ----
#pragma unroll
        for (int kb = 0; kb < 4; kb++) {
            const float p0 = __expf(s[2 * kb    ][0] - mn_lo);
            const float p1 = __expf(s[2 * kb    ][1] - mn_lo);
            const float p2 = __expf(s[2 * kb    ][2] - mn_hi);
            const float p3 = __expf(s[2 * kb    ][3] - mn_hi);
            const float r0 = __expf(s[2 * kb + 1][0] - mn_lo);
            const float r1 = __expf(s[2 * kb + 1][1] - mn_lo);
            const float r2 = __expf(s[2 * kb + 1][2] - mn_hi);
            const float r3 = __expf(s[2 * kb + 1][3] - mn_hi);
            l_lo += p0 + p1 + r0 + r1;
            l_hi += p2 + p3 + r2 + r3;
            uint32_t pa[4];
            pa[0] = f2h2(p0, p1);
            pa[1] = f2h2(p2, p3);
            pa[2] = f2h2(r0, r1);
            pa[3] = f2h2(r2, r3);
#pragma unroll
            for (int nb = 0; nb < 4; nb++) {
                uint32_t b0 = Vs2[stage][nb * 8 + gid][kb * 8 + tig    ];
                uint32_t b1 = Vs2[stage][nb * 8 + gid][kb * 8 + tig + 4];
                mma_f16(o[nb], pa, b0, b1);
            }
        }

        if (more) storeKV(stage ^ 1);
        __syncthreads();
        stage ^= 1;
    }

    l_lo += __shfl_xor_sync(0xffffffffu, l_lo, 1);
    l_lo += __shfl_xor_sync(0xffffffffu, l_lo, 2);
    l_hi += __shfl_xor_sync(0xffffffffu, l_hi, 1);
    l_hi += __shfl_xor_sync(0xffffffffu, l_hi, 2);

    const int row0 = (((b * NH + h) * NSPLIT) + sp) * Sq + q0 + warp * 16;
#pragma unroll
    for (int nb = 0; nb < 4; nb++) {
        *(float2*)(Po + (size_t)(row0 + gid)     * HD + nb * 8 + 2 * tig) =
            make_float2(o[nb][0], o[nb][1]);
        *(float2*)(Po + (size_t)(row0 + gid + 8) * HD + nb * 8 + 2 * tig) =
            make_float2(o[nb][2], o[nb][3]);
    }
    if (tig == 0) {
        Pm[row0 + gid]     = m_lo;  Pl[row0 + gid]     = l_lo;
        Pm[row0 + gid + 8] = m_hi;  Pl[row0 + gid + 8] = l_hi;
    }
}

// ---------------------------------------------------------------------------
// combine split partials -> (B,S,D)
// ---------------------------------------------------------------------------
__global__ __launch_bounds__(256)
void attn_combine(const float* __restrict__ Po, const float* __restrict__ Pm,
                  const float* __restrict__ Pl, float* __restrict__ Aout)
{
    const int t = blockIdx.x * 256 + threadIdx.x;
    const int row = t >> 2;
    const int dc  = (t & 3) * 8;
    const int bh  = row / Sq;
    const int q   = row % Sq;
    const int b   = bh / NH;
    const int h   = bh % NH;

    const size_t i0 = (size_t)(bh * NSPLIT + 0) * Sq + q;
    const size_t i1 = (size_t)(bh * NSPLIT + 1) * Sq + q;
    const float m0 = Pm[i0], m1 = Pm[i1];
    const float l0 = Pl[i0], l1 = Pl[i1];
    const float m  = fmaxf(m0, m1);
    const float w0 = __expf(m0 - m);
    const float w1 = __expf(m1 - m);
    const float inv = 1.f / (l0 * w0 + l1 * w1);

    const float* o0 = Po + i0 * HD + dc;
    const float* o1 = Po + i1 * HD + dc;
    float* out = Aout + ((size_t)(b * Sq + q)) * Dm + h * HD + dc;
#pragma unroll
    for (int i = 0; i < 8; i += 4) {
        float4 a = *(const float4*)(o0 + i);
        float4 c = *(const float4*)(o1 + i);
        float4 r;
        r.x = (a.x * w0 + c.x * w1) * inv;
        r.y = (a.y * w0 + c.y * w1) * inv;
        r.z = (a.z * w0 + c.z * w1) * inv;
        r.w = (a.w * w0 + c.w * w1) * inv;
        *(float4*)(out + i) = r;
    }
}

// ---------------------------------------------------------------------------
// Launch
// ---------------------------------------------------------------------------
extern "C" void kernel_launch(void* const* d_in, const int* in_sizes, int n_in,
                              void* d_out, int out_size)
{
    const float* query = (const float*)d_in[0];
    const float* keyv  = (const float*)d_in[1];
    const float* Wq    = (const float*)d_in[2];
    const float* bq    = (const float*)d_in[3];
    const float* Wk    = (const float*)d_in[4];
    const float* bk    = (const float*)d_in[5];
    const float* Wv    = (const float*)d_in[6];
    const float* bv    = (const float*)d_in[7];
    const float* Wo    = (const float*)d_in[8];
    const float* bo    = (const float*)d_in[9];
    float* out = (float*)d_out;

    float *dQ, *dK, *dV, *dA, *dPo, *dPm, *dPl;
    cudaGetSymbolAddress((void**)&dQ, g_Q);
    cudaGetSymbolAddress((void**)&dK, g_K);
    cudaGetSymbolAddress((void**)&dV, g_V);
    cudaGetSymbolAddress((void**)&dA, g_A);
    cudaGetSymbolAddress((void**)&dPo, g_Po);
    cudaGetSymbolAddress((void**)&dPm, g_Pm);
    cudaGetSymbolAddress((void**)&dPl, g_Pl);

    // Q projection
    {
        dim3 grid((Bsz * Sq) / 64, Dm / 128);
        gemm_rm_f16<<<grid, 128>>>(query, Wq, bq, dQ);
    }
    // fused K+V projections (one launch, all batches)
    {
        dim3 grid(HWk / 128, Dm / 128, Bsz * 2);
        gemm_kv_fused<<<grid, 256>>>(keyv, Wk, bk, Wv, bv, dK, dV);
    }
    // attention (split-KV)
    {
        dim3 grid(Sq / 64, NH, Bsz * NSPLIT);
        attn_mma<<<grid, 128>>>(dQ, dK, dV, dPo, dPm, dPl);
    }
    // combine
    {
        attn_combine<<<(Bsz * NH * Sq * 4) / 256, 256>>>(dPo, dPm, dPl, dA);
    }
    // output projection -> d_out
    {
        dim3 grid((Bsz * Sq) / 64, Dm / 128);
        gemm_rm_f16<<<grid, 128>>>(dA, Wo, bo, out);
    }
}

// round 7
// speedup vs baseline: 1.5156x; 1.1659x over previous
#include <cuda_runtime.h>
#include <cuda_fp16.h>
#include <cstdint>

// Problem dims (fixed)
#define Dm   256
#define Bsz  4
#define Sq   512
#define HWk  4096
#define NH   8
#define HD   32
#define NSPLIT 2

// Scratch (no cudaMalloc allowed)
__device__ float  g_Q[Bsz * Sq * Dm];
__device__ __half g_K[Bsz * HWk * Dm];
__device__ __half g_V[Bsz * HWk * Dm];
__device__ float  g_Po[Bsz * NH * NSPLIT * Sq * HD];
__device__ float  g_Pm[Bsz * NH * NSPLIT * Sq];
__device__ float  g_Pl[Bsz * NH * NSPLIT * Sq];

__device__ __forceinline__ uint32_t f2h2(float x, float y) {
    __half2 h = __floats2half2_rn(x, y);
    return *reinterpret_cast<uint32_t*>(&h);
}

// mma.m16n8k16 f16 inputs, f32 accumulate
__device__ __forceinline__ void mma_f16(float c[4], const uint32_t a[4],
                                        uint32_t b0, uint32_t b1) {
    asm volatile(
        "mma.sync.aligned.m16n8k16.row.col.f32.f16.f16.f32 "
        "{%0,%1,%2,%3}, {%4,%5,%6,%7}, {%8,%9}, {%0,%1,%2,%3};"
        : "+f"(c[0]), "+f"(c[1]), "+f"(c[2]), "+f"(c[3])
        : "r"(a[0]), "r"(a[1]), "r"(a[2]), "r"(a[3]), "r"(b0), "r"(b1));
}

#define KS2 20   // [row][k2] tiles: 16 data words + 4 pad
#define VS2 36   // [d][key2] tile: 32 data words + 4 pad

// ---------------------------------------------------------------------------
// FUSED KV projection (fp16 mma, half output): grid.z in [0,8).
// C[b,m,n] = sum_k kv[b,k,m] * W[n,k] + bias[n]. Double-buffered.
// BM=128, BN=128, BK=32, 8 warps (4m x 2n), warp tile 32x64.
// ---------------------------------------------------------------------------
__global__ __launch_bounds__(256)
void gemm_kv_fused(const float* __restrict__ KVin,
                   const float* __restrict__ Wk, const float* __restrict__ bk,
                   const float* __restrict__ Wv, const float* __restrict__ bv,
                   __half* __restrict__ Kout, __half* __restrict__ Vout)
{
    const int z = blockIdx.z;
    const int b = z >> 1;
    const int isv = z & 1;
    const float* A    = KVin + (size_t)b * Dm * HWk;   // A[k][m], lda = HWk
    const float* W    = isv ? Wv : Wk;
    const float* bias = isv ? bv : bk;
    __half* C = (isv ? Vout : Kout) + (size_t)b * HWk * Dm;

    __shared__ uint32_t As2[2][128][KS2];   // [m][k2]
    __shared__ uint32_t Ws2[2][128][KS2];   // [n][k2]

    const int bm = blockIdx.x * 128;
    const int bn = blockIdx.y * 128;
    const int tid  = threadIdx.x;
    const int warp = tid >> 5;
    const int lane = tid & 31;
    const int gid  = lane >> 2;
    const int tig  = lane & 3;
    const int wm = (warp >> 1) * 32;
    const int wn = (warp & 1) * 64;

    float acc[2][8][4];
#pragma unroll
    for (int mf = 0; mf < 2; mf++)
#pragma unroll
        for (int nb = 0; nb < 8; nb++)
#pragma unroll
            for (int j = 0; j < 4; j++) acc[mf][nb][j] = 0.f;

    const int k2 = tid >> 4;
    const int mc = (tid & 15) * 8;
    const int rr = tid >> 1;
    const int kc = (tid & 1) * 16;

    float4 ra0[2], ra1[2], rw[4];

    auto loadA = [&](int k0) {
#pragma unroll
        for (int i = 0; i < 2; i++) {
            ra0[i] = *(const float4*)(A + (size_t)(k0 + 2 * k2)     * HWk + bm + mc + 4 * i);
            ra1[i] = *(const float4*)(A + (size_t)(k0 + 2 * k2 + 1) * HWk + bm + mc + 4 * i);
        }
#pragma unroll
        for (int i = 0; i < 4; i++)
            rw[i] = *(const float4*)(W + (size_t)(bn + rr) * Dm + k0 + kc + 4 * i);
    };
    auto storeA = [&](int st) {
        const float* lo = (const float*)&ra0[0];
        const float* hi = (const float*)&ra1[0];
#pragma unroll
        for (int i = 0; i < 8; i++)
            As2[st][mc + i][k2] = f2h2(lo[i], hi[i]);
        const float* w = (const float*)&rw[0];
#pragma unroll
        for (int j = 0; j < 8; j++)
            Ws2[st][rr][(tid & 1) * 8 + j] = f2h2(w[2 * j], w[2 * j + 1]);
    };

    loadA(0);
    storeA(0);
    __syncthreads();

#pragma unroll
    for (int it = 0; it < 8; it++) {
        const int cur = it & 1;
        const bool more = (it + 1) < 8;
        if (more) loadA((it + 1) * 32);

#pragma unroll
        for (int kb = 0; kb < 2; kb++) {
            uint32_t a[2][4];
#pragma unroll
            for (int mf = 0; mf < 2; mf++) {
                const int m = wm + mf * 16 + gid;
                a[mf][0] = As2[cur][m    ][kb * 8 + tig    ];
                a[mf][1] = As2[cur][m + 8][kb * 8 + tig    ];
                a[mf][2] = As2[cur][m    ][kb * 8 + tig + 4];
                a[mf][3] = As2[cur][m + 8][kb * 8 + tig + 4];
            }
#pragma unroll
            for (int nb = 0; nb < 8; nb++) {
                uint32_t b0 = Ws2[cur][wn + nb * 8 + gid][kb * 8 + tig    ];
                uint32_t b1 = Ws2[cur][wn + nb * 8 + gid][kb * 8 + tig + 4];
                mma_f16(acc[0][nb], a[0], b0, b1);
                mma_f16(acc[1][nb], a[1], b0, b1);
            }
        }

        if (more) storeA(cur ^ 1);
        __syncthreads();
    }

    // epilogue: bias + store as half2
#pragma unroll
    for (int mf = 0; mf < 2; mf++) {
        const int row = bm + wm + mf * 16 + gid;
#pragma unroll
        for (int nb = 0; nb < 8; nb++) {
            const int col = bn + wn + nb * 8 + 2 * tig;
            const float b0 = bias[col], b1 = bias[col + 1];
            *(uint32_t*)(C + (size_t)row * Dm + col) =
                f2h2(acc[mf][nb][0] + b0, acc[mf][nb][1] + b1);
            *(uint32_t*)(C + (size_t)(row + 8) * Dm + col) =
                f2h2(acc[mf][nb][2] + b0, acc[mf][nb][3] + b1);
        }
    }
}

// ---------------------------------------------------------------------------
// Q projection (fp16 mma): A row-major fp32 in, fp32 out.
// BM=64, BN=64, 4 warps (2m x 2n), warp tile 32x32. Grid (32, 4).
// ---------------------------------------------------------------------------
__global__ __launch_bounds__(128)
void gemm_q_f16(const float* __restrict__ A, const float* __restrict__ W,
                const float* __restrict__ bias, float* __restrict__ C)
{
    __shared__ uint32_t As2[64][KS2];
    __shared__ uint32_t Ws2[64][KS2];

    const int bm = blockIdx.x * 64;
    const int bn = blockIdx.y * 64;
    const int tid  = threadIdx.x;
    const int warp = tid >> 5;
    const int lane = tid & 31;
    const int gid  = lane >> 2;
    const int tig  = lane & 3;
    const int wm = (warp >> 1) * 32;
    const int wn = (warp & 1) * 32;

    float acc[2][4][4];
#pragma unroll
    for (int mf = 0; mf < 2; mf++)
#pragma unroll
        for (int nb = 0; nb < 4; nb++)
#pragma unroll
            for (int j = 0; j < 4; j++) acc[mf][nb][j] = 0.f;

    const int rr = tid >> 1;
    const int kc = (tid & 1) * 16;

    for (int k0 = 0; k0 < Dm; k0 += 32) {
        __syncthreads();
        {
            float4 v[4];
#pragma unroll
            for (int i = 0; i < 4; i++)
                v[i] = *(const float4*)(A + (size_t)(bm + rr) * Dm + k0 + kc + 4 * i);
            const float* f = (const float*)&v[0];
#pragma unroll
            for (int j = 0; j < 8; j++)
                As2[rr][(tid & 1) * 8 + j] = f2h2(f[2 * j], f[2 * j + 1]);
        }
        {
            float4 v[4];
#pragma unroll
            for (int i = 0; i < 4; i++)
                v[i] = *(const float4*)(W + (size_t)(bn + rr) * Dm + k0 + kc + 4 * i);
            const float* f = (const float*)&v[0];
#pragma unroll
            for (int j = 0; j < 8; j++)
                Ws2[rr][(tid & 1) * 8 + j] = f2h2(f[2 * j], f[2 * j + 1]);
        }
        __syncthreads();

#pragma unroll
        for (int kb = 0; kb < 2; kb++) {
            uint32_t a[2][4];
#pragma unroll
            for (int mf = 0; mf < 2; mf++) {
                const int m = wm + mf * 16 + gid;
                a[mf][0] = As2[m    ][kb * 8 + tig    ];
                a[mf][1] = As2[m + 8][kb * 8 + tig    ];
                a[mf][2] = As2[m    ][kb * 8 + tig + 4];
                a[mf][3] = As2[m + 8][kb * 8 + tig + 4];
            }
#pragma unroll
            for (int nb = 0; nb < 4; nb++) {
                uint32_t b0 = Ws2[wn + nb * 8 + gid][kb * 8 + tig    ];
                uint32_t b1 = Ws2[wn + nb * 8 + gid][kb * 8 + tig + 4];
                mma_f16(acc[0][nb], a[0], b0, b1);
                mma_f16(acc[1][nb], a[1], b0, b1);
            }
        }
    }

#pragma unroll
    for (int mf = 0; mf < 2; mf++) {
        const int row = bm + wm + mf * 16 + gid;
#pragma unroll
        for (int nb = 0; nb < 4; nb++) {
            const int col = bn + wn + nb * 8 + 2 * tig;
            const float b0 = bias[col], b1 = bias[col + 1];
            *(float2*)(C + (size_t)row * Dm + col) =
                make_float2(acc[mf][nb][0] + b0, acc[mf][nb][1] + b1);
            *(float2*)(C + (size_t)(row + 8) * Dm + col) =
                make_float2(acc[mf][nb][2] + b0, acc[mf][nb][3] + b1);
        }
    }
}

// ---------------------------------------------------------------------------
// O projection with FUSED split-KV combine: A is computed on the fly from
// Po/Pm/Pl (normalized attention output). BM=64, BN=64, 4 warps.
// ---------------------------------------------------------------------------
__global__ __launch_bounds__(128)
void gemm_out_f16(const float* __restrict__ Po, const float* __restrict__ Pm,
                  const float* __restrict__ Pl, const float* __restrict__ W,
                  const float* __restrict__ bias, float* __restrict__ C)
{
    __shared__ uint32_t As2[64][KS2];
    __shared__ uint32_t Ws2[64][KS2];

    const int bm = blockIdx.x * 64;
    const int bn = blockIdx.y * 64;
    const int tid  = threadIdx.x;
    const int warp = tid >> 5;
    const int lane = tid & 31;
    const int gid  = lane >> 2;
    const int tig  = lane & 3;
    const int wm = (warp >> 1) * 32;
    const int wn = (warp & 1) * 32;

    float acc[2][4][4];
#pragma unroll
    for (int mf = 0; mf < 2; mf++)
#pragma unroll
        for (int nb = 0; nb < 4; nb++)
#pragma unroll
            for (int j = 0; j < 4; j++) acc[mf][nb][j] = 0.f;

    const int rr = tid >> 1;          // row within block (0..63)
    const int kc = (tid & 1) * 16;    // k offset (0 or 16)

    const int rowg = bm + rr;
    const int b = rowg >> 9;          // rowg / Sq
    const int q = rowg & (Sq - 1);

    for (int k0 = 0; k0 < Dm; k0 += 32) {
        __syncthreads();
        {
            // A chunk = 16 floats of normalized attention output at dims k0+kc..
            const int kg  = k0 + kc;
            const int h   = kg >> 5;          // head
            const int dof = kg & 31;          // 0 or 16 within head
            const int bh  = b * NH + h;
            const size_t i0 = (size_t)(bh * NSPLIT + 0) * Sq + q;
            const size_t i1 = i0 + Sq;
            const float m0 = Pm[i0], m1 = Pm[i1];
            const float l0 = Pl[i0], l1 = Pl[i1];
            const float m  = fmaxf(m0, m1);
            float w0 = __expf(m0 - m);
            float w1 = __expf(m1 - m);
            const float inv = 1.f / (l0 * w0 + l1 * w1);
            w0 *= inv; w1 *= inv;

            float4 p0[4], p1[4];
#pragma unroll
            for (int i = 0; i < 4; i++) {
                p0[i] = *(const float4*)(Po + i0 * HD + dof + 4 * i);
                p1[i] = *(const float4*)(Po + i1 * HD + dof + 4 * i);
            }
            const float* f0 = (const float*)&p0[0];
            const float* f1 = (const float*)&p1[0];
#pragma unroll
            for (int j = 0; j < 8; j++)
                As2[rr][(tid & 1) * 8 + j] =
                    f2h2(f0[2 * j] * w0 + f1[2 * j] * w1,
                         f0[2 * j + 1] * w0 + f1[2 * j + 1] * w1);
        }
        {
            float4 v[4];
#pragma unroll
            for (int i = 0; i < 4; i++)
                v[i] = *(const float4*)(W + (size_t)(bn + rr) * Dm + k0 + kc + 4 * i);
            const float* f = (const float*)&v[0];
#pragma unroll
            for (int j = 0; j < 8; j++)
                Ws2[rr][(tid & 1) * 8 + j] = f2h2(f[2 * j], f[2 * j + 1]);
        }
        __syncthreads();

#pragma unroll
        for (int kb = 0; kb < 2; kb++) {
            uint32_t a[2][4];
#pragma unroll
            for (int mf = 0; mf < 2; mf++) {
                const int m = wm + mf * 16 + gid;
                a[mf][0] = As2[m    ][kb * 8 + tig    ];
                a[mf][1] = As2[m + 8][kb * 8 + tig    ];
                a[mf][2] = As2[m    ][kb * 8 + tig + 4];
                a[mf][3] = As2[m + 8][kb * 8 + tig + 4];
            }
#pragma unroll
            for (int nb = 0; nb < 4; nb++) {
                uint32_t b0 = Ws2[wn + nb * 8 + gid][kb * 8 + tig    ];
                uint32_t b1 = Ws2[wn + nb * 8 + gid][kb * 8 + tig + 4];
                mma_f16(acc[0][nb], a[0], b0, b1);
                mma_f16(acc[1][nb], a[1], b0, b1);
            }
        }
    }

#pragma unroll
    for (int mf = 0; mf < 2; mf++) {
        const int row = bm + wm + mf * 16 + gid;
#pragma unroll
        for (int nb = 0; nb < 4; nb++) {
            const int col = bn + wn + nb * 8 + 2 * tig;
            const float b0 = bias[col], b1 = bias[col + 1];
            *(float2*)(C + (size_t)row * Dm + col) =
                make_float2(acc[mf][nb][0] + b0, acc[mf][nb][1] + b1);
            *(float2*)(C + (size_t)(row + 8) * Dm + col) =
                make_float2(acc[mf][nb][2] + b0, acc[mf][nb][3] + b1);
        }
    }
}

// ---------------------------------------------------------------------------
// fp16 flash attention, split-KV, double-buffered, half K/V in gmem.
// CTA = (64-q block, head, b*2+split), 4 warps x 16 queries.
// K tiles: pure copy gmem->SMEM (no conversion). V: transposed repack.
// ---------------------------------------------------------------------------
__global__ __launch_bounds__(128)
void attn_mma(const float* __restrict__ Q, const __half* __restrict__ K,
              const __half* __restrict__ V, float* __restrict__ Po,
              float* __restrict__ Pm, float* __restrict__ Pl)
{
    const int h  = blockIdx.y;
    const int bz = blockIdx.z;
    const int b  = bz >> 1;
    const int sp = bz & 1;
    const int q0 = blockIdx.x * 64;

    __shared__ uint32_t Ks2[2][64][KS2];   // [key][d2]
    __shared__ uint32_t Vs2[2][32][VS2];   // [d][key2]

    const int tid  = threadIdx.x;
    const int warp = tid >> 5;
    const int lane = tid & 31;
    const int gid  = lane >> 2;
    const int tig  = lane & 3;

    const float scale = 0.17677669529663687f;  // 1/sqrt(32)

    uint32_t qa[2][4];
    {
        const float* Qb = Q + ((size_t)(b * Sq + q0 + warp * 16)) * Dm + h * HD;
#pragma unroll
        for (int kb = 0; kb < 2; kb++) {
            const int d0 = kb * 16 + 2 * tig;
            qa[kb][0] = f2h2(Qb[(size_t)gid       * Dm + d0    ] * scale,
                             Qb[(size_t)gid       * Dm + d0 + 1] * scale);
            qa[kb][1] = f2h2(Qb[(size_t)(gid + 8) * Dm + d0    ] * scale,
                             Qb[(size_t)(gid + 8) * Dm + d0 + 1] * scale);
            qa[kb][2] = f2h2(Qb[(size_t)gid       * Dm + d0 + 8] * scale,
                             Qb[(size_t)gid       * Dm + d0 + 9] * scale);
            qa[kb][3] = f2h2(Qb[(size_t)(gid + 8) * Dm + d0 + 8] * scale,
                             Qb[(size_t)(gid + 8) * Dm + d0 + 9] * scale);
        }
    }

    float m_lo = -1e30f, m_hi = -1e30f;
    float l_lo = 0.f,    l_hi = 0.f;
    float o[4][4];
#pragma unroll
    for (int nb = 0; nb < 4; nb++)
#pragma unroll
        for (int i = 0; i < 4; i++) o[nb][i] = 0.f;

    const __half* Kb = K + (size_t)b * HWk * Dm + h * HD;
    const __half* Vb = V + (size_t)b * HWk * Dm + h * HD;

    // K loader: key = tid>>1, 16 halves at (tid&1)*16
    const int krow = tid >> 1;
    const int kdc  = (tid & 1) * 16;
    // V loader: key2 = tid>>2 (0..31), 8 halves at (tid&3)*8
    const int vk2 = tid >> 2;
    const int vdc = (tid & 3) * 8;

    const int jbeg = sp * (HWk / NSPLIT);
    const int jend = jbeg + (HWk / NSPLIT);

    uint4 rk[2], rv[2];
    auto loadKV = [&](int j0) {
        rk[0] = *(const uint4*)(Kb + (size_t)(j0 + krow) * Dm + kdc);
        rk[1] = *(const uint4*)(Kb + (size_t)(j0 + krow) * Dm + kdc + 8);
        rv[0] = *(const uint4*)(Vb + (size_t)(j0 + 2 * vk2)     * Dm + vdc);
        rv[1] = *(const uint4*)(Vb + (size_t)(j0 + 2 * vk2 + 1) * Dm + vdc);
    };
    auto storeKV = [&](int st) {
        const uint32_t* kw = (const uint32_t*)&rk[0];
#pragma unroll
        for (int j = 0; j < 8; j++)
            Ks2[st][krow][(tid & 1) * 8 + j] = kw[j];
        const __half* h0 = (const __half*)&rv[0];
        const __half* h1 = (const __half*)&rv[1];
#pragma unroll
        for (int j = 0; j < 8; j++) {
            __half2 p = __halves2half2(h0[j], h1[j]);
            Vs2[st][vdc + j][vk2] = *(uint32_t*)&p;
        }
    };

    loadKV(jbeg);
    storeKV(0);
    __syncthreads();

    int stage = 0;
    for (int j0 = jbeg; j0 < jend; j0 += 64) {
        const bool more = (j0 + 64) < jend;
        if (more) loadKV(j0 + 64);

        // ---- S = Q K^T ----
        float s[8][4];
#pragma unroll
        for (int nb = 0; nb < 8; nb++)
#pragma unroll
            for (int i = 0; i < 4; i++) s[nb][i] = 0.f;

#pragma unroll
        for (int kb = 0; kb < 2; kb++) {
#pragma unroll
            for (int nb = 0; nb < 8; nb++) {
                uint32_t b0 = Ks2[stage][nb * 8 + gid][kb * 8 + tig    ];
                uint32_t b1 = Ks2[stage][nb * 8 + gid][kb * 8 + tig + 4];
                mma_f16(s[nb], qa[kb], b0, b1);
            }
        }

        // ---- online softmax ----
        float tmax_lo = -1e30f, tmax_hi = -1e30f;
#pragma unroll
        for (int nb = 0; nb < 8; nb++) {
            tmax_lo = fmaxf(tmax_lo, fmaxf(s[nb][0], s[nb][1]));
            tmax_hi = fmaxf(tmax_hi, fmaxf(s[nb][2], s[nb][3]));
        }
        tmax_lo = fmaxf(tmax_lo, __shfl_xor_sync(0xffffffffu, tmax_lo, 1));
        tmax_lo = fmaxf(tmax_lo, __shfl_xor_sync(0xffffffffu, tmax_lo, 2));
        tmax_hi = fmaxf(tmax_hi, __shfl_xor_sync(0xffffffffu, tmax_hi, 1));
        tmax_hi = fmaxf(tmax_hi, __shfl_xor_sync(0xffffffffu, tmax_hi, 2));

        const float mn_lo = fmaxf(m_lo, tmax_lo);
        const float mn_hi = fmaxf(m_hi, tmax_hi);
        const float al_lo = __expf(m_lo - mn_lo);
        const float al_hi = __expf(m_hi - mn_hi);
        m_lo = mn_lo; m_hi = mn_hi;
        l_lo *= al_lo; l_hi *= al_hi;
#pragma unroll
        for (int nb = 0; nb < 4; nb++) {
            o[nb][0] *= al_lo; o[nb][1] *= al_lo;
            o[nb][2] *= al_hi; o[nb][3] *= al_hi;
        }

        // ---- exp + O += P V ----
#pragma unroll
        for (int kb = 0; kb < 4; kb++) {
            const float p0 = __expf(s[2 * kb    ][0] - mn_lo);
            const float p1 = __expf(s[2 * kb    ][1] - mn_lo);
            const float p2 = __expf(s[2 * kb    ][2] - mn_hi);
            const float p3 = __expf(s[2 * kb    ][3] - mn_hi);
            const float r0 = __expf(s[2 * kb + 1][0] - mn_lo);
            const float r1 = __expf(s[2 * kb + 1][1] - mn_lo);
            const float r2 = __expf(s[2 * kb + 1][2] - mn_hi);
            const float r3 = __expf(s[2 * kb + 1][3] - mn_hi);
            l_lo += p0 + p1 + r0 + r1;
            l_hi += p2 + p3 + r2 + r3;
            uint32_t pa[4];
            pa[0] = f2h2(p0, p1);
            pa[1] = f2h2(p2, p3);
            pa[2] = f2h2(r0, r1);
            pa[3] = f2h2(r2, r3);
#pragma unroll
            for (int nb = 0; nb < 4; nb++) {
                uint32_t b0 = Vs2[stage][nb * 8 + gid][kb * 8 + tig    ];
                uint32_t b1 = Vs2[stage][nb * 8 + gid][kb * 8 + tig + 4];
                mma_f16(o[nb], pa, b0, b1);
            }
        }

        if (more) storeKV(stage ^ 1);
        __syncthreads();
        stage ^= 1;
    }

    l_lo += __shfl_xor_sync(0xffffffffu, l_lo, 1);
    l_lo += __shfl_xor_sync(0xffffffffu, l_lo, 2);
    l_hi += __shfl_xor_sync(0xffffffffu, l_hi, 1);
    l_hi += __shfl_xor_sync(0xffffffffu, l_hi, 2);

    const int row0 = (((b * NH + h) * NSPLIT) + sp) * Sq + q0 + warp * 16;
#pragma unroll
    for (int nb = 0; nb < 4; nb++) {
        *(float2*)(Po + (size_t)(row0 + gid)     * HD + nb * 8 + 2 * tig) =
            make_float2(o[nb][0], o[nb][1]);
        *(float2*)(Po + (size_t)(row0 + gid + 8) * HD + nb * 8 + 2 * tig) =
            make_float2(o[nb][2], o[nb][3]);
    }
    if (tig == 0) {
        Pm[row0 + gid]     = m_lo;  Pl[row0 + gid]     = l_lo;
        Pm[row0 + gid + 8] = m_hi;  Pl[row0 + gid + 8] = l_hi;
    }
}

// ---------------------------------------------------------------------------
// Launch
// ---------------------------------------------------------------------------
extern "C" void kernel_launch(void* const* d_in, const int* in_sizes, int n_in,
                              void* d_out, int out_size)
{
    const float* query = (const float*)d_in[0];
    const float* keyv  = (const float*)d_in[1];
    const float* Wq    = (const float*)d_in[2];
    const float* bq    = (const float*)d_in[3];
    const float* Wk    = (const float*)d_in[4];
    const float* bk    = (const float*)d_in[5];
    const float* Wv    = (const float*)d_in[6];
    const float* bv    = (const float*)d_in[7];
    const float* Wo    = (const float*)d_in[8];
    const float* bo    = (const float*)d_in[9];
    float* out = (float*)d_out;

    float *dQ, *dPo, *dPm, *dPl;
    __half *dK, *dV;
    cudaGetSymbolAddress((void**)&dQ, g_Q);
    cudaGetSymbolAddress((void**)&dK, g_K);
    cudaGetSymbolAddress((void**)&dV, g_V);
    cudaGetSymbolAddress((void**)&dPo, g_Po);
    cudaGetSymbolAddress((void**)&dPm, g_Pm);
    cudaGetSymbolAddress((void**)&dPl, g_Pl);

    // Q projection
    {
        dim3 grid((Bsz * Sq) / 64, Dm / 64);
        gemm_q_f16<<<grid, 128>>>(query, Wq, bq, dQ);
    }
    // fused K+V projections (one launch, all batches), half output
    {
        dim3 grid(HWk / 128, Dm / 128, Bsz * 2);
        gemm_kv_fused<<<grid, 256>>>(keyv, Wk, bk, Wv, bv, dK, dV);
    }
    // attention (split-KV)
    {
        dim3 grid(Sq / 64, NH, Bsz * NSPLIT);
        attn_mma<<<grid, 128>>>(dQ, dK, dV, dPo, dPm, dPl);
    }
    // output projection with fused combine -> d_out
    {
        dim3 grid((Bsz * Sq) / 64, Dm / 64);
        gemm_out_f16<<<grid, 128>>>(dPo, dPm, dPl, Wo, bo, out);
    }
}

// round 8
// speedup vs baseline: 1.7234x; 1.1371x over previous
#include <cuda_runtime.h>
#include <cuda_fp16.h>
#include <cstdint>

// Problem dims (fixed)
#define Dm   256
#define Bsz  4
#define Sq   512
#define HWk  4096
#define NH   8
#define HD   32
#define NSPLIT 2

// Scratch (no cudaMalloc allowed)
__device__ float  g_Q[Bsz * Sq * Dm];
__device__ __half g_K[Bsz * HWk * Dm];
__device__ __half g_V[Bsz * HWk * Dm];
__device__ float  g_Po[Bsz * NH * NSPLIT * Sq * HD];
__device__ float  g_Pm[Bsz * NH * NSPLIT * Sq];
__device__ float  g_Pl[Bsz * NH * NSPLIT * Sq];

__device__ __forceinline__ uint32_t f2h2(float x, float y) {
    __half2 h = __floats2half2_rn(x, y);
    return *reinterpret_cast<uint32_t*>(&h);
}

// mma.m16n8k16 f16 inputs, f32 accumulate
__device__ __forceinline__ void mma_f16(float c[4], const uint32_t a[4],
                                        uint32_t b0, uint32_t b1) {
    asm volatile(
        "mma.sync.aligned.m16n8k16.row.col.f32.f16.f16.f32 "
        "{%0,%1,%2,%3}, {%4,%5,%6,%7}, {%8,%9}, {%0,%1,%2,%3};"
        : "+f"(c[0]), "+f"(c[1]), "+f"(c[2]), "+f"(c[3])
        : "r"(a[0]), "r"(a[1]), "r"(a[2]), "r"(a[3]), "r"(b0), "r"(b1));
}

#define KS2 20   // attn/proj [row][k2] tiles: 16 data words + 4 pad
#define KSG 17   // KV-proj tiles: odd stride -> A-store conflicts 16-way -> 4-way
#define VS2 36   // attn V [d][key2] tile

// ---------------------------------------------------------------------------
// FUSED KV projection (fp16 mma, half output): grid.z in [0,8).
// ---------------------------------------------------------------------------
__global__ __launch_bounds__(256)
void gemm_kv_fused(const float* __restrict__ KVin,
                   const float* __restrict__ Wk, const float* __restrict__ bk,
                   const float* __restrict__ Wv, const float* __restrict__ bv,
                   __half* __restrict__ Kout, __half* __restrict__ Vout)
{
    const int z = blockIdx.z;
    const int b = z >> 1;
    const int isv = z & 1;
    const float* A    = KVin + (size_t)b * Dm * HWk;   // A[k][m], lda = HWk
    const float* W    = isv ? Wv : Wk;
    const float* bias = isv ? bv : bk;
    __half* C = (isv ? Vout : Kout) + (size_t)b * HWk * Dm;

    __shared__ uint32_t As2[2][128][KSG];   // [m][k2]
    __shared__ uint32_t Ws2[2][128][KSG];   // [n][k2]

    const int bm = blockIdx.x * 128;
    const int bn = blockIdx.y * 128;
    const int tid  = threadIdx.x;
    const int warp = tid >> 5;
    const int lane = tid & 31;
    const int gid  = lane >> 2;
    const int tig  = lane & 3;
    const int wm = (warp >> 1) * 32;
    const int wn = (warp & 1) * 64;

    float acc[2][8][4];
#pragma unroll
    for (int mf = 0; mf < 2; mf++)
#pragma unroll
        for (int nb = 0; nb < 8; nb++)
#pragma unroll
            for (int j = 0; j < 4; j++) acc[mf][nb][j] = 0.f;

    const int k2 = tid >> 4;
    const int mc = (tid & 15) * 8;
    const int rr = tid >> 1;
    const int kc = (tid & 1) * 16;

    float4 ra0[2], ra1[2], rw[4];

    auto loadA = [&](int k0) {
#pragma unroll
        for (int i = 0; i < 2; i++) {
            ra0[i] = *(const float4*)(A + (size_t)(k0 + 2 * k2)     * HWk + bm + mc + 4 * i);
            ra1[i] = *(const float4*)(A + (size_t)(k0 + 2 * k2 + 1) * HWk + bm + mc + 4 * i);
        }
#pragma unroll
        for (int i = 0; i < 4; i++)
            rw[i] = *(const float4*)(W + (size_t)(bn + rr) * Dm + k0 + kc + 4 * i);
    };
    auto storeA = [&](int st) {
        const float* lo = (const float*)&ra0[0];
        const float* hi = (const float*)&ra1[0];
#pragma unroll
        for (int i = 0; i < 8; i++)
            As2[st][mc + i][k2] = f2h2(lo[i], hi[i]);
        const float* w = (const float*)&rw[0];
#pragma unroll
        for (int j = 0; j < 8; j++)
            Ws2[st][rr][(tid & 1) * 8 + j] = f2h2(w[2 * j], w[2 * j + 1]);
    };

    loadA(0);
    storeA(0);
    __syncthreads();

#pragma unroll
    for (int it = 0; it < 8; it++) {
        const int cur = it & 1;
        const bool more = (it + 1) < 8;
        if (more) loadA((it + 1) * 32);

#pragma unroll
        for (int kb = 0; kb < 2; kb++) {
            uint32_t a[2][4];
#pragma unroll
            for (int mf = 0; mf < 2; mf++) {
                const int m = wm + mf * 16 + gid;
                a[mf][0] = As2[cur][m    ][kb * 8 + tig    ];
                a[mf][1] = As2[cur][m + 8][kb * 8 + tig    ];
                a[mf][2] = As2[cur][m    ][kb * 8 + tig + 4];
                a[mf][3] = As2[cur][m + 8][kb * 8 + tig + 4];
            }
#pragma unroll
            for (int nb = 0; nb < 8; nb++) {
                uint32_t b0 = Ws2[cur][wn + nb * 8 + gid][kb * 8 + tig    ];
                uint32_t b1 = Ws2[cur][wn + nb * 8 + gid][kb * 8 + tig + 4];
                mma_f16(acc[0][nb], a[0], b0, b1);
                mma_f16(acc[1][nb], a[1], b0, b1);
            }
        }

        if (more) storeA(cur ^ 1);
        __syncthreads();
    }

#pragma unroll
    for (int mf = 0; mf < 2; mf++) {
        const int row = bm + wm + mf * 16 + gid;
#pragma unroll
        for (int nb = 0; nb < 8; nb++) {
            const int col = bn + wn + nb * 8 + 2 * tig;
            const float b0 = bias[col], b1 = bias[col + 1];
            *(uint32_t*)(C + (size_t)row * Dm + col) =
                f2h2(acc[mf][nb][0] + b0, acc[mf][nb][1] + b1);
            *(uint32_t*)(C + (size_t)(row + 8) * Dm + col) =
                f2h2(acc[mf][nb][2] + b0, acc[mf][nb][3] + b1);
        }
    }
}

// ---------------------------------------------------------------------------
// Q projection: 256 threads, 8 warps (4m x 2n), warp tile 16x32.
// BM=64, BN=64, BK=32, double-buffered. fp32 in/out.
// ---------------------------------------------------------------------------
__global__ __launch_bounds__(256)
void gemm_q_f16(const float* __restrict__ A, const float* __restrict__ W,
                const float* __restrict__ bias, float* __restrict__ C)
{
    __shared__ uint32_t As2[2][64][KS2];
    __shared__ uint32_t Ws2[2][64][KS2];

    const int bm = blockIdx.x * 64;
    const int bn = blockIdx.y * 64;
    const int tid  = threadIdx.x;
    const int warp = tid >> 5;
    const int lane = tid & 31;
    const int gid  = lane >> 2;
    const int tig  = lane & 3;
    const int wm = (warp >> 1) * 16;
    const int wn = (warp & 1) * 32;

    float acc[4][4];
#pragma unroll
    for (int nb = 0; nb < 4; nb++)
#pragma unroll
        for (int j = 0; j < 4; j++) acc[nb][j] = 0.f;

    const int rr = tid >> 2;          // 0..63
    const int kq = (tid & 3) * 8;     // float k offset 0,8,16,24

    float4 va[2], vw[2];
    auto loadT = [&](int k0) {
        va[0] = *(const float4*)(A + (size_t)(bm + rr) * Dm + k0 + kq);
        va[1] = *(const float4*)(A + (size_t)(bm + rr) * Dm + k0 + kq + 4);
        vw[0] = *(const float4*)(W + (size_t)(bn + rr) * Dm + k0 + kq);
        vw[1] = *(const float4*)(W + (size_t)(bn + rr) * Dm + k0 + kq + 4);
    };
    auto storeT = [&](int st) {
        const float* fa = (const float*)&va[0];
        const float* fw = (const float*)&vw[0];
        uint4 ua, uw;
        ua.x = f2h2(fa[0], fa[1]); ua.y = f2h2(fa[2], fa[3]);
        ua.z = f2h2(fa[4], fa[5]); ua.w = f2h2(fa[6], fa[7]);
        uw.x = f2h2(fw[0], fw[1]); uw.y = f2h2(fw[2], fw[3]);
        uw.z = f2h2(fw[4], fw[5]); uw.w = f2h2(fw[6], fw[7]);
        *(uint4*)&As2[st][rr][(tid & 3) * 4] = ua;
        *(uint4*)&Ws2[st][rr][(tid & 3) * 4] = uw;
    };

    loadT(0);
    storeT(0);
    __syncthreads();

#pragma unroll
    for (int it = 0; it < 8; it++) {
        const int cur = it & 1;
        const bool more = (it + 1) < 8;
        if (more) loadT((it + 1) * 32);

#pragma unroll
        for (int kb = 0; kb < 2; kb++) {
            uint32_t a[4];
            a[0] = As2[cur][wm + gid    ][kb * 8 + tig    ];
            a[1] = As2[cur][wm + gid + 8][kb * 8 + tig    ];
            a[2] = As2[cur][wm + gid    ][kb * 8 + tig + 4];
            a[3] = As2[cur][wm + gid + 8][kb * 8 + tig + 4];
#pragma unroll
            for (int nb = 0; nb < 4; nb++) {
                uint32_t b0 = Ws2[cur][wn + nb * 8 + gid][kb * 8 + tig    ];
                uint32_t b1 = Ws2[cur][wn + nb * 8 + gid][kb * 8 + tig + 4];
                mma_f16(acc[nb], a, b0, b1);
            }
        }

        if (more) storeT(cur ^ 1);
        __syncthreads();
    }

    const int row = bm + wm + gid;
#pragma unroll
    for (int nb = 0; nb < 4; nb++) {
        const int col = bn + wn + nb * 8 + 2 * tig;
        const float b0 = bias[col], b1 = bias[col + 1];
        *(float2*)(C + (size_t)row * Dm + col) =
            make_float2(acc[nb][0] + b0, acc[nb][1] + b1);
        *(float2*)(C + (size_t)(row + 8) * Dm + col) =
            make_float2(acc[nb][2] + b0, acc[nb][3] + b1);
    }
}

// ---------------------------------------------------------------------------
// O projection with FUSED split-KV combine, 256 threads, double-buffered.
// A rows are built on the fly from Po/Pm/Pl (normalized attention output).
// ---------------------------------------------------------------------------
__global__ __launch_bounds__(256)
void gemm_out_f16(const float* __restrict__ Po, const float* __restrict__ Pm,
                  const float* __restrict__ Pl, const float* __restrict__ W,
                  const float* __restrict__ bias, float* __restrict__ C)
{
    __shared__ uint32_t As2[2][64][KS2];
    __shared__ uint32_t Ws2[2][64][KS2];

    const int bm = blockIdx.x * 64;
    const int bn = blockIdx.y * 64;
    const int tid  = threadIdx.x;
    const int warp = tid >> 5;
    const int lane = tid & 31;
    const int gid  = lane >> 2;
    const int tig  = lane & 3;
    const int wm = (warp >> 1) * 16;
    const int wn = (warp & 1) * 32;

    float acc[4][4];
#pragma unroll
    for (int nb = 0; nb < 4; nb++)
#pragma unroll
        for (int j = 0; j < 4; j++) acc[nb][j] = 0.f;

    const int rr = tid >> 2;          // row within block (0..63)
    const int kq = (tid & 3) * 8;     // k offset within 32-chunk (0,8,16,24)

    const int rowg = bm + rr;
    const int b = rowg >> 9;          // rowg / Sq
    const int q = rowg & (Sq - 1);

    float4 p0[2], p1[2], vw[2];
    float w0c, w1c;

    auto loadT = [&](int k0) {
        const int h  = k0 >> 5;           // head for this 32-chunk
        const int bh = b * NH + h;
        const size_t i0 = (size_t)(bh * NSPLIT + 0) * Sq + q;
        const size_t i1 = i0 + Sq;
        const float m0 = Pm[i0], m1 = Pm[i1];
        const float l0 = Pl[i0], l1 = Pl[i1];
        const float m  = fmaxf(m0, m1);
        float w0 = __expf(m0 - m);
        float w1 = __expf(m1 - m);
        const float inv = 1.f / (l0 * w0 + l1 * w1);
        w0c = w0 * inv; w1c = w1 * inv;
        p0[0] = *(const float4*)(Po + i0 * HD + kq);
        p0[1] = *(const float4*)(Po + i0 * HD + kq + 4);
        p1[0] = *(const float4*)(Po + i1 * HD + kq);
        p1[1] = *(const float4*)(Po + i1 * HD + kq + 4);
        vw[0] = *(const float4*)(W + (size_t)(bn + rr) * Dm + k0 + kq);
        vw[1] = *(const float4*)(W + (size_t)(bn + rr) * Dm + k0 + kq + 4);
    };
    auto storeT = [&](int st) {
        const float* f0 = (const float*)&p0[0];
        const float* f1 = (const float*)&p1[0];
        const float* fw = (const float*)&vw[0];
        uint4 ua, uw;
        ua.x = f2h2(f0[0] * w0c + f1[0] * w1c, f0[1] * w0c + f1[1] * w1c);
        ua.y = f2h2(f0[2] * w0c + f1[2] * w1c, f0[3] * w0c + f1[3] * w1c);
        ua.z = f2h2(f0[4] * w0c + f1[4] * w1c, f0[5] * w0c + f1[5] * w1c);
        ua.w = f2h2(f0[6] * w0c + f1[6] * w1c, f0[7] * w0c + f1[7] * w1c);
        uw.x = f2h2(fw[0], fw[1]); uw.y = f2h2(fw[2], fw[3]);
        uw.z = f2h2(fw[4], fw[5]); uw.w = f2h2(fw[6], fw[7]);
        *(uint4*)&As2[st][rr][(tid & 3) * 4] = ua;
        *(uint4*)&Ws2[st][rr][(tid & 3) * 4] = uw;
    };

    loadT(0);
    storeT(0);
    __syncthreads();

#pragma unroll
    for (int it = 0; it < 8; it++) {
        const int cur = it & 1;
        const bool more = (it + 1) < 8;
        if (more) loadT((it + 1) * 32);

#pragma unroll
        for (int kb = 0; kb < 2; kb++) {
            uint32_t a[4];
            a[0] = As2[cur][wm + gid    ][kb * 8 + tig    ];
            a[1] = As2[cur][wm + gid + 8][kb * 8 + tig    ];
            a[2] = As2[cur][wm + gid    ][kb * 8 + tig + 4];
            a[3] = As2[cur][wm + gid + 8][kb * 8 + tig + 4];
#pragma unroll
            for (int nb = 0; nb < 4; nb++) {
                uint32_t b0 = Ws2[cur][wn + nb * 8 + gid][kb * 8 + tig    ];
                uint32_t b1 = Ws2[cur][wn + nb * 8 + gid][kb * 8 + tig + 4];
                mma_f16(acc[nb], a, b0, b1);
            }
        }

        if (more) storeT(cur ^ 1);
        __syncthreads();
    }

    const int row = bm + wm + gid;
#pragma unroll
    for (int nb = 0; nb < 4; nb++) {
        const int col = bn + wn + nb * 8 + 2 * tig;
        const float b0 = bias[col], b1 = bias[col + 1];
        *(float2*)(C + (size_t)row * Dm + col) =
            make_float2(acc[nb][0] + b0, acc[nb][1] + b1);
        *(float2*)(C + (size_t)(row + 8) * Dm + col) =
            make_float2(acc[nb][2] + b0, acc[nb][3] + b1);
    }
}

// ---------------------------------------------------------------------------
// fp16 flash attention, split-KV, double-buffered, half K/V in gmem.
// ---------------------------------------------------------------------------
__global__ __launch_bounds__(128)
void attn_mma(const float* __restrict__ Q, const __half* __restrict__ K,
              const __half* __restrict__ V, float* __restrict__ Po,
              float* __restrict__ Pm, float* __restrict__ Pl)
{
    const int h  = blockIdx.y;
    const int bz = blockIdx.z;
    const int b  = bz >> 1;
    const int sp = bz & 1;
    const int q0 = blockIdx.x * 64;

    __shared__ uint32_t Ks2[2][64][KS2];   // [key][d2]
    __shared__ uint32_t Vs2[2][32][VS2];   // [d][key2]

    const int tid  = threadIdx.x;
    const int warp = tid >> 5;
    const int lane = tid & 31;
    const int gid  = lane >> 2;
    const int tig  = lane & 3;

    const float scale = 0.17677669529663687f;  // 1/sqrt(32)

    uint32_t qa[2][4];
    {
        const float* Qb = Q + ((size_t)(b * Sq + q0 + warp * 16)) * Dm + h * HD;
#pragma unroll
        for (int kb = 0; kb < 2; kb++) {
            const int d0 = kb * 16 + 2 * tig;
            qa[kb][0] = f2h2(Qb[(size_t)gid       * Dm + d0    ] * scale,
                             Qb[(size_t)gid       * Dm + d0 + 1] * scale);
            qa[kb][1] = f2h2(Qb[(size_t)(gid + 8) * Dm + d0    ] * scale,
                             Qb[(size_t)(gid + 8) * Dm + d0 + 1] * scale);
            qa[kb][2] = f2h2(Qb[(size_t)gid       * Dm + d0 + 8] * scale,
                             Qb[(size_t)gid       * Dm + d0 + 9] * scale);
            qa[kb][3] = f2h2(Qb[(size_t)(gid + 8) * Dm + d0 + 8] * scale,
                             Qb[(size_t)(gid + 8) * Dm + d0 + 9] * scale);
        }
    }

    float m_lo = -1e30f, m_hi = -1e30f;
    float l_lo = 0.f,    l_hi = 0.f;
    float o[4][4];
#pragma unroll
    for (int nb = 0; nb < 4; nb++)
#pragma unroll
        for (int i = 0; i < 4; i++) o[nb][i] = 0.f;

    const __half* Kb = K + (size_t)b * HWk * Dm + h * HD;
    const __half* Vb = V + (size_t)b * HWk * Dm + h * HD;

    const int krow = tid >> 1;
    const int kdc  = (tid & 1) * 16;
    const int vk2 = tid >> 2;
    const int vdc = (tid & 3) * 8;

    const int jbeg = sp * (HWk / NSPLIT);
    const int jend = jbeg + (HWk / NSPLIT);

    uint4 rk[2], rv[2];
    auto loadKV = [&](int j0) {
        rk[0] = *(const uint4*)(Kb + (size_t)(j0 + krow) * Dm + kdc);
        rk[1] = *(const uint4*)(Kb + (size_t)(j0 + krow) * Dm + kdc + 8);
        rv[0] = *(const uint4*)(Vb + (size_t)(j0 + 2 * vk2)     * Dm + vdc);
        rv[1] = *(const uint4*)(Vb + (size_t)(j0 + 2 * vk2 + 1) * Dm + vdc);
    };
    auto storeKV = [&](int st) {
        const uint32_t* kw = (const uint32_t*)&rk[0];
#pragma unroll
        for (int j = 0; j < 8; j++)
            Ks2[st][krow][(tid & 1) * 8 + j] = kw[j];
        const __half* h0 = (const __half*)&rv[0];
        const __half* h1 = (const __half*)&rv[1];
#pragma unroll
        for (int j = 0; j < 8; j++) {
            __half2 p = __halves2half2(h0[j], h1[j]);
            Vs2[st][vdc + j][vk2] = *(uint32_t*)&p;
        }
    };

    loadKV(jbeg);
    storeKV(0);
    __syncthreads();

    int stage = 0;
    for (int j0 = jbeg; j0 < jend; j0 += 64) {
        const bool more = (j0 + 64) < jend;
        if (more) loadKV(j0 + 64);

        // ---- S = Q K^T ----
        float s[8][4];
#pragma unroll
        for (int nb = 0; nb < 8; nb++)
#pragma unroll
            for (int i = 0; i < 4; i++) s[nb][i] = 0.f;

#pragma unroll
        for (int kb = 0; kb < 2; kb++) {
#pragma unroll
            for (int nb = 0; nb < 8; nb++) {
                uint32_t b0 = Ks2[stage][nb * 8 + gid][kb * 8 + tig    ];
                uint32_t b1 = Ks2[stage][nb * 8 + gid][kb * 8 + tig + 4];
                mma_f16(s[nb], qa[kb], b0, b1);
            }
        }

        // ---- online softmax ----
        float tmax_lo = -1e30f, tmax_hi = -1e30f;
#pragma unroll
        for (int nb = 0; nb < 8; nb++) {
            tmax_lo = fmaxf(tmax_lo, fmaxf(s[nb][0], s[nb][1]));
            tmax_hi = fmaxf(tmax_hi, fmaxf(s[nb][2], s[nb][3]));
        }
        tmax_lo = fmaxf(tmax_lo, __shfl_xor_sync(0xffffffffu, tmax_lo, 1));
        tmax_lo = fmaxf(tmax_lo, __shfl_xor_sync(0xffffffffu, tmax_lo, 2));
        tmax_hi = fmaxf(tmax_hi, __shfl_xor_sync(0xffffffffu, tmax_hi, 1));
        tmax_hi = fmaxf(tmax_hi, __shfl_xor_sync(0xffffffffu, tmax_hi, 2));

        const float mn_lo = fmaxf(m_lo, tmax_lo);
        const float mn_hi = fmaxf(m_hi, tmax_hi);
        const float al_lo = __expf(m_lo - mn_lo);
        const float al_hi = __expf(m_hi - mn_hi);
        m_lo = mn_lo; m_hi = mn_hi;
        l_lo *= al_lo; l_hi *= al_hi;
#pragma unroll
        for (int nb = 0; nb < 4; nb++) {
            o[nb][0] *= al_lo; o[nb][1] *= al_lo;
            o[nb][2] *= al_hi; o[nb][3] *= al_hi;
        }

        // ---- exp + O += P V ----
#pragma unroll
        for (int kb = 0; kb < 4; kb++) {
            const float p0 = __expf(s[2 * kb    ][0] - mn_lo);
            const float p1 = __expf(s[2 * kb    ][1] - mn_lo);
            const float p2 = __expf(s[2 * kb    ][2] - mn_hi);
            const float p3 = __expf(s[2 * kb    ][3] - mn_hi);
            const float r0 = __expf(s[2 * kb + 1][0] - mn_lo);
            const float r1 = __expf(s[2 * kb + 1][1] - mn_lo);
            const float r2 = __expf(s[2 * kb + 1][2] - mn_hi);
            const float r3 = __expf(s[2 * kb + 1][3] - mn_hi);
            l_lo += p0 + p1 + r0 + r1;
            l_hi += p2 + p3 + r2 + r3;
            uint32_t pa[4];
            pa[0] = f2h2(p0, p1);
            pa[1] = f2h2(p2, p3);
            pa[2] = f2h2(r0, r1);
            pa[3] = f2h2(r2, r3);
#pragma unroll
            for (int nb = 0; nb < 4; nb++) {
                uint32_t b0 = Vs2[stage][nb * 8 + gid][kb * 8 + tig    ];
                uint32_t b1 = Vs2[stage][nb * 8 + gid][kb * 8 + tig + 4];
                mma_f16(o[nb], pa, b0, b1);
            }
        }

        if (more) storeKV(stage ^ 1);
        __syncthreads();
        stage ^= 1;
    }

    l_lo += __shfl_xor_sync(0xffffffffu, l_lo, 1);
    l_lo += __shfl_xor_sync(0xffffffffu, l_lo, 2);
    l_hi += __shfl_xor_sync(0xffffffffu, l_hi, 1);
    l_hi += __shfl_xor_sync(0xffffffffu, l_hi, 2);

    const int row0 = (((b * NH + h) * NSPLIT) + sp) * Sq + q0 + warp * 16;
#pragma unroll
    for (int nb = 0; nb < 4; nb++) {
        *(float2*)(Po + (size_t)(row0 + gid)     * HD + nb * 8 + 2 * tig) =
            make_float2(o[nb][0], o[nb][1]);
        *(float2*)(Po + (size_t)(row0 + gid + 8) * HD + nb * 8 + 2 * tig) =
            make_float2(o[nb][2], o[nb][3]);
    }
    if (tig == 0) {
        Pm[row0 + gid]     = m_lo;  Pl[row0 + gid]     = l_lo;
        Pm[row0 + gid + 8] = m_hi;  Pl[row0 + gid + 8] = l_hi;
    }
}

// ---------------------------------------------------------------------------
// Launch
// ---------------------------------------------------------------------------
extern "C" void kernel_launch(void* const* d_in, const int* in_sizes, int n_in,
                              void* d_out, int out_size)
{
    const float* query = (const float*)d_in[0];
    const float* keyv  = (const float*)d_in[1];
    const float* Wq    = (const float*)d_in[2];
    const float* bq    = (const float*)d_in[3];
    const float* Wk    = (const float*)d_in[4];
    const float* bk    = (const float*)d_in[5];
    const float* Wv    = (const float*)d_in[6];
    const float* bv    = (const float*)d_in[7];
    const float* Wo    = (const float*)d_in[8];
    const float* bo    = (const float*)d_in[9];
    float* out = (float*)d_out;

    float *dQ, *dPo, *dPm, *dPl;
    __half *dK, *dV;
    cudaGetSymbolAddress((void**)&dQ, g_Q);
    cudaGetSymbolAddress((void**)&dK, g_K);
    cudaGetSymbolAddress((void**)&dV, g_V);
    cudaGetSymbolAddress((void**)&dPo, g_Po);
    cudaGetSymbolAddress((void**)&dPm, g_Pm);
    cudaGetSymbolAddress((void**)&dPl, g_Pl);

    // Q projection
    {
        dim3 grid((Bsz * Sq) / 64, Dm / 64);
        gemm_q_f16<<<grid, 256>>>(query, Wq, bq, dQ);
    }
    // fused K+V projections (one launch, all batches), half output
    {
        dim3 grid(HWk / 128, Dm / 128, Bsz * 2);
        gemm_kv_fused<<<grid, 256>>>(keyv, Wk, bk, Wv, bv, dK, dV);
    }
    // attention (split-KV)
    {
        dim3 grid(Sq / 64, NH, Bsz * NSPLIT);
        attn_mma<<<grid, 128>>>(dQ, dK, dV, dPo, dPm, dPl);
    }
    // output projection with fused combine -> d_out
    {
        dim3 grid((Bsz * Sq) / 64, Dm / 64);
        gemm_out_f16<<<grid, 256>>>(dPo, dPm, dPl, Wo, bo, out);
    }
}

// round 9
// speedup vs baseline: 1.8510x; 1.0741x over previous
#include <cuda_runtime.h>
#include <cuda_fp16.h>
#include <cstdint>

// Problem dims (fixed)
#define Dm   256
#define Bsz  4
#define Sq   512
#define HWk  4096
#define NH   8
#define HD   32
#define NSPLIT 4

// Scratch (no cudaMalloc allowed)
__device__ float  g_Q[Bsz * Sq * Dm];
__device__ __half g_K[Bsz * HWk * Dm];
__device__ __half g_V[Bsz * HWk * Dm];
__device__ float  g_Po[Bsz * NH * NSPLIT * Sq * HD];
__device__ float  g_Pm[Bsz * NH * NSPLIT * Sq];
__device__ float  g_Pl[Bsz * NH * NSPLIT * Sq];

__device__ __forceinline__ uint32_t f2h2(float x, float y) {
    __half2 h = __floats2half2_rn(x, y);
    return *reinterpret_cast<uint32_t*>(&h);
}

__device__ __forceinline__ float ex2f(float x) {
    float r;
    asm("ex2.approx.f32 %0, %1;" : "=f"(r) : "f"(x));
    return r;
}

// mma.m16n8k16 f16 inputs, f32 accumulate
__device__ __forceinline__ void mma_f16(float c[4], const uint32_t a[4],
                                        uint32_t b0, uint32_t b1) {
    asm volatile(
        "mma.sync.aligned.m16n8k16.row.col.f32.f16.f16.f32 "
        "{%0,%1,%2,%3}, {%4,%5,%6,%7}, {%8,%9}, {%0,%1,%2,%3};"
        : "+f"(c[0]), "+f"(c[1]), "+f"(c[2]), "+f"(c[3])
        : "r"(a[0]), "r"(a[1]), "r"(a[2]), "r"(a[3]), "r"(b0), "r"(b1));
}

#define KS2 20   // attn/O-proj [row][k2] tiles: 16 data words + 4 pad
#define KSG 17   // proj tiles: odd stride keeps store conflicts low
#define VS2 36   // attn V [d][key2] tile

// ---------------------------------------------------------------------------
// FUSED projections: grid.z in [0,9).
//  z<8 : KV projection (b = z>>1, K/V = z&1), A is kv[b] (D x HW), half out.
//  z==8: Q projection, A row-major (B*S x D), fp32 out; only x<16 active.
// BM=128, BN=128, BK=32, 8 warps (4m x 2n), warp tile 32x64, double-buffered.
// ---------------------------------------------------------------------------
__global__ __launch_bounds__(256)
void gemm_proj_fused(const float* __restrict__ KVin,
                     const float* __restrict__ Wk, const float* __restrict__ bk,
                     const float* __restrict__ Wv, const float* __restrict__ bv,
                     __half* __restrict__ Kout, __half* __restrict__ Vout,
                     const float* __restrict__ Qin, const float* __restrict__ Wq,
                     const float* __restrict__ bq, float* __restrict__ Qout)
{
    const int z = blockIdx.z;
    const bool isq = (z == 8);
    if (isq && blockIdx.x >= (Bsz * Sq) / 128) return;

    const int b = z >> 1;
    const int isv = z & 1;
    const float* A;
    const float* W;
    const float* bias;
    if (isq) { A = Qin; W = Wq; bias = bq; }
    else {
        A    = KVin + (size_t)b * Dm * HWk;
        W    = isv ? Wv : Wk;
        bias = isv ? bv : bk;
    }

    __shared__ uint32_t As2[2][128][KSG];   // [m][k2]
    __shared__ uint32_t Ws2[2][128][KSG];   // [n][k2]

    const int bm = blockIdx.x * 128;
    const int bn = blockIdx.y * 128;
    const int tid  = threadIdx.x;
    const int warp = tid >> 5;
    const int lane = tid & 31;
    const int gid  = lane >> 2;
    const int tig  = lane & 3;
    const int wm = (warp >> 1) * 32;
    const int wn = (warp & 1) * 64;

    float acc[2][8][4];
#pragma unroll
    for (int mf = 0; mf < 2; mf++)
#pragma unroll
        for (int nb = 0; nb < 8; nb++)
#pragma unroll
            for (int j = 0; j < 4; j++) acc[mf][nb][j] = 0.f;

    const int k2 = tid >> 4;          // KV A loader
    const int mc = (tid & 15) * 8;
    const int rr = tid >> 1;          // W / Q-A loader
    const int kc = (tid & 1) * 16;

    float4 ra0[2], ra1[2], rq[4], rw[4];

    auto loadT = [&](int k0) {
        if (isq) {
#pragma unroll
            for (int i = 0; i < 4; i++)
                rq[i] = *(const float4*)(A + (size_t)(bm + rr) * Dm + k0 + kc + 4 * i);
        } else {
#pragma unroll
            for (int i = 0; i < 2; i++) {
                ra0[i] = *(const float4*)(A + (size_t)(k0 + 2 * k2)     * HWk + bm + mc + 4 * i);
                ra1[i] = *(const float4*)(A + (size_t)(k0 + 2 * k2 + 1) * HWk + bm + mc + 4 * i);
            }
        }
#pragma unroll
        for (int i = 0; i < 4; i++)
            rw[i] = *(const float4*)(W + (size_t)(bn + rr) * Dm + k0 + kc + 4 * i);
    };
    auto storeT = [&](int st) {
        if (isq) {
            const float* f = (const float*)&rq[0];
#pragma unroll
            for (int j = 0; j < 8; j++)
                As2[st][rr][(tid & 1) * 8 + j] = f2h2(f[2 * j], f[2 * j + 1]);
        } else {
            const float* lo = (const float*)&ra0[0];
            const float* hi = (const float*)&ra1[0];
#pragma unroll
            for (int i = 0; i < 8; i++)
                As2[st][mc + i][k2] = f2h2(lo[i], hi[i]);
        }
        const float* w = (const float*)&rw[0];
#pragma unroll
        for (int j = 0; j < 8; j++)
            Ws2[st][rr][(tid & 1) * 8 + j] = f2h2(w[2 * j], w[2 * j + 1]);
    };

    loadT(0);
    storeT(0);
    __syncthreads();

#pragma unroll
    for (int it = 0; it < 8; it++) {
        const int cur = it & 1;
        const bool more = (it + 1) < 8;
        if (more) loadT((it + 1) * 32);

#pragma unroll
        for (int kb = 0; kb < 2; kb++) {
            uint32_t a[2][4];
#pragma unroll
            for (int mf = 0; mf < 2; mf++) {
                const int m = wm + mf * 16 + gid;
                a[mf][0] = As2[cur][m    ][kb * 8 + tig    ];
                a[mf][1] = As2[cur][m + 8][kb * 8 + tig    ];
                a[mf][2] = As2[cur][m    ][kb * 8 + tig + 4];
                a[mf][3] = As2[cur][m + 8][kb * 8 + tig + 4];
            }
#pragma unroll
            for (int nb = 0; nb < 8; nb++) {
                uint32_t b0 = Ws2[cur][wn + nb * 8 + gid][kb * 8 + tig    ];
                uint32_t b1 = Ws2[cur][wn + nb * 8 + gid][kb * 8 + tig + 4];
                mma_f16(acc[0][nb], a[0], b0, b1);
                mma_f16(acc[1][nb], a[1], b0, b1);
            }
        }

        if (more) storeT(cur ^ 1);
        __syncthreads();
    }

    if (isq) {
#pragma unroll
        for (int mf = 0; mf < 2; mf++) {
            const int row = bm + wm + mf * 16 + gid;
#pragma unroll
            for (int nb = 0; nb < 8; nb++) {
                const int col = bn + wn + nb * 8 + 2 * tig;
                const float b0 = bias[col], b1 = bias[col + 1];
                *(float2*)(Qout + (size_t)row * Dm + col) =
                    make_float2(acc[mf][nb][0] + b0, acc[mf][nb][1] + b1);
                *(float2*)(Qout + (size_t)(row + 8) * Dm + col) =
                    make_float2(acc[mf][nb][2] + b0, acc[mf][nb][3] + b1);
            }
        }
    } else {
        __half* C = (isv ? Vout : Kout) + (size_t)b * HWk * Dm;
#pragma unroll
        for (int mf = 0; mf < 2; mf++) {
            const int row = bm + wm + mf * 16 + gid;
#pragma unroll
            for (int nb = 0; nb < 8; nb++) {
                const int col = bn + wn + nb * 8 + 2 * tig;
                const float b0 = bias[col], b1 = bias[col + 1];
                *(uint32_t*)(C + (size_t)row * Dm + col) =
                    f2h2(acc[mf][nb][0] + b0, acc[mf][nb][1] + b1);
                *(uint32_t*)(C + (size_t)(row + 8) * Dm + col) =
                    f2h2(acc[mf][nb][2] + b0, acc[mf][nb][3] + b1);
            }
        }
    }
}

// ---------------------------------------------------------------------------
// O projection with FUSED 4-way split-KV combine, 256 threads, dbl-buffered.
// ---------------------------------------------------------------------------
__global__ __launch_bounds__(256)
void gemm_out_f16(const float* __restrict__ Po, const float* __restrict__ Pm,
                  const float* __restrict__ Pl, const float* __restrict__ W,
                  const float* __restrict__ bias, float* __restrict__ C)
{
    __shared__ uint32_t As2[2][64][KS2];
    __shared__ uint32_t Ws2[2][64][KS2];

    const int bm = blockIdx.x * 64;
    const int bn = blockIdx.y * 64;
    const int tid  = threadIdx.x;
    const int warp = tid >> 5;
    const int lane = tid & 31;
    const int gid  = lane >> 2;
    const int tig  = lane & 3;
    const int wm = (warp >> 1) * 16;
    const int wn = (warp & 1) * 32;

    float acc[4][4];
#pragma unroll
    for (int nb = 0; nb < 4; nb++)
#pragma unroll
        for (int j = 0; j < 4; j++) acc[nb][j] = 0.f;

    const int rr = tid >> 2;
    const int kq = (tid & 3) * 8;

    const int rowg = bm + rr;
    const int b = rowg >> 9;
    const int q = rowg & (Sq - 1);

    float4 ps[NSPLIT][2], vw[2];
    float wc[NSPLIT];

    auto loadT = [&](int k0) {
        const int h  = k0 >> 5;
        const int bh = b * NH + h;
        const size_t i0 = (size_t)(bh * NSPLIT) * Sq + q;
        float mv[NSPLIT], lv[NSPLIT];
        float m = -1e30f;
#pragma unroll
        for (int s = 0; s < NSPLIT; s++) {
            mv[s] = Pm[i0 + (size_t)s * Sq];
            lv[s] = Pl[i0 + (size_t)s * Sq];
            m = fmaxf(m, mv[s]);
        }
        float denom = 0.f;
#pragma unroll
        for (int s = 0; s < NSPLIT; s++) {
            wc[s] = ex2f(mv[s] - m);
            denom += lv[s] * wc[s];
        }
        const float inv = 1.f / denom;
#pragma unroll
        for (int s = 0; s < NSPLIT; s++) {
            wc[s] *= inv;
            ps[s][0] = *(const float4*)(Po + (i0 + (size_t)s * Sq) * HD + kq);
            ps[s][1] = *(const float4*)(Po + (i0 + (size_t)s * Sq) * HD + kq + 4);
        }
        vw[0] = *(const float4*)(W + (size_t)(bn + rr) * Dm + k0 + kq);
        vw[1] = *(const float4*)(W + (size_t)(bn + rr) * Dm + k0 + kq + 4);
    };
    auto storeT = [&](int st) {
        float av[8];
#pragma unroll
        for (int j = 0; j < 8; j++) {
            float acc_j = 0.f;
#pragma unroll
            for (int s = 0; s < NSPLIT; s++)
                acc_j += ((const float*)&ps[s][0])[j] * wc[s];
            av[j] = acc_j;
        }
        const float* fw = (const float*)&vw[0];
        uint4 ua, uw;
        ua.x = f2h2(av[0], av[1]); ua.y = f2h2(av[2], av[3]);
        ua.z = f2h2(av[4], av[5]); ua.w = f2h2(av[6], av[7]);
        uw.x = f2h2(fw[0], fw[1]); uw.y = f2h2(fw[2], fw[3]);
        uw.z = f2h2(fw[4], fw[5]); uw.w = f2h2(fw[6], fw[7]);
        *(uint4*)&As2[st][rr][(tid & 3) * 4] = ua;
        *(uint4*)&Ws2[st][rr][(tid & 3) * 4] = uw;
    };

    loadT(0);
    storeT(0);
    __syncthreads();

#pragma unroll
    for (int it = 0; it < 8; it++) {
        const int cur = it & 1;
        const bool more = (it + 1) < 8;
        if (more) loadT((it + 1) * 32);

#pragma unroll
        for (int kb = 0; kb < 2; kb++) {
            uint32_t a[4];
            a[0] = As2[cur][wm + gid    ][kb * 8 + tig    ];
            a[1] = As2[cur][wm + gid + 8][kb * 8 + tig    ];
            a[2] = As2[cur][wm + gid    ][kb * 8 + tig + 4];
            a[3] = As2[cur][wm + gid + 8][kb * 8 + tig + 4];
#pragma unroll
            for (int nb = 0; nb < 4; nb++) {
                uint32_t b0 = Ws2[cur][wn + nb * 8 + gid][kb * 8 + tig    ];
                uint32_t b1 = Ws2[cur][wn + nb * 8 + gid][kb * 8 + tig + 4];
                mma_f16(acc[nb], a, b0, b1);
            }
        }

        if (more) storeT(cur ^ 1);
        __syncthreads();
    }

    const int row = bm + wm + gid;
#pragma unroll
    for (int nb = 0; nb < 4; nb++) {
        const int col = bn + wn + nb * 8 + 2 * tig;
        const float b0 = bias[col], b1 = bias[col + 1];
        *(float2*)(C + (size_t)row * Dm + col) =
            make_float2(acc[nb][0] + b0, acc[nb][1] + b1);
        *(float2*)(C + (size_t)(row + 8) * Dm + col) =
            make_float2(acc[nb][2] + b0, acc[nb][3] + b1);
    }
}

// ---------------------------------------------------------------------------
// fp16 flash attention, split-KV x4, double-buffered, half K/V in gmem.
// exp2-domain softmax (Q pre-scaled by scale*log2e). m/l are in log2 domain.
// ---------------------------------------------------------------------------
__global__ __launch_bounds__(128)
void attn_mma(const float* __restrict__ Q, const __half* __restrict__ K,
              const __half* __restrict__ V, float* __restrict__ Po,
              float* __restrict__ Pm, float* __restrict__ Pl)
{
    const int h  = blockIdx.y;
    const int bz = blockIdx.z;
    const int b  = bz >> 2;
    const int sp = bz & 3;
    const int q0 = blockIdx.x * 64;

    __shared__ uint32_t Ks2[2][64][KS2];   // [key][d2]
    __shared__ uint32_t Vs2[2][32][VS2];   // [d][key2]

    const int tid  = threadIdx.x;
    const int warp = tid >> 5;
    const int lane = tid & 31;
    const int gid  = lane >> 2;
    const int tig  = lane & 3;

    // 1/sqrt(32) * log2(e): softmax done in exp2 domain
    const float scale = 0.17677669529663687f * 1.4426950408889634f;

    uint32_t qa[2][4];
    {
        const float* Qb = Q + ((size_t)(b * Sq + q0 + warp * 16)) * Dm + h * HD;
#pragma unroll
        for (int kb = 0; kb < 2; kb++) {
            const int d0 = kb * 16 + 2 * tig;
            qa[kb][0] = f2h2(Qb[(size_t)gid       * Dm + d0    ] * scale,
                             Qb[(size_t)gid       * Dm + d0 + 1] * scale);
            qa[kb][1] = f2h2(Qb[(size_t)(gid + 8) * Dm + d0    ] * scale,
                             Qb[(size_t)(gid + 8) * Dm + d0 + 1] * scale);
            qa[kb][2] = f2h2(Qb[(size_t)gid       * Dm + d0 + 8] * scale,
                             Qb[(size_t)gid       * Dm + d0 + 9] * scale);
            qa[kb][3] = f2h2(Qb[(size_t)(gid + 8) * Dm + d0 + 8] * scale,
                             Qb[(size_t)(gid + 8) * Dm + d0 + 9] * scale);
        }
    }

    float m_lo = -1e30f, m_hi = -1e30f;
    float l_lo = 0.f,    l_hi = 0.f;
    float o[4][4];
#pragma unroll
    for (int nb = 0; nb < 4; nb++)
#pragma unroll
        for (int i = 0; i < 4; i++) o[nb][i] = 0.f;

    const __half* Kb = K + (size_t)b * HWk * Dm + h * HD;
    const __half* Vb = V + (size_t)b * HWk * Dm + h * HD;

    const int krow = tid >> 1;
    const int kdc  = (tid & 1) * 16;
    const int vk2 = tid >> 2;
    const int vdc = (tid & 3) * 8;

    const int jbeg = sp * (HWk / NSPLIT);
    const int jend = jbeg + (HWk / NSPLIT);

    uint4 rk[2], rv[2];
    auto loadKV = [&](int j0) {
        rk[0] = *(const uint4*)(Kb + (size_t)(j0 + krow) * Dm + kdc);
        rk[1] = *(const uint4*)(Kb + (size_t)(j0 + krow) * Dm + kdc + 8);
        rv[0] = *(const uint4*)(Vb + (size_t)(j0 + 2 * vk2)     * Dm + vdc);
        rv[1] = *(const uint4*)(Vb + (size_t)(j0 + 2 * vk2 + 1) * Dm + vdc);
    };
    auto storeKV = [&](int st) {
        const uint32_t* kw = (const uint32_t*)&rk[0];
#pragma unroll
        for (int j = 0; j < 8; j++)
            Ks2[st][krow][(tid & 1) * 8 + j] = kw[j];
        const __half* h0 = (const __half*)&rv[0];
        const __half* h1 = (const __half*)&rv[1];
#pragma unroll
        for (int j = 0; j < 8; j++) {
            __half2 p = __halves2half2(h0[j], h1[j]);
            Vs2[st][vdc + j][vk2] = *(uint32_t*)&p;
        }
    };

    loadKV(jbeg);
    storeKV(0);
    __syncthreads();

    int stage = 0;
    for (int j0 = jbeg; j0 < jend; j0 += 64) {
        const bool more = (j0 + 64) < jend;
        if (more) loadKV(j0 + 64);

        // ---- S = Q K^T (log2 domain) ----
        float s[8][4];
#pragma unroll
        for (int nb = 0; nb < 8; nb++)
#pragma unroll
            for (int i = 0; i < 4; i++) s[nb][i] = 0.f;

#pragma unroll
        for (int kb = 0; kb < 2; kb++) {
#pragma unroll
            for (int nb = 0; nb < 8; nb++) {
                uint32_t b0 = Ks2[stage][nb * 8 + gid][kb * 8 + tig    ];
                uint32_t b1 = Ks2[stage][nb * 8 + gid][kb * 8 + tig + 4];
                mma_f16(s[nb], qa[kb], b0, b1);
            }
        }

        // ---- online softmax (exp2) ----
        float tmax_lo = -1e30f, tmax_hi = -1e30f;
#pragma unroll
        for (int nb = 0; nb < 8; nb++) {
            tmax_lo = fmaxf(tmax_lo, fmaxf(s[nb][0], s[nb][1]));
            tmax_hi = fmaxf(tmax_hi, fmaxf(s[nb][2], s[nb][3]));
        }
        tmax_lo = fmaxf(tmax_lo, __shfl_xor_sync(0xffffffffu, tmax_lo, 1));
        tmax_lo = fmaxf(tmax_lo, __shfl_xor_sync(0xffffffffu, tmax_lo, 2));
        tmax_hi = fmaxf(tmax_hi, __shfl_xor_sync(0xffffffffu, tmax_hi, 1));
        tmax_hi = fmaxf(tmax_hi, __shfl_xor_sync(0xffffffffu, tmax_hi, 2));

        const float mn_lo = fmaxf(m_lo, tmax_lo);
        const float mn_hi = fmaxf(m_hi, tmax_hi);
        const float al_lo = ex2f(m_lo - mn_lo);
        const float al_hi = ex2f(m_hi - mn_hi);
        m_lo = mn_lo; m_hi = mn_hi;
        l_lo *= al_lo; l_hi *= al_hi;
#pragma unroll
        for (int nb = 0; nb < 4; nb++) {
            o[nb][0] *= al_lo; o[nb][1] *= al_lo;
            o[nb][2] *= al_hi; o[nb][3] *= al_hi;
        }

        // ---- exp2 + O += P V ----
#pragma unroll
        for (int kb = 0; kb < 4; kb++) {
            const float p0 = ex2f(s[2 * kb    ][0] - mn_lo);
            const float p1 = ex2f(s[2 * kb    ][1] - mn_lo);
            const float p2 = ex2f(s[2 * kb    ][2] - mn_hi);
            const float p3 = ex2f(s[2 * kb    ][3] - mn_hi);
            const float r0 = ex2f(s[2 * kb + 1][0] - mn_lo);
            const float r1 = ex2f(s[2 * kb + 1][1] - mn_lo);
            const float r2 = ex2f(s[2 * kb + 1][2] - mn_hi);
            const float r3 = ex2f(s[2 * kb + 1][3] - mn_hi);
            l_lo += p0 + p1 + r0 + r1;
            l_hi += p2 + p3 + r2 + r3;
            uint32_t pa[4];
            pa[0] = f2h2(p0, p1);
            pa[1] = f2h2(p2, p3);
            pa[2] = f2h2(r0, r1);
            pa[3] = f2h2(r2, r3);
#pragma unroll
            for (int nb = 0; nb < 4; nb++) {
                uint32_t b0 = Vs2[stage][nb * 8 + gid][kb * 8 + tig    ];
                uint32_t b1 = Vs2[stage][nb * 8 + gid][kb * 8 + tig + 4];
                mma_f16(o[nb], pa, b0, b1);
            }
        }

        if (more) storeKV(stage ^ 1);
        __syncthreads();
        stage ^= 1;
    }

    l_lo += __shfl_xor_sync(0xffffffffu, l_lo, 1);
    l_lo += __shfl_xor_sync(0xffffffffu, l_lo, 2);
    l_hi += __shfl_xor_sync(0xffffffffu, l_hi, 1);
    l_hi += __shfl_xor_sync(0xffffffffu, l_hi, 2);

    const int row0 = (((b * NH + h) * NSPLIT) + sp) * Sq + q0 + warp * 16;
#pragma unroll
    for (int nb = 0; nb < 4; nb++) {
        *(float2*)(Po + (size_t)(row0 + gid)     * HD + nb * 8 + 2 * tig) =
            make_float2(o[nb][0], o[nb][1]);
        *(float2*)(Po + (size_t)(row0 + gid + 8) * HD + nb * 8 + 2 * tig) =
            make_float2(o[nb][2], o[nb][3]);
    }
    if (tig == 0) {
        Pm[row0 + gid]     = m_lo;  Pl[row0 + gid]     = l_lo;
        Pm[row0 + gid + 8] = m_hi;  Pl[row0 + gid + 8] = l_hi;
    }
}

// ---------------------------------------------------------------------------
// Launch
// ---------------------------------------------------------------------------
extern "C" void kernel_launch(void* const* d_in, const int* in_sizes, int n_in,
                              void* d_out, int out_size)
{
    const float* query = (const float*)d_in[0];
    const float* keyv  = (const float*)d_in[1];
    const float* Wq    = (const float*)d_in[2];
    const float* bq    = (const float*)d_in[3];
    const float* Wk    = (const float*)d_in[4];
    const float* bk    = (const float*)d_in[5];
    const float* Wv    = (const float*)d_in[6];
    const float* bv    = (const float*)d_in[7];
    const float* Wo    = (const float*)d_in[8];
    const float* bo    = (const float*)d_in[9];
    float* out = (float*)d_out;

    float *dQ, *dPo, *dPm, *dPl;
    __half *dK, *dV;
    cudaGetSymbolAddress((void**)&dQ, g_Q);
    cudaGetSymbolAddress((void**)&dK, g_K);
    cudaGetSymbolAddress((void**)&dV, g_V);
    cudaGetSymbolAddress((void**)&dPo, g_Po);
    cudaGetSymbolAddress((void**)&dPm, g_Pm);
    cudaGetSymbolAddress((void**)&dPl, g_Pl);

    // fused Q + K + V projections: one launch
    {
        dim3 grid(HWk / 128, Dm / 128, Bsz * 2 + 1);
        gemm_proj_fused<<<grid, 256>>>(keyv, Wk, bk, Wv, bv, dK, dV,
                                       query, Wq, bq, dQ);
    }
    // attention (split-KV x4)
    {
        dim3 grid(Sq / 64, NH, Bsz * NSPLIT);
        attn_mma<<<grid, 128>>>(dQ, dK, dV, dPo, dPm, dPl);
    }
    // output projection with fused 4-way combine -> d_out
    {
        dim3 grid((Bsz * Sq) / 64, Dm / 64);
        gemm_out_f16<<<grid, 256>>>(dPo, dPm, dPl, Wo, bo, out);
    }
}

// round 10
// speedup vs baseline: 1.9978x; 1.0793x over previous
#include <cuda_runtime.h>
#include <cuda_fp16.h>
#include <cstdint>

// Problem dims (fixed)
#define Dm   256
#define Bsz  4
#define Sq   512
#define HWk  4096
#define NH   8
#define HD   32
#define NSPLIT 4

// Scratch (no cudaMalloc allowed)
__device__ float  g_Q[Bsz * Sq * Dm];
__device__ __half g_K[Bsz * HWk * Dm];
__device__ __half g_V[Bsz * HWk * Dm];
__device__ float  g_Po[Bsz * NH * NSPLIT * Sq * HD];
__device__ float  g_Pm[Bsz * NH * NSPLIT * Sq];
__device__ float  g_Pl[Bsz * NH * NSPLIT * Sq];

__device__ __forceinline__ uint32_t f2h2(float x, float y) {
    __half2 h = __floats2half2_rn(x, y);
    return *reinterpret_cast<uint32_t*>(&h);
}

__device__ __forceinline__ float ex2f(float x) {
    float r;
    asm("ex2.approx.f32 %0, %1;" : "=f"(r) : "f"(x));
    return r;
}

// mma.m16n8k16 f16 inputs, f32 accumulate
__device__ __forceinline__ void mma_f16(float c[4], const uint32_t a[4],
                                        uint32_t b0, uint32_t b1) {
    asm volatile(
        "mma.sync.aligned.m16n8k16.row.col.f32.f16.f16.f32 "
        "{%0,%1,%2,%3}, {%4,%5,%6,%7}, {%8,%9}, {%0,%1,%2,%3};"
        : "+f"(c[0]), "+f"(c[1]), "+f"(c[2]), "+f"(c[3])
        : "r"(a[0]), "r"(a[1]), "r"(a[2]), "r"(a[3]), "r"(b0), "r"(b1));
}

#define KS2 20    // [row][k2] tiles: 16 data words + 4 pad (b-frag reads conflict-free)
#define AST 132   // proj A tile [k2][m]: 128 m-words + 4 pad
#define VS2 36    // attn V [d][key2] tile

// ---------------------------------------------------------------------------
// FUSED projections: grid.z in [0,9).
//  z<8 : KV projection (b = z>>1, K/V = z&1), A is kv[b] (D x HW), half out.
//  z==8: Q projection, A row-major (B*S x D), fp32 out; only x<16 active.
// BM=128, BN=128, BK=32, 8 warps (4m x 2n), warp tile 32x64, double-buffered.
// A tile stored k2-major so KV loaders use STS.128; 2 CTAs/SM enforced.
// ---------------------------------------------------------------------------
__global__ __launch_bounds__(256, 2)
void gemm_proj_fused(const float* __restrict__ KVin,
                     const float* __restrict__ Wk, const float* __restrict__ bk,
                     const float* __restrict__ Wv, const float* __restrict__ bv,
                     __half* __restrict__ Kout, __half* __restrict__ Vout,
                     const float* __restrict__ Qin, const float* __restrict__ Wq,
                     const float* __restrict__ bq, float* __restrict__ Qout)
{
    const int z = blockIdx.z;
    const bool isq = (z == 8);
    if (isq && blockIdx.x >= (Bsz * Sq) / 128) return;

    const int b = z >> 1;
    const int isv = z & 1;
    const float* A;
    const float* W;
    const float* bias;
    if (isq) { A = Qin; W = Wq; bias = bq; }
    else {
        A    = KVin + (size_t)b * Dm * HWk;
        W    = isv ? Wv : Wk;
        bias = isv ? bv : bk;
    }

    __shared__ uint32_t As2[2][16][AST];   // [k2][m] (k2-major)
    __shared__ uint32_t Ws2[2][128][KS2];  // [n][k2]

    const int bm = blockIdx.x * 128;
    const int bn = blockIdx.y * 128;
    const int tid  = threadIdx.x;
    const int warp = tid >> 5;
    const int lane = tid & 31;
    const int gid  = lane >> 2;
    const int tig  = lane & 3;
    const int wm = (warp >> 1) * 32;
    const int wn = (warp & 1) * 64;

    float acc[2][8][4];
#pragma unroll
    for (int mf = 0; mf < 2; mf++)
#pragma unroll
        for (int nb = 0; nb < 8; nb++)
#pragma unroll
            for (int j = 0; j < 4; j++) acc[mf][nb][j] = 0.f;

    const int k2 = tid >> 4;          // KV A loader: k2-pair row 0..15
    const int mc = (tid & 15) * 8;    //              m chunk
    const int rr = tid >> 1;          // W / Q-A loader row
    const int kc = (tid & 1) * 16;    //              k float offset

    float4 rb[4], rw[4];              // unified 16-float A buffer + W buffer

    auto loadT = [&](int k0) {
        if (isq) {
#pragma unroll
            for (int i = 0; i < 4; i++)
                rb[i] = *(const float4*)(A + (size_t)(bm + rr) * Dm + k0 + kc + 4 * i);
        } else {
            rb[0] = *(const float4*)(A + (size_t)(k0 + 2 * k2)     * HWk + bm + mc);
            rb[1] = *(const float4*)(A + (size_t)(k0 + 2 * k2)     * HWk + bm + mc + 4);
            rb[2] = *(const float4*)(A + (size_t)(k0 + 2 * k2 + 1) * HWk + bm + mc);
            rb[3] = *(const float4*)(A + (size_t)(k0 + 2 * k2 + 1) * HWk + bm + mc + 4);
        }
#pragma unroll
        for (int i = 0; i < 4; i++)
            rw[i] = *(const float4*)(W + (size_t)(bn + rr) * Dm + k0 + kc + 4 * i);
    };
    auto storeT = [&](int st) {
        if (isq) {
            // Q holds 16 consecutive k for one m: column writes (Q is 1/9 of CTAs)
            const float* f = (const float*)&rb[0];
#pragma unroll
            for (int j = 0; j < 8; j++)
                As2[st][(tid & 1) * 8 + j][rr] = f2h2(f[2 * j], f[2 * j + 1]);
        } else {
            // KV holds 8 consecutive m for k-pair: 2x STS.128
            const float* lo = (const float*)&rb[0];   // k even
            const float* hi = (const float*)&rb[2];   // k odd
            uint4 u0, u1;
            u0.x = f2h2(lo[0], hi[0]); u0.y = f2h2(lo[1], hi[1]);
            u0.z = f2h2(lo[2], hi[2]); u0.w = f2h2(lo[3], hi[3]);
            u1.x = f2h2(lo[4], hi[4]); u1.y = f2h2(lo[5], hi[5]);
            u1.z = f2h2(lo[6], hi[6]); u1.w = f2h2(lo[7], hi[7]);
            *(uint4*)&As2[st][k2][mc]     = u0;
            *(uint4*)&As2[st][k2][mc + 4] = u1;
        }
        // W holds 16 consecutive k for one n: 2x STS.128
        const float* w = (const float*)&rw[0];
        uint4 v0, v1;
        v0.x = f2h2(w[0],  w[1]);  v0.y = f2h2(w[2],  w[3]);
        v0.z = f2h2(w[4],  w[5]);  v0.w = f2h2(w[6],  w[7]);
        v1.x = f2h2(w[8],  w[9]);  v1.y = f2h2(w[10], w[11]);
        v1.z = f2h2(w[12], w[13]); v1.w = f2h2(w[14], w[15]);
        *(uint4*)&Ws2[st][rr][(tid & 1) * 16 - ((tid & 1) * 8)]     = v0;  // offset 0 or 8
        *(uint4*)&Ws2[st][rr][(tid & 1) * 8 + 4] = v1;
    };

    loadT(0);
    storeT(0);
    __syncthreads();

#pragma unroll
    for (int it = 0; it < 8; it++) {
        const int cur = it & 1;
        const bool more = (it + 1) < 8;
        if (more) loadT((it + 1) * 32);

#pragma unroll
        for (int kb = 0; kb < 2; kb++) {
            uint32_t a[2][4];
#pragma unroll
            for (int mf = 0; mf < 2; mf++) {
                const int m = wm + mf * 16 + gid;
                a[mf][0] = As2[cur][kb * 8 + tig    ][m    ];
                a[mf][1] = As2[cur][kb * 8 + tig    ][m + 8];
                a[mf][2] = As2[cur][kb * 8 + tig + 4][m    ];
                a[mf][3] = As2[cur][kb * 8 + tig + 4][m + 8];
            }
#pragma unroll
            for (int nb = 0; nb < 8; nb++) {
                uint32_t b0 = Ws2[cur][wn + nb * 8 + gid][kb * 8 + tig    ];
                uint32_t b1 = Ws2[cur][wn + nb * 8 + gid][kb * 8 + tig + 4];
                mma_f16(acc[0][nb], a[0], b0, b1);
                mma_f16(acc[1][nb], a[1], b0, b1);
            }
        }

        if (more) storeT(cur ^ 1);
        __syncthreads();
    }

    if (isq) {
#pragma unroll
        for (int mf = 0; mf < 2; mf++) {
            const int row = bm + wm + mf * 16 + gid;
#pragma unroll
            for (int nb = 0; nb < 8; nb++) {
                const int col = bn + wn + nb * 8 + 2 * tig;
                const float b0 = bias[col], b1 = bias[col + 1];
                *(float2*)(Qout + (size_t)row * Dm + col) =
                    make_float2(acc[mf][nb][0] + b0, acc[mf][nb][1] + b1);
                *(float2*)(Qout + (size_t)(row + 8) * Dm + col) =
                    make_float2(acc[mf][nb][2] + b0, acc[mf][nb][3] + b1);
            }
        }
    } else {
        __half* C = (isv ? Vout : Kout) + (size_t)b * HWk * Dm;
#pragma unroll
        for (int mf = 0; mf < 2; mf++) {
            const int row = bm + wm + mf * 16 + gid;
#pragma unroll
            for (int nb = 0; nb < 8; nb++) {
                const int col = bn + wn + nb * 8 + 2 * tig;
                const float b0 = bias[col], b1 = bias[col + 1];
                *(uint32_t*)(C + (size_t)row * Dm + col) =
                    f2h2(acc[mf][nb][0] + b0, acc[mf][nb][1] + b1);
                *(uint32_t*)(C + (size_t)(row + 8) * Dm + col) =
                    f2h2(acc[mf][nb][2] + b0, acc[mf][nb][3] + b1);
            }
        }
    }
}

// ---------------------------------------------------------------------------
// O projection with FUSED 4-way split-KV combine, 256 threads, dbl-buffered.
// ---------------------------------------------------------------------------
__global__ __launch_bounds__(256)
void gemm_out_f16(const float* __restrict__ Po, const float* __restrict__ Pm,
                  const float* __restrict__ Pl, const float* __restrict__ W,
                  const float* __restrict__ bias, float* __restrict__ C)
{
    __shared__ uint32_t As2[2][64][KS2];
    __shared__ uint32_t Ws2[2][64][KS2];

    const int bm = blockIdx.x * 64;
    const int bn = blockIdx.y * 64;
    const int tid  = threadIdx.x;
    const int warp = tid >> 5;
    const int lane = tid & 31;
    const int gid  = lane >> 2;
    const int tig  = lane & 3;
    const int wm = (warp >> 1) * 16;
    const int wn = (warp & 1) * 32;

    float acc[4][4];
#pragma unroll
    for (int nb = 0; nb < 4; nb++)
#pragma unroll
        for (int j = 0; j < 4; j++) acc[nb][j] = 0.f;

    const int rr = tid >> 2;
    const int kq = (tid & 3) * 8;

    const int rowg = bm + rr;
    const int b = rowg >> 9;
    const int q = rowg & (Sq - 1);

    float4 ps[NSPLIT][2], vw[2];
    float wc[NSPLIT];

    auto loadT = [&](int k0) {
        const int h  = k0 >> 5;
        const int bh = b * NH + h;
        const size_t i0 = (size_t)(bh * NSPLIT) * Sq + q;
        float mv[NSPLIT], lv[NSPLIT];
        float m = -1e30f;
#pragma unroll
        for (int s = 0; s < NSPLIT; s++) {
            mv[s] = Pm[i0 + (size_t)s * Sq];
            lv[s] = Pl[i0 + (size_t)s * Sq];
            m = fmaxf(m, mv[s]);
        }
        float denom = 0.f;
#pragma unroll
        for (int s = 0; s < NSPLIT; s++) {
            wc[s] = ex2f(mv[s] - m);
            denom += lv[s] * wc[s];
        }
        const float inv = 1.f / denom;
#pragma unroll
        for (int s = 0; s < NSPLIT; s++) {
            wc[s] *= inv;
            ps[s][0] = *(const float4*)(Po + (i0 + (size_t)s * Sq) * HD + kq);
            ps[s][1] = *(const float4*)(Po + (i0 + (size_t)s * Sq) * HD + kq + 4);
        }
        vw[0] = *(const float4*)(W + (size_t)(bn + rr) * Dm + k0 + kq);
        vw[1] = *(const float4*)(W + (size_t)(bn + rr) * Dm + k0 + kq + 4);
    };
    auto storeT = [&](int st) {
        float av[8];
#pragma unroll
        for (int j = 0; j < 8; j++) {
            float acc_j = 0.f;
#pragma unroll
            for (int s = 0; s < NSPLIT; s++)
                acc_j += ((const float*)&ps[s][0])[j] * wc[s];
            av[j] = acc_j;
        }
        const float* fw = (const float*)&vw[0];
        uint4 ua, uw;
        ua.x = f2h2(av[0], av[1]); ua.y = f2h2(av[2], av[3]);
        ua.z = f2h2(av[4], av[5]); ua.w = f2h2(av[6], av[7]);
        uw.x = f2h2(fw[0], fw[1]); uw.y = f2h2(fw[2], fw[3]);
        uw.z = f2h2(fw[4], fw[5]); uw.w = f2h2(fw[6], fw[7]);
        *(uint4*)&As2[st][rr][(tid & 3) * 4] = ua;
        *(uint4*)&Ws2[st][rr][(tid & 3) * 4] = uw;
    };

    loadT(0);
    storeT(0);
    __syncthreads();

#pragma unroll
    for (int it = 0; it < 8; it++) {
        const int cur = it & 1;
        const bool more = (it + 1) < 8;
        if (more) loadT((it + 1) * 32);

#pragma unroll
        for (int kb = 0; kb < 2; kb++) {
            uint32_t a[4];
            a[0] = As2[cur][wm + gid    ][kb * 8 + tig    ];
            a[1] = As2[cur][wm + gid + 8][kb * 8 + tig    ];
            a[2] = As2[cur][wm + gid    ][kb * 8 + tig + 4];
            a[3] = As2[cur][wm + gid + 8][kb * 8 + tig + 4];
#pragma unroll
            for (int nb = 0; nb < 4; nb++) {
                uint32_t b0 = Ws2[cur][wn + nb * 8 + gid][kb * 8 + tig    ];
                uint32_t b1 = Ws2[cur][wn + nb * 8 + gid][kb * 8 + tig + 4];
                mma_f16(acc[nb], a, b0, b1);
            }
        }

        if (more) storeT(cur ^ 1);
        __syncthreads();
    }

    const int row = bm + wm + gid;
#pragma unroll
    for (int nb = 0; nb < 4; nb++) {
        const int col = bn + wn + nb * 8 + 2 * tig;
        const float b0 = bias[col], b1 = bias[col + 1];
        *(float2*)(C + (size_t)row * Dm + col) =
            make_float2(acc[nb][0] + b0, acc[nb][1] + b1);
        *(float2*)(C + (size_t)(row + 8) * Dm + col) =
            make_float2(acc[nb][2] + b0, acc[nb][3] + b1);
    }
}

// ---------------------------------------------------------------------------
// fp16 flash attention, split-KV x4, double-buffered, half K/V in gmem.
// exp2-domain softmax (Q pre-scaled by scale*log2e).
// ---------------------------------------------------------------------------
__global__ __launch_bounds__(128)
void attn_mma(const float* __restrict__ Q, const __half* __restrict__ K,
              const __half* __restrict__ V, float* __restrict__ Po,
              float* __restrict__ Pm, float* __restrict__ Pl)
{
    const int h  = blockIdx.y;
    const int bz = blockIdx.z;
    const int b  = bz >> 2;
    const int sp = bz & 3;
    const int q0 = blockIdx.x * 64;

    __shared__ uint32_t Ks2[2][64][KS2];   // [key][d2]
    __shared__ uint32_t Vs2[2][32][VS2];   // [d][key2]

    const int tid  = threadIdx.x;
    const int warp = tid >> 5;
    const int lane = tid & 31;
    const int gid  = lane >> 2;
    const int tig  = lane & 3;

    const float scale = 0.17677669529663687f * 1.4426950408889634f;

    uint32_t qa[2][4];
    {
        const float* Qb = Q + ((size_t)(b * Sq + q0 + warp * 16)) * Dm + h * HD;
#pragma unroll
        for (int kb = 0; kb < 2; kb++) {
            const int d0 = kb * 16 + 2 * tig;
            qa[kb][0] = f2h2(Qb[(size_t)gid       * Dm + d0    ] * scale,
                             Qb[(size_t)gid       * Dm + d0 + 1] * scale);
            qa[kb][1] = f2h2(Qb[(size_t)(gid + 8) * Dm + d0    ] * scale,
                             Qb[(size_t)(gid + 8) * Dm + d0 + 1] * scale);
            qa[kb][2] = f2h2(Qb[(size_t)gid       * Dm + d0 + 8] * scale,
                             Qb[(size_t)gid       * Dm + d0 + 9] * scale);
            qa[kb][3] = f2h2(Qb[(size_t)(gid + 8) * Dm + d0 + 8] * scale,
                             Qb[(size_t)(gid + 8) * Dm + d0 + 9] * scale);
        }
    }

    float m_lo = -1e30f, m_hi = -1e30f;
    float l_lo = 0.f,    l_hi = 0.f;
    float o[4][4];
#pragma unroll
    for (int nb = 0; nb < 4; nb++)
#pragma unroll
        for (int i = 0; i < 4; i++) o[nb][i] = 0.f;

    const __half* Kb = K + (size_t)b * HWk * Dm + h * HD;
    const __half* Vb = V + (size_t)b * HWk * Dm + h * HD;

    const int krow = tid >> 1;
    const int kdc  = (tid & 1) * 16;
    const int vk2 = tid >> 2;
    const int vdc = (tid & 3) * 8;

    const int jbeg = sp * (HWk / NSPLIT);
    const int jend = jbeg + (HWk / NSPLIT);

    uint4 rk[2], rv[2];
    auto loadKV = [&](int j0) {
        rk[0] = *(const uint4*)(Kb + (size_t)(j0 + krow) * Dm + kdc);
        rk[1] = *(const uint4*)(Kb + (size_t)(j0 + krow) * Dm + kdc + 8);
        rv[0] = *(const uint4*)(Vb + (size_t)(j0 + 2 * vk2)     * Dm + vdc);
        rv[1] = *(const uint4*)(Vb + (size_t)(j0 + 2 * vk2 + 1) * Dm + vdc);
    };
    auto storeKV = [&](int st) {
        *(uint4*)&Ks2[st][krow][(tid & 1) * 8]     = rk[0];
        *(uint4*)&Ks2[st][krow][(tid & 1) * 8 + 4] = rk[1];
        const __half* h0 = (const __half*)&rv[0];
        const __half* h1 = (const __half*)&rv[1];
#pragma unroll
        for (int j = 0; j < 8; j++) {
            __half2 p = __halves2half2(h0[j], h1[j]);
            Vs2[st][vdc + j][vk2] = *(uint32_t*)&p;
        }
    };

    loadKV(jbeg);
    storeKV(0);
    __syncthreads();

    int stage = 0;
    for (int j0 = jbeg; j0 < jend; j0 += 64) {
        const bool more = (j0 + 64) < jend;
        if (more) loadKV(j0 + 64);

        // ---- S = Q K^T (log2 domain) ----
        float s[8][4];
#pragma unroll
        for (int nb = 0; nb < 8; nb++)
#pragma unroll
            for (int i = 0; i < 4; i++) s[nb][i] = 0.f;

#pragma unroll
        for (int kb = 0; kb < 2; kb++) {
#pragma unroll
            for (int nb = 0; nb < 8; nb++) {
                uint32_t b0 = Ks2[stage][nb * 8 + gid][kb * 8 + tig    ];
                uint32_t b1 = Ks2[stage][nb * 8 + gid][kb * 8 + tig + 4];
                mma_f16(s[nb], qa[kb], b0, b1);
            }
        }

        // ---- online softmax (exp2) ----
        float tmax_lo = -1e30f, tmax_hi = -1e30f;
#pragma unroll
        for (int nb = 0; nb < 8; nb++) {
            tmax_lo = fmaxf(tmax_lo, fmaxf(s[nb][0], s[nb][1]));
            tmax_hi = fmaxf(tmax_hi, fmaxf(s[nb][2], s[nb][3]));
        }
        tmax_lo = fmaxf(tmax_lo, __shfl_xor_sync(0xffffffffu, tmax_lo, 1));
        tmax_lo = fmaxf(tmax_lo, __shfl_xor_sync(0xffffffffu, tmax_lo, 2));
        tmax_hi = fmaxf(tmax_hi, __shfl_xor_sync(0xffffffffu, tmax_hi, 1));
        tmax_hi = fmaxf(tmax_hi, __shfl_xor_sync(0xffffffffu, tmax_hi, 2));

        const float mn_lo = fmaxf(m_lo, tmax_lo);
        const float mn_hi = fmaxf(m_hi, tmax_hi);
        const float al_lo = ex2f(m_lo - mn_lo);
        const float al_hi = ex2f(m_hi - mn_hi);
        m_lo = mn_lo; m_hi = mn_hi;
        l_lo *= al_lo; l_hi *= al_hi;
#pragma unroll
        for (int nb = 0; nb < 4; nb++) {
            o[nb][0] *= al_lo; o[nb][1] *= al_lo;
            o[nb][2] *= al_hi; o[nb][3] *= al_hi;
        }

        // ---- exp2 + O += P V ----
#pragma unroll
        for (int kb = 0; kb < 4; kb++) {
            const float p0 = ex2f(s[2 * kb    ][0] - mn_lo);
            const float p1 = ex2f(s[2 * kb    ][1] - mn_lo);
            const float p2 = ex2f(s[2 * kb    ][2] - mn_hi);
            const float p3 = ex2f(s[2 * kb    ][3] - mn_hi);
            const float r0 = ex2f(s[2 * kb + 1][0] - mn_lo);
            const float r1 = ex2f(s[2 * kb + 1][1] - mn_lo);
            const float r2 = ex2f(s[2 * kb + 1][2] - mn_hi);
            const float r3 = ex2f(s[2 * kb + 1][3] - mn_hi);
            l_lo += p0 + p1 + r0 + r1;
            l_hi += p2 + p3 + r2 + r3;
            uint32_t pa[4];
            pa[0] = f2h2(p0, p1);
            pa[1] = f2h2(p2, p3);
            pa[2] = f2h2(r0, r1);
            pa[3] = f2h2(r2, r3);
#pragma unroll
            for (int nb = 0; nb < 4; nb++) {
                uint32_t b0 = Vs2[stage][nb * 8 + gid][kb * 8 + tig    ];
                uint32_t b1 = Vs2[stage][nb * 8 + gid][kb * 8 + tig + 4];
                mma_f16(o[nb], pa, b0, b1);
            }
        }

        if (more) storeKV(stage ^ 1);
        __syncthreads();
        stage ^= 1;
    }

    l_lo += __shfl_xor_sync(0xffffffffu, l_lo, 1);
    l_lo += __shfl_xor_sync(0xffffffffu, l_lo, 2);
    l_hi += __shfl_xor_sync(0xffffffffu, l_hi, 1);
    l_hi += __shfl_xor_sync(0xffffffffu, l_hi, 2);

    const int row0 = (((b * NH + h) * NSPLIT) + sp) * Sq + q0 + warp * 16;
#pragma unroll
    for (int nb = 0; nb < 4; nb++) {
        *(float2*)(Po + (size_t)(row0 + gid)     * HD + nb * 8 + 2 * tig) =
            make_float2(o[nb][0], o[nb][1]);
        *(float2*)(Po + (size_t)(row0 + gid + 8) * HD + nb * 8 + 2 * tig) =
            make_float2(o[nb][2], o[nb][3]);
    }
    if (tig == 0) {
        Pm[row0 + gid]     = m_lo;  Pl[row0 + gid]     = l_lo;
        Pm[row0 + gid + 8] = m_hi;  Pl[row0 + gid + 8] = l_hi;
    }
}

// ---------------------------------------------------------------------------
// Launch
// ---------------------------------------------------------------------------
extern "C" void kernel_launch(void* const* d_in, const int* in_sizes, int n_in,
                              void* d_out, int out_size)
{
    const float* query = (const float*)d_in[0];
    const float* keyv  = (const float*)d_in[1];
    const float* Wq    = (const float*)d_in[2];
    const float* bq    = (const float*)d_in[3];
    const float* Wk    = (const float*)d_in[4];
    const float* bk    = (const float*)d_in[5];
    const float* Wv    = (const float*)d_in[6];
    const float* bv    = (const float*)d_in[7];
    const float* Wo    = (const float*)d_in[8];
    const float* bo    = (const float*)d_in[9];
    float* out = (float*)d_out;

    float *dQ, *dPo, *dPm, *dPl;
    __half *dK, *dV;
    cudaGetSymbolAddress((void**)&dQ, g_Q);
    cudaGetSymbolAddress((void**)&dK, g_K);
    cudaGetSymbolAddress((void**)&dV, g_V);
    cudaGetSymbolAddress((void**)&dPo, g_Po);
    cudaGetSymbolAddress((void**)&dPm, g_Pm);
    cudaGetSymbolAddress((void**)&dPl, g_Pl);

    // fused Q + K + V projections: one launch
    {
        dim3 grid(HWk / 128, Dm / 128, Bsz * 2 + 1);
        gemm_proj_fused<<<grid, 256>>>(keyv, Wk, bk, Wv, bv, dK, dV,
                                       query, Wq, bq, dQ);
    }
    // attention (split-KV x4)
    {
        dim3 grid(Sq / 64, NH, Bsz * NSPLIT);
        attn_mma<<<grid, 128>>>(dQ, dK, dV, dPo, dPm, dPl);
    }
    // output projection with fused 4-way combine -> d_out
    {
        dim3 grid((Bsz * Sq) / 64, Dm / 64);
        gemm_out_f16<<<grid, 256>>>(dPo, dPm, dPl, Wo, bo, out);
    }
}

// round 11
// speedup vs baseline: 2.0807x; 1.0415x over previous
#include <cuda_runtime.h>
#include <cuda_fp16.h>
#include <cstdint>

// Problem dims (fixed)
#define Dm   256
#define Bsz  4
#define Sq   512
#define HWk  4096
#define NH   8
#define HD   32
#define NSPLIT 4

// Scratch (no cudaMalloc allowed)
__device__ float  g_Q[Bsz * Sq * Dm];
__device__ __half g_K[Bsz * HWk * Dm];
__device__ __half g_V[Bsz * HWk * Dm];
__device__ float  g_Po[Bsz * NH * NSPLIT * Sq * HD];
__device__ float  g_Pm[Bsz * NH * NSPLIT * Sq];
__device__ float  g_Pl[Bsz * NH * NSPLIT * Sq];

__device__ __forceinline__ uint32_t f2h2(float x, float y) {
    __half2 h = __floats2half2_rn(x, y);
    return *reinterpret_cast<uint32_t*>(&h);
}

__device__ __forceinline__ float ex2f(float x) {
    float r;
    asm("ex2.approx.f32 %0, %1;" : "=f"(r) : "f"(x));
    return r;
}

// mma.m16n8k16 f16 inputs, f32 accumulate
__device__ __forceinline__ void mma_f16(float c[4], const uint32_t a[4],
                                        uint32_t b0, uint32_t b1) {
    asm volatile(
        "mma.sync.aligned.m16n8k16.row.col.f32.f16.f16.f32 "
        "{%0,%1,%2,%3}, {%4,%5,%6,%7}, {%8,%9}, {%0,%1,%2,%3};"
        : "+f"(c[0]), "+f"(c[1]), "+f"(c[2]), "+f"(c[3])
        : "r"(a[0]), "r"(a[1]), "r"(a[2]), "r"(a[3]), "r"(b0), "r"(b1));
}

// ldmatrix x4: loads 4 8x8 b16 matrices; per-lane row addresses.
__device__ __forceinline__ void ldsm_x4(uint32_t r[4], uint32_t addr) {
    asm volatile(
        "ldmatrix.sync.aligned.m8n8.x4.shared.b16 {%0,%1,%2,%3}, [%4];"
        : "=r"(r[0]), "=r"(r[1]), "=r"(r[2]), "=r"(r[3]) : "r"(addr));
}

__device__ __forceinline__ uint32_t cvta_s(const void* p) {
    return (uint32_t)__cvta_generic_to_shared(p);
}

#define KS2 20    // [row][k2] tiles: 16 data words + 4 pad (ldmatrix rows conflict-free)
#define AST 136   // proj A tile [k2][m]: 8*tig+gid -> 32 distinct banks on a-frag reads
#define VS2 36    // attn V [d][key2] tile (rows 4n mod 32: conflict-free)

// ---------------------------------------------------------------------------
// FUSED projections: grid.z in [0,9).
//  z<8 : KV projection (b = z>>1, K/V = z&1), A is kv[b] (D x HW), half out.
//  z==8: Q projection, A row-major (B*S x D), fp32 out; only x<16 active.
// BM=128, BN=128, BK=32, 8 warps (4m x 2n), warp tile 32x64, double-buffered.
// W b-fragments via ldmatrix.x4.
// ---------------------------------------------------------------------------
__global__ __launch_bounds__(256, 2)
void gemm_proj_fused(const float* __restrict__ KVin,
                     const float* __restrict__ Wk, const float* __restrict__ bk,
                     const float* __restrict__ Wv, const float* __restrict__ bv,
                     __half* __restrict__ Kout, __half* __restrict__ Vout,
                     const float* __restrict__ Qin, const float* __restrict__ Wq,
                     const float* __restrict__ bq, float* __restrict__ Qout)
{
    const int z = blockIdx.z;
    const bool isq = (z == 8);
    if (isq && blockIdx.x >= (Bsz * Sq) / 128) return;

    const int b = z >> 1;
    const int isv = z & 1;
    const float* A;
    const float* W;
    const float* bias;
    if (isq) { A = Qin; W = Wq; bias = bq; }
    else {
        A    = KVin + (size_t)b * Dm * HWk;
        W    = isv ? Wv : Wk;
        bias = isv ? bv : bk;
    }

    __shared__ uint32_t As2[2][16][AST];   // [k2][m] (k2-major)
    __shared__ uint32_t Ws2[2][128][KS2];  // [n][k2]

    const int bm = blockIdx.x * 128;
    const int bn = blockIdx.y * 128;
    const int tid  = threadIdx.x;
    const int warp = tid >> 5;
    const int lane = tid & 31;
    const int gid  = lane >> 2;
    const int tig  = lane & 3;
    const int wm = (warp >> 1) * 32;
    const int wn = (warp & 1) * 64;

    // b-frag ldmatrix lane selectors (rows = n, chunks = k2 quads)
    const int brow = ((lane >> 4) & 1) * 8 + (lane & 7);
    const int bchk = ((lane >> 3) & 1) * 4;
    const uint32_t ws0 = cvta_s(&Ws2[0][0][0]) + ((wn + brow) * KS2 + bchk) * 4;

    float acc[2][8][4];
#pragma unroll
    for (int mf = 0; mf < 2; mf++)
#pragma unroll
        for (int nb = 0; nb < 8; nb++)
#pragma unroll
            for (int j = 0; j < 4; j++) acc[mf][nb][j] = 0.f;

    const int k2 = tid >> 4;          // KV A loader: k2-pair row 0..15
    const int mc = (tid & 15) * 8;    //              m chunk
    const int rr = tid >> 1;          // W / Q-A loader row
    const int kc = (tid & 1) * 16;    //              k float offset

    float4 rb[4], rw[4];

    auto loadT = [&](int k0) {
        if (isq) {
#pragma unroll
            for (int i = 0; i < 4; i++)
                rb[i] = *(const float4*)(A + (size_t)(bm + rr) * Dm + k0 + kc + 4 * i);
        } else {
            rb[0] = *(const float4*)(A + (size_t)(k0 + 2 * k2)     * HWk + bm + mc);
            rb[1] = *(const float4*)(A + (size_t)(k0 + 2 * k2)     * HWk + bm + mc + 4);
            rb[2] = *(const float4*)(A + (size_t)(k0 + 2 * k2 + 1) * HWk + bm + mc);
            rb[3] = *(const float4*)(A + (size_t)(k0 + 2 * k2 + 1) * HWk + bm + mc + 4);
        }
#pragma unroll
        for (int i = 0; i < 4; i++)
            rw[i] = *(const float4*)(W + (size_t)(bn + rr) * Dm + k0 + kc + 4 * i);
    };
    auto storeT = [&](int st) {
        if (isq) {
            const float* f = (const float*)&rb[0];
#pragma unroll
            for (int j = 0; j < 8; j++)
                As2[st][(tid & 1) * 8 + j][rr] = f2h2(f[2 * j], f[2 * j + 1]);
        } else {
            const float* lo = (const float*)&rb[0];   // k even
            const float* hi = (const float*)&rb[2];   // k odd
            uint4 u0, u1;
            u0.x = f2h2(lo[0], hi[0]); u0.y = f2h2(lo[1], hi[1]);
            u0.z = f2h2(lo[2], hi[2]); u0.w = f2h2(lo[3], hi[3]);
            u1.x = f2h2(lo[4], hi[4]); u1.y = f2h2(lo[5], hi[5]);
            u1.z = f2h2(lo[6], hi[6]); u1.w = f2h2(lo[7], hi[7]);
            *(uint4*)&As2[st][k2][mc]     = u0;
            *(uint4*)&As2[st][k2][mc + 4] = u1;
        }
        const float* w = (const float*)&rw[0];
        uint4 v0, v1;
        v0.x = f2h2(w[0],  w[1]);  v0.y = f2h2(w[2],  w[3]);
        v0.z = f2h2(w[4],  w[5]);  v0.w = f2h2(w[6],  w[7]);
        v1.x = f2h2(w[8],  w[9]);  v1.y = f2h2(w[10], w[11]);
        v1.z = f2h2(w[12], w[13]); v1.w = f2h2(w[14], w[15]);
        *(uint4*)&Ws2[st][rr][(tid & 1) * 8]     = v0;
        *(uint4*)&Ws2[st][rr][(tid & 1) * 8 + 4] = v1;
    };

    loadT(0);
    storeT(0);
    __syncthreads();

#pragma unroll
    for (int it = 0; it < 8; it++) {
        const int cur = it & 1;
        const bool more = (it + 1) < 8;
        if (more) loadT((it + 1) * 32);

        const uint32_t wsb = ws0 + cur * (128 * KS2 * 4);
#pragma unroll
        for (int kb = 0; kb < 2; kb++) {
            uint32_t a[2][4];
#pragma unroll
            for (int mf = 0; mf < 2; mf++) {
                const int m = wm + mf * 16 + gid;
                a[mf][0] = As2[cur][kb * 8 + tig    ][m    ];
                a[mf][1] = As2[cur][kb * 8 + tig    ][m + 8];
                a[mf][2] = As2[cur][kb * 8 + tig + 4][m    ];
                a[mf][3] = As2[cur][kb * 8 + tig + 4][m + 8];
            }
#pragma unroll
            for (int p = 0; p < 4; p++) {
                uint32_t bf[4];
                ldsm_x4(bf, wsb + (p * 16 * KS2 + kb * 8) * 4);
                mma_f16(acc[0][2 * p    ], a[0], bf[0], bf[1]);
                mma_f16(acc[1][2 * p    ], a[1], bf[0], bf[1]);
                mma_f16(acc[0][2 * p + 1], a[0], bf[2], bf[3]);
                mma_f16(acc[1][2 * p + 1], a[1], bf[2], bf[3]);
            }
        }

        if (more) storeT(cur ^ 1);
        __syncthreads();
    }

    if (isq) {
#pragma unroll
        for (int mf = 0; mf < 2; mf++) {
            const int row = bm + wm + mf * 16 + gid;
#pragma unroll
            for (int nb = 0; nb < 8; nb++) {
                const int col = bn + wn + nb * 8 + 2 * tig;
                const float b0 = bias[col], b1 = bias[col + 1];
                *(float2*)(Qout + (size_t)row * Dm + col) =
                    make_float2(acc[mf][nb][0] + b0, acc[mf][nb][1] + b1);
                *(float2*)(Qout + (size_t)(row + 8) * Dm + col) =
                    make_float2(acc[mf][nb][2] + b0, acc[mf][nb][3] + b1);
            }
        }
    } else {
        __half* C = (isv ? Vout : Kout) + (size_t)b * HWk * Dm;
#pragma unroll
        for (int mf = 0; mf < 2; mf++) {
            const int row = bm + wm + mf * 16 + gid;
#pragma unroll
            for (int nb = 0; nb < 8; nb++) {
                const int col = bn + wn + nb * 8 + 2 * tig;
                const float b0 = bias[col], b1 = bias[col + 1];
                *(uint32_t*)(C + (size_t)row * Dm + col) =
                    f2h2(acc[mf][nb][0] + b0, acc[mf][nb][1] + b1);
                *(uint32_t*)(C + (size_t)(row + 8) * Dm + col) =
                    f2h2(acc[mf][nb][2] + b0, acc[mf][nb][3] + b1);
            }
        }
    }
}

// ---------------------------------------------------------------------------
// O projection with FUSED 4-way split-KV combine, 256 threads, dbl-buffered.
// A and W fragments via ldmatrix.x4.
// ---------------------------------------------------------------------------
__global__ __launch_bounds__(256)
void gemm_out_f16(const float* __restrict__ Po, const float* __restrict__ Pm,
                  const float* __restrict__ Pl, const float* __restrict__ W,
                  const float* __restrict__ bias, float* __restrict__ C)
{
    __shared__ uint32_t As2[2][64][KS2];
    __shared__ uint32_t Ws2[2][64][KS2];

    const int bm = blockIdx.x * 64;
    const int bn = blockIdx.y * 64;
    const int tid  = threadIdx.x;
    const int warp = tid >> 5;
    const int lane = tid & 31;
    const int gid  = lane >> 2;
    const int tig  = lane & 3;
    const int wm = (warp >> 1) * 16;
    const int wn = (warp & 1) * 32;

    // ldmatrix lane selectors
    const int brow = ((lane >> 4) & 1) * 8 + (lane & 7);
    const int bchk = ((lane >> 3) & 1) * 4;
    const int arow = ((lane >> 3) & 1) * 8 + (lane & 7);
    const int achk = ((lane >> 4) & 1) * 4;
    const uint32_t as0 = cvta_s(&As2[0][0][0]) + ((wm + arow) * KS2 + achk) * 4;
    const uint32_t ws0 = cvta_s(&Ws2[0][0][0]) + ((wn + brow) * KS2 + bchk) * 4;

    float acc[4][4];
#pragma unroll
    for (int nb = 0; nb < 4; nb++)
#pragma unroll
        for (int j = 0; j < 4; j++) acc[nb][j] = 0.f;

    const int rr = tid >> 2;
    const int kq = (tid & 3) * 8;

    const int rowg = bm + rr;
    const int b = rowg >> 9;
    const int q = rowg & (Sq - 1);

    float4 ps[NSPLIT][2], vw[2];
    float wc[NSPLIT];

    auto loadT = [&](int k0) {
        const int h  = k0 >> 5;
        const int bh = b * NH + h;
        const size_t i0 = (size_t)(bh * NSPLIT) * Sq + q;
        float mv[NSPLIT], lv[NSPLIT];
        float m = -1e30f;
#pragma unroll
        for (int s = 0; s < NSPLIT; s++) {
            mv[s] = Pm[i0 + (size_t)s * Sq];
            lv[s] = Pl[i0 + (size_t)s * Sq];
            m = fmaxf(m, mv[s]);
        }
        float denom = 0.f;
#pragma unroll
        for (int s = 0; s < NSPLIT; s++) {
            wc[s] = ex2f(mv[s] - m);
            denom += lv[s] * wc[s];
        }
        const float inv = 1.f / denom;
#pragma unroll
        for (int s = 0; s < NSPLIT; s++) {
            wc[s] *= inv;
            ps[s][0] = *(const float4*)(Po + (i0 + (size_t)s * Sq) * HD + kq);
            ps[s][1] = *(const float4*)(Po + (i0 + (size_t)s * Sq) * HD + kq + 4);
        }
        vw[0] = *(const float4*)(W + (size_t)(bn + rr) * Dm + k0 + kq);
        vw[1] = *(const float4*)(W + (size_t)(bn + rr) * Dm + k0 + kq + 4);
    };
    auto storeT = [&](int st) {
        float av[8];
#pragma unroll
        for (int j = 0; j < 8; j++) {
            float acc_j = 0.f;
#pragma unroll
            for (int s = 0; s < NSPLIT; s++)
                acc_j += ((const float*)&ps[s][0])[j] * wc[s];
            av[j] = acc_j;
        }
        const float* fw = (const float*)&vw[0];
        uint4 ua, uw;
        ua.x = f2h2(av[0], av[1]); ua.y = f2h2(av[2], av[3]);
        ua.z = f2h2(av[4], av[5]); ua.w = f2h2(av[6], av[7]);
        uw.x = f2h2(fw[0], fw[1]); uw.y = f2h2(fw[2], fw[3]);
        uw.z = f2h2(fw[4], fw[5]); uw.w = f2h2(fw[6], fw[7]);
        *(uint4*)&As2[st][rr][(tid & 3) * 4] = ua;
        *(uint4*)&Ws2[st][rr][(tid & 3) * 4] = uw;
    };

    loadT(0);
    storeT(0);
    __syncthreads();

#pragma unroll
    for (int it = 0; it < 8; it++) {
        const int cur = it & 1;
        const bool more = (it + 1) < 8;
        if (more) loadT((it + 1) * 32);

        const uint32_t asb = as0 + cur * (64 * KS2 * 4);
        const uint32_t wsb = ws0 + cur * (64 * KS2 * 4);
#pragma unroll
        for (int kb = 0; kb < 2; kb++) {
            uint32_t a[4];
            ldsm_x4(a, asb + kb * 8 * 4);
#pragma unroll
            for (int p = 0; p < 2; p++) {
                uint32_t bf[4];
                ldsm_x4(bf, wsb + (p * 16 * KS2 + kb * 8) * 4);
                mma_f16(acc[2 * p    ], a, bf[0], bf[1]);
                mma_f16(acc[2 * p + 1], a, bf[2], bf[3]);
            }
        }

        if (more) storeT(cur ^ 1);
        __syncthreads();
    }

    const int row = bm + wm + gid;
#pragma unroll
    for (int nb = 0; nb < 4; nb++) {
        const int col = bn + wn + nb * 8 + 2 * tig;
        const float b0 = bias[col], b1 = bias[col + 1];
        *(float2*)(C + (size_t)row * Dm + col) =
            make_float2(acc[nb][0] + b0, acc[nb][1] + b1);
        *(float2*)(C + (size_t)(row + 8) * Dm + col) =
            make_float2(acc[nb][2] + b0, acc[nb][3] + b1);
    }
}

// ---------------------------------------------------------------------------
// fp16 flash attention, split-KV x4, double-buffered, half K/V in gmem.
// exp2-domain softmax. K and V b-fragments via ldmatrix.x4.
// ---------------------------------------------------------------------------
__global__ __launch_bounds__(128)
void attn_mma(const float* __restrict__ Q, const __half* __restrict__ K,
              const __half* __restrict__ V, float* __restrict__ Po,
              float* __restrict__ Pm, float* __restrict__ Pl)
{
    const int h  = blockIdx.y;
    const int bz = blockIdx.z;
    const int b  = bz >> 2;
    const int sp = bz & 3;
    const int q0 = blockIdx.x * 64;

    __shared__ uint32_t Ks2[2][64][KS2];   // [key][d2]
    __shared__ uint32_t Vs2[2][32][VS2];   // [d][key2]

    const int tid  = threadIdx.x;
    const int warp = tid >> 5;
    const int lane = tid & 31;
    const int gid  = lane >> 2;
    const int tig  = lane & 3;

    const int brow = ((lane >> 4) & 1) * 8 + (lane & 7);
    const int bchk = ((lane >> 3) & 1) * 4;
    const uint32_t ks0 = cvta_s(&Ks2[0][0][0]) + (brow * KS2 + bchk) * 4;
    const uint32_t vs0 = cvta_s(&Vs2[0][0][0]) + (brow * VS2 + bchk) * 4;

    const float scale = 0.17677669529663687f * 1.4426950408889634f;

    uint32_t qa[2][4];
    {
        const float* Qb = Q + ((size_t)(b * Sq + q0 + warp * 16)) * Dm + h * HD;
#pragma unroll
        for (int kb = 0; kb < 2; kb++) {
            const int d0 = kb * 16 + 2 * tig;
            qa[kb][0] = f2h2(Qb[(size_t)gid       * Dm + d0    ] * scale,
                             Qb[(size_t)gid       * Dm + d0 + 1] * scale);
            qa[kb][1] = f2h2(Qb[(size_t)(gid + 8) * Dm + d0    ] * scale,
                             Qb[(size_t)(gid + 8) * Dm + d0 + 1] * scale);
            qa[kb][2] = f2h2(Qb[(size_t)gid       * Dm + d0 + 8] * scale,
                             Qb[(size_t)gid       * Dm + d0 + 9] * scale);
            qa[kb][3] = f2h2(Qb[(size_t)(gid + 8) * Dm + d0 + 8] * scale,
                             Qb[(size_t)(gid + 8) * Dm + d0 + 9] * scale);
        }
    }

    float m_lo = -1e30f, m_hi = -1e30f;
    float l_lo = 0.f,    l_hi = 0.f;
    float o[4][4];
#pragma unroll
    for (int nb = 0; nb < 4; nb++)
#pragma unroll
        for (int i = 0; i < 4; i++) o[nb][i] = 0.f;

    const __half* Kb = K + (size_t)b * HWk * Dm + h * HD;
    const __half* Vb = V + (size_t)b * HWk * Dm + h * HD;

    const int krow = tid >> 1;
    const int kdc  = (tid & 1) * 16;
    const int vk2 = tid >> 2;
    const int vdc = (tid & 3) * 8;

    const int jbeg = sp * (HWk / NSPLIT);
    const int jend = jbeg + (HWk / NSPLIT);

    uint4 rk[2], rv[2];
    auto loadKV = [&](int j0) {
        rk[0] = *(const uint4*)(Kb + (size_t)(j0 + krow) * Dm + kdc);
        rk[1] = *(const uint4*)(Kb + (size_t)(j0 + krow) * Dm + kdc + 8);
        rv[0] = *(const uint4*)(Vb + (size_t)(j0 + 2 * vk2)     * Dm + vdc);
        rv[1] = *(const uint4*)(Vb + (size_t)(j0 + 2 * vk2 + 1) * Dm + vdc);
    };
    auto storeKV = [&](int st) {
        *(uint4*)&Ks2[st][krow][(tid & 1) * 8]     = rk[0];
        *(uint4*)&Ks2[st][krow][(tid & 1) * 8 + 4] = rk[1];
        const __half* h0 = (const __half*)&rv[0];
        const __half* h1 = (const __half*)&rv[1];
#pragma unroll
        for (int j = 0; j < 8; j++) {
            __half2 p = __halves2half2(h0[j], h1[j]);
            Vs2[st][vdc + j][vk2] = *(uint32_t*)&p;
        }
    };

    loadKV(jbeg);
    storeKV(0);
    __syncthreads();

    int stage = 0;
    for (int j0 = jbeg; j0 < jend; j0 += 64) {
        const bool more = (j0 + 64) < jend;
        if (more) loadKV(j0 + 64);

        // ---- S = Q K^T (log2 domain), K b-frags via ldmatrix ----
        float s[8][4];
#pragma unroll
        for (int nb = 0; nb < 8; nb++)
#pragma unroll
            for (int i = 0; i < 4; i++) s[nb][i] = 0.f;

        const uint32_t ksb = ks0 + stage * (64 * KS2 * 4);
#pragma unroll
        for (int kb = 0; kb < 2; kb++) {
#pragma unroll
            for (int p = 0; p < 4; p++) {
                uint32_t bf[4];
                ldsm_x4(bf, ksb + (p * 16 * KS2 + kb * 8) * 4);
                mma_f16(s[2 * p    ], qa[kb], bf[0], bf[1]);
                mma_f16(s[2 * p + 1], qa[kb], bf[2], bf[3]);
            }
        }

        // ---- online softmax (exp2) ----
        float tmax_lo = -1e30f, tmax_hi = -1e30f;
#pragma unroll
        for (int nb = 0; nb < 8; nb++) {
            tmax_lo = fmaxf(tmax_lo, fmaxf(s[nb][0], s[nb][1]));
            tmax_hi = fmaxf(tmax_hi, fmaxf(s[nb][2], s[nb][3]));
        }
        tmax_lo = fmaxf(tmax_lo, __shfl_xor_sync(0xffffffffu, tmax_lo, 1));
        tmax_lo = fmaxf(tmax_lo, __shfl_xor_sync(0xffffffffu, tmax_lo, 2));
        tmax_hi = fmaxf(tmax_hi, __shfl_xor_sync(0xffffffffu, tmax_hi, 1));
        tmax_hi = fmaxf(tmax_hi, __shfl_xor_sync(0xffffffffu, tmax_hi, 2));

        const float mn_lo = fmaxf(m_lo, tmax_lo);
        const float mn_hi = fmaxf(m_hi, tmax_hi);
        const float al_lo = ex2f(m_lo - mn_lo);
        const float al_hi = ex2f(m_hi - mn_hi);
        m_lo = mn_lo; m_hi = mn_hi;
        l_lo *= al_lo; l_hi *= al_hi;
#pragma unroll
        for (int nb = 0; nb < 4; nb++) {
            o[nb][0] *= al_lo; o[nb][1] *= al_lo;
            o[nb][2] *= al_hi; o[nb][3] *= al_hi;
        }

        // ---- exp2 + O += P V, V b-frags via ldmatrix ----
        const uint32_t vsb = vs0 + stage * (32 * VS2 * 4);
#pragma unroll
        for (int kb = 0; kb < 4; kb++) {
            const float p0 = ex2f(s[2 * kb    ][0] - mn_lo);
            const float p1 = ex2f(s[2 * kb    ][1] - mn_lo);
            const float p2 = ex2f(s[2 * kb    ][2] - mn_hi);
            const float p3 = ex2f(s[2 * kb    ][3] - mn_hi);
            const float r0 = ex2f(s[2 * kb + 1][0] - mn_lo);
            const float r1 = ex2f(s[2 * kb + 1][1] - mn_lo);
            const float r2 = ex2f(s[2 * kb + 1][2] - mn_hi);
            const float r3 = ex2f(s[2 * kb + 1][3] - mn_hi);
            l_lo += p0 + p1 + r0 + r1;
            l_hi += p2 + p3 + r2 + r3;
            uint32_t pa[4];
            pa[0] = f2h2(p0, p1);
            pa[1] = f2h2(p2, p3);
            pa[2] = f2h2(r0, r1);
            pa[3] = f2h2(r2, r3);
#pragma unroll
            for (int p = 0; p < 2; p++) {
                uint32_t bf[4];
                ldsm_x4(bf, vsb + (p * 16 * VS2 + kb * 8) * 4);
                mma_f16(o[2 * p    ], pa, bf[0], bf[1]);
                mma_f16(o[2 * p + 1], pa, bf[2], bf[3]);
            }
        }

        if (more) storeKV(stage ^ 1);
        __syncthreads();
        stage ^= 1;
    }

    l_lo += __shfl_xor_sync(0xffffffffu, l_lo, 1);
    l_lo += __shfl_xor_sync(0xffffffffu, l_lo, 2);
    l_hi += __shfl_xor_sync(0xffffffffu, l_hi, 1);
    l_hi += __shfl_xor_sync(0xffffffffu, l_hi, 2);

    const int row0 = (((b * NH + h) * NSPLIT) + sp) * Sq + q0 + warp * 16;
#pragma unroll
    for (int nb = 0; nb < 4; nb++) {
        *(float2*)(Po + (size_t)(row0 + gid)     * HD + nb * 8 + 2 * tig) =
            make_float2(o[nb][0], o[nb][1]);
        *(float2*)(Po + (size_t)(row0 + gid + 8) * HD + nb * 8 + 2 * tig) =
            make_float2(o[nb][2], o[nb][3]);
    }
    if (tig == 0) {
        Pm[row0 + gid]     = m_lo;  Pl[row0 + gid]     = l_lo;
        Pm[row0 + gid + 8] = m_hi;  Pl[row0 + gid + 8] = l_hi;
    }
}

// ---------------------------------------------------------------------------
// Launch
// ---------------------------------------------------------------------------
extern "C" void kernel_launch(void* const* d_in, const int* in_sizes, int n_in,
                              void* d_out, int out_size)
{
    const float* query = (const float*)d_in[0];
    const float* keyv  = (const float*)d_in[1];
    const float* Wq    = (const float*)d_in[2];
    const float* bq    = (const float*)d_in[3];
    const float* Wk    = (const float*)d_in[4];
    const float* bk    = (const float*)d_in[5];
    const float* Wv    = (const float*)d_in[6];
    const float* bv    = (const float*)d_in[7];
    const float* Wo    = (const float*)d_in[8];
    const float* bo    = (const float*)d_in[9];
    float* out = (float*)d_out;

    float *dQ, *dPo, *dPm, *dPl;
    __half *dK, *dV;
    cudaGetSymbolAddress((void**)&dQ, g_Q);
    cudaGetSymbolAddress((void**)&dK, g_K);
    cudaGetSymbolAddress((void**)&dV, g_V);
    cudaGetSymbolAddress((void**)&dPo, g_Po);
    cudaGetSymbolAddress((void**)&dPm, g_Pm);
    cudaGetSymbolAddress((void**)&dPl, g_Pl);

    // fused Q + K + V projections: one launch
    {
        dim3 grid(HWk / 128, Dm / 128, Bsz * 2 + 1);
        gemm_proj_fused<<<grid, 256>>>(keyv, Wk, bk, Wv, bv, dK, dV,
                                       query, Wq, bq, dQ);
    }
    // attention (split-KV x4)
    {
        dim3 grid(Sq / 64, NH, Bsz * NSPLIT);
        attn_mma<<<grid, 128>>>(dQ, dK, dV, dPo, dPm, dPl);
    }
    // output projection with fused 4-way combine -> d_out
    {
        dim3 grid((Bsz * Sq) / 64, Dm / 64);
        gemm_out_f16<<<grid, 256>>>(dPo, dPm, dPl, Wo, bo, out);
    }
}

// round 12
// speedup vs baseline: 2.5579x; 1.2294x over previous
#include <cuda_runtime.h>
#include <cuda_fp16.h>
#include <cstdint>

// Problem dims (fixed)
#define Dm   256
#define Bsz  4
#define Sq   512
#define HWk  4096
#define NH   8
#define HD   32
#define NSPLIT 4

// Scratch (no cudaMalloc allowed)
__device__ __half g_KVh[Bsz * Dm * HWk];          // kv converted to half [b][k][m]
__device__ __half g_Qih[Bsz * Sq * Dm];           // query half
__device__ __half g_Wh[4 * Dm * Dm];              // Wq,Wk,Wv,Wo half
__device__ __half g_Qh[Bsz * Sq * Dm];            // projected Q (half, pre-scaled)
__device__ __half g_K [Bsz * HWk * Dm];           // projected K [b][hw][d]
__device__ __half g_Vt[Bsz * Dm * HWk];           // projected V transposed [b][d][hw]
__device__ float  g_Po[Bsz * NH * NSPLIT * Sq * HD];
__device__ float  g_Pm[Bsz * NH * NSPLIT * Sq];
__device__ float  g_Pl[Bsz * NH * NSPLIT * Sq];

__device__ __forceinline__ uint32_t f2h2(float x, float y) {
    __half2 h = __floats2half2_rn(x, y);
    return *reinterpret_cast<uint32_t*>(&h);
}
__device__ __forceinline__ float ex2f(float x) {
    float r;
    asm("ex2.approx.f32 %0, %1;" : "=f"(r) : "f"(x));
    return r;
}
__device__ __forceinline__ void mma_f16(float c[4], const uint32_t a[4],
                                        uint32_t b0, uint32_t b1) {
    asm volatile(
        "mma.sync.aligned.m16n8k16.row.col.f32.f16.f16.f32 "
        "{%0,%1,%2,%3}, {%4,%5,%6,%7}, {%8,%9}, {%0,%1,%2,%3};"
        : "+f"(c[0]), "+f"(c[1]), "+f"(c[2]), "+f"(c[3])
        : "r"(a[0]), "r"(a[1]), "r"(a[2]), "r"(a[3]), "r"(b0), "r"(b1));
}
__device__ __forceinline__ void ldsm_x4(uint32_t r[4], uint32_t addr) {
    asm volatile(
        "ldmatrix.sync.aligned.m8n8.x4.shared.b16 {%0,%1,%2,%3}, [%4];"
        : "=r"(r[0]), "=r"(r[1]), "=r"(r[2]), "=r"(r[3]) : "r"(addr));
}
__device__ __forceinline__ void ldsm_x4_t(uint32_t r[4], uint32_t addr) {
    asm volatile(
        "ldmatrix.sync.aligned.m8n8.x4.trans.shared.b16 {%0,%1,%2,%3}, [%4];"
        : "=r"(r[0]), "=r"(r[1]), "=r"(r[2]), "=r"(r[3]) : "r"(addr));
}
__device__ __forceinline__ uint32_t cvta_s(const void* p) {
    return (uint32_t)__cvta_generic_to_shared(p);
}
__device__ __forceinline__ void cp16(uint32_t dst, const void* src) {
    asm volatile("cp.async.cg.shared.global [%0], [%1], 16;"
                 :: "r"(dst), "l"(src));
}
__device__ __forceinline__ void cp_commit() {
    asm volatile("cp.async.commit_group;");
}
__device__ __forceinline__ void cp_wait0() {
    asm volatile("cp.async.wait_group 0;");
}

#define KS2 20    // [row][k2] half2 tiles: rows conflict-free for ldmatrix
#define ATW 68    // proj KV A tile [k][m] half: 64 words + 4 pad (4k mod 32 distinct)
#define AQW 20    // proj Q A tile [m][k2]
#define VS2 36    // attn V [d][key] tile

// ---------------------------------------------------------------------------
// prep: fp32 -> fp16 conversions (kv, query, 4 weight matrices)
// ---------------------------------------------------------------------------
__global__ void prep_half(const float* __restrict__ kv,
                          const float* __restrict__ query,
                          const float* __restrict__ Wq, const float* __restrict__ Wk,
                          const float* __restrict__ Wv, const float* __restrict__ Wo)
{
    const int idx = blockIdx.x * blockDim.x + threadIdx.x;
    const int stride = gridDim.x * blockDim.x;

    const int N1 = Bsz * Dm * HWk / 4;
    uint2* kvh = (uint2*)g_KVh;
    for (int i = idx; i < N1; i += stride) {
        float4 v = ((const float4*)kv)[i];
        kvh[i] = make_uint2(f2h2(v.x, v.y), f2h2(v.z, v.w));
    }
    const int N2 = Bsz * Sq * Dm / 4;
    uint2* qh = (uint2*)g_Qih;
    for (int i = idx; i < N2; i += stride) {
        float4 v = ((const float4*)query)[i];
        qh[i] = make_uint2(f2h2(v.x, v.y), f2h2(v.z, v.w));
    }
    const int N3 = Dm * Dm / 4;
    const float* Ws[4] = {Wq, Wk, Wv, Wo};
    for (int w = 0; w < 4; w++) {
        uint2* wh = (uint2*)(g_Wh + w * Dm * Dm);
        for (int i = idx; i < N3; i += stride) {
            float4 v = ((const float4*)Ws[w])[i];
            wh[i] = make_uint2(f2h2(v.x, v.y), f2h2(v.z, v.w));
        }
    }
}

// ---------------------------------------------------------------------------
// FUSED projections, all-cp.async mainloop. grid.z in [0,9).
//  z<8 : KV projection (b=z>>1, K/V=z&1): A = kv_h[b] (D x HW), trans a-frags.
//        K out [hw][d] half; V out TRANSPOSED [d][hw] half.
//  z==8: Q projection from query_h (row-major), out half pre-scaled.
// BM=128, BN=128, BK=32, 8 warps (4m x 2n).
// ---------------------------------------------------------------------------
__global__ __launch_bounds__(256, 2)
void gemm_proj_fused(const __half* __restrict__ KVh, const __half* __restrict__ Qih,
                     const __half* __restrict__ Wh,
                     const float* __restrict__ bq, const float* __restrict__ bk,
                     const float* __restrict__ bv,
                     __half* __restrict__ Kout, __half* __restrict__ Vt,
                     __half* __restrict__ Qout)
{
    const int z = blockIdx.z;
    const bool isq = (z == 8);
    if (isq && blockIdx.x >= (Bsz * Sq) / 128) return;

    const int b = z >> 1;
    const int isv = z & 1;
    const __half* A;
    const __half* Wm;
    const float* bias;
    if (isq) { A = Qih; Wm = Wh; bias = bq; }
    else {
        A    = KVh + (size_t)b * Dm * HWk;
        Wm   = Wh + (size_t)(isv ? 2 : 1) * Dm * Dm;
        bias = isv ? bv : bk;
    }

    __shared__ uint32_t As2[2][2560];       // KV: [k][ATW] (32*68); Q: [m][AQW] (128*20)
    __shared__ uint32_t Ws2[2][128 * KS2];  // [n][k2]

    const int bm = blockIdx.x * 128;
    const int bn = blockIdx.y * 128;
    const int tid  = threadIdx.x;
    const int warp = tid >> 5;
    const int lane = tid & 31;
    const int gid  = lane >> 2;
    const int tig  = lane & 3;
    const int wm = (warp >> 1) * 32;
    const int wn = (warp & 1) * 64;

    const uint32_t asb = cvta_s(&As2[0][0]);
    const uint32_t wsb = cvta_s(&Ws2[0][0]);

    // b-frag selectors (rows n, chunk k)
    const int brow = ((lane >> 4) & 1) * 8 + (lane & 7);
    const int bchk = ((lane >> 3) & 1) * 4;
    const uint32_t ws0 = wsb + ((wn + brow) * KS2 + bchk) * 4;
    // KV trans a-frag selectors (rows k, chunk m)
    const int at_row = (lane & 7) + ((lane >> 4) & 1) * 8;
    const int at_mo  = ((lane >> 3) & 1) * 16;
    // Q non-trans a-frag selectors (rows m, chunk k)
    const int aq_row = (lane & 7) + ((lane >> 3) & 1) * 8;
    const int aq_co  = ((lane >> 4) & 1) * 16;

    float acc[2][8][4];
#pragma unroll
    for (int mf = 0; mf < 2; mf++)
#pragma unroll
        for (int nb = 0; nb < 8; nb++)
#pragma unroll
            for (int j = 0; j < 4; j++) acc[mf][nb][j] = 0.f;

    auto issueT = [&](int st, int k0) {
        const uint32_t stA = asb + st * 2560 * 4;
        const uint32_t stW = wsb + st * (128 * KS2 * 4);
        if (isq) {
            const uint32_t d = stA + (tid >> 1) * (AQW * 4) + (tid & 1) * 32;
            const __half* s = A + (size_t)(bm + (tid >> 1)) * Dm + k0 + (tid & 1) * 16;
            cp16(d, s); cp16(d + 16, s + 8);
        } else {
            const uint32_t d = stA + (tid >> 3) * (ATW * 4) + (tid & 7) * 32;
            const __half* s = A + (size_t)(k0 + (tid >> 3)) * HWk + bm + (tid & 7) * 16;
            cp16(d, s); cp16(d + 16, s + 8);
        }
        const uint32_t dw = stW + (tid >> 1) * (KS2 * 4) + (tid & 1) * 32;
        const __half* sw = Wm + (size_t)(bn + (tid >> 1)) * Dm + k0 + (tid & 1) * 16;
        cp16(dw, sw); cp16(dw + 16, sw + 8);
    };

    issueT(0, 0);
    cp_commit();
    cp_wait0();
    __syncthreads();

#pragma unroll
    for (int it = 0; it < 8; it++) {
        const int cur = it & 1;
        const bool more = (it + 1) < 8;
        if (more) { issueT(cur ^ 1, (it + 1) * 32); cp_commit(); }

        const uint32_t asc = asb + cur * 2560 * 4;
        const uint32_t wsc = ws0 + cur * (128 * KS2 * 4);
#pragma unroll
        for (int kb = 0; kb < 2; kb++) {
            uint32_t a[2][4];
            if (isq) {
#pragma unroll
                for (int mf = 0; mf < 2; mf++)
                    ldsm_x4(a[mf], asc + (wm + mf * 16 + aq_row) * (AQW * 4)
                                       + kb * 32 + aq_co);
            } else {
#pragma unroll
                for (int mf = 0; mf < 2; mf++)
                    ldsm_x4_t(a[mf], asc + (kb * 16 + at_row) * (ATW * 4)
                                         + (wm + mf * 16) * 2 + at_mo);
            }
#pragma unroll
            for (int p = 0; p < 4; p++) {
                uint32_t bf[4];
                ldsm_x4(bf, wsc + (p * 16 * KS2 + kb * 8) * 4);
                mma_f16(acc[0][2 * p    ], a[0], bf[0], bf[1]);
                mma_f16(acc[1][2 * p    ], a[1], bf[0], bf[1]);
                mma_f16(acc[0][2 * p + 1], a[0], bf[2], bf[3]);
                mma_f16(acc[1][2 * p + 1], a[1], bf[2], bf[3]);
            }
        }

        cp_wait0();
        __syncthreads();
    }

    if (isq) {
        const float scl = 0.17677669529663687f * 1.4426950408889634f;
#pragma unroll
        for (int mf = 0; mf < 2; mf++) {
            const int row = bm + wm + mf * 16 + gid;
#pragma unroll
            for (int nb = 0; nb < 8; nb++) {
                const int col = bn + wn + nb * 8 + 2 * tig;
                const float b0 = bias[col], b1 = bias[col + 1];
                *(uint32_t*)(Qout + (size_t)row * Dm + col) =
                    f2h2((acc[mf][nb][0] + b0) * scl, (acc[mf][nb][1] + b1) * scl);
                *(uint32_t*)(Qout + (size_t)(row + 8) * Dm + col) =
                    f2h2((acc[mf][nb][2] + b0) * scl, (acc[mf][nb][3] + b1) * scl);
            }
        }
    } else if (!isv) {
        __half* C = Kout + (size_t)b * HWk * Dm;
#pragma unroll
        for (int mf = 0; mf < 2; mf++) {
            const int row = bm + wm + mf * 16 + gid;
#pragma unroll
            for (int nb = 0; nb < 8; nb++) {
                const int col = bn + wn + nb * 8 + 2 * tig;
                const float b0 = bias[col], b1 = bias[col + 1];
                *(uint32_t*)(C + (size_t)row * Dm + col) =
                    f2h2(acc[mf][nb][0] + b0, acc[mf][nb][1] + b1);
                *(uint32_t*)(C + (size_t)(row + 8) * Dm + col) =
                    f2h2(acc[mf][nb][2] + b0, acc[mf][nb][3] + b1);
            }
        }
    } else {
        // V: write TRANSPOSED [d][hw]
        __half* C = Vt + (size_t)b * Dm * HWk;
#pragma unroll
        for (int mf = 0; mf < 2; mf++) {
            const int row = bm + wm + mf * 16 + gid;   // hw
#pragma unroll
            for (int nb = 0; nb < 8; nb++) {
                const int col = bn + wn + nb * 8 + 2 * tig;  // d
                const float b0 = bias[col], b1 = bias[col + 1];
                C[(size_t)col       * HWk + row]     = __float2half_rn(acc[mf][nb][0] + b0);
                C[(size_t)(col + 1) * HWk + row]     = __float2half_rn(acc[mf][nb][1] + b1);
                C[(size_t)col       * HWk + row + 8] = __float2half_rn(acc[mf][nb][2] + b0);
                C[(size_t)(col + 1) * HWk + row + 8] = __float2half_rn(acc[mf][nb][3] + b1);
            }
        }
    }
}

// ---------------------------------------------------------------------------
// O projection with FUSED 4-way split-KV combine; W via cp.async (half).
// ---------------------------------------------------------------------------
__global__ __launch_bounds__(256)
void gemm_out_f16(const float* __restrict__ Po, const float* __restrict__ Pm,
                  const float* __restrict__ Pl, const __half* __restrict__ Woh,
                  const float* __restrict__ bias, float* __restrict__ C)
{
    __shared__ uint32_t As2[2][64][KS2];
    __shared__ uint32_t Ws2[2][64][KS2];

    const int bm = blockIdx.x * 64;
    const int bn = blockIdx.y * 64;
    const int tid  = threadIdx.x;
    const int warp = tid >> 5;
    const int lane = tid & 31;
    const int gid  = lane >> 2;
    const int tig  = lane & 3;
    const int wm = (warp >> 1) * 16;
    const int wn = (warp & 1) * 32;

    const int brow = ((lane >> 4) & 1) * 8 + (lane & 7);
    const int bchk = ((lane >> 3) & 1) * 4;
    const int arow = ((lane >> 3) & 1) * 8 + (lane & 7);
    const int achk = ((lane >> 4) & 1) * 4;
    const uint32_t as0 = cvta_s(&As2[0][0][0]) + ((wm + arow) * KS2 + achk) * 4;
    const uint32_t wsb = cvta_s(&Ws2[0][0][0]);
    const uint32_t ws0 = wsb + ((wn + brow) * KS2 + bchk) * 4;

    float acc[4][4];
#pragma unroll
    for (int nb = 0; nb < 4; nb++)
#pragma unroll
        for (int j = 0; j < 4; j++) acc[nb][j] = 0.f;

    const int rr = tid >> 2;
    const int kq = (tid & 3) * 8;

    const int rowg = bm + rr;
    const int b = rowg >> 9;
    const int q = rowg & (Sq - 1);

    float4 ps[NSPLIT][2];
    float wc[NSPLIT];

    auto cpW = [&](int st, int k0) {
        const uint32_t d = wsb + st * (64 * KS2 * 4) + (tid >> 2) * (KS2 * 4) + (tid & 3) * 16;
        const __half* s = Woh + (size_t)(bn + (tid >> 2)) * Dm + k0 + (tid & 3) * 8;
        cp16(d, s);
    };
    auto loadA = [&](int k0) {
        const int h  = k0 >> 5;
        const int bh = b * NH + h;
        const size_t i0 = (size_t)(bh * NSPLIT) * Sq + q;
        float mv[NSPLIT], lv[NSPLIT];
        float m = -1e30f;
#pragma unroll
        for (int s = 0; s < NSPLIT; s++) {
            mv[s] = Pm[i0 + (size_t)s * Sq];
            lv[s] = Pl[i0 + (size_t)s * Sq];
            m = fmaxf(m, mv[s]);
        }
        float denom = 0.f;
#pragma unroll
        for (int s = 0; s < NSPLIT; s++) {
            wc[s] = ex2f(mv[s] - m);
            denom += lv[s] * wc[s];
        }
        const float inv = 1.f / denom;
#pragma unroll
        for (int s = 0; s < NSPLIT; s++) {
            wc[s] *= inv;
            ps[s][0] = *(const float4*)(Po + (i0 + (size_t)s * Sq) * HD + kq);
            ps[s][1] = *(const float4*)(Po + (i0 + (size_t)s * Sq) * HD + kq + 4);
        }
    };
    auto stsA = [&](int st) {
        float av[8];
#pragma unroll
        for (int j = 0; j < 8; j++) {
            float a = 0.f;
#pragma unroll
            for (int s = 0; s < NSPLIT; s++)
                a += ((const float*)&ps[s][0])[j] * wc[s];
            av[j] = a;
        }
        uint4 ua;
        ua.x = f2h2(av[0], av[1]); ua.y = f2h2(av[2], av[3]);
        ua.z = f2h2(av[4], av[5]); ua.w = f2h2(av[6], av[7]);
        *(uint4*)&As2[st][rr][(tid & 3) * 4] = ua;
    };

    cpW(0, 0);
    cp_commit();
    loadA(0);
    stsA(0);
    cp_wait0();
    __syncthreads();

#pragma unroll
    for (int it = 0; it < 8; it++) {
        const int cur = it & 1;
        const bool more = (it + 1) < 8;
        if (more) { cpW(cur ^ 1, (it + 1) * 32); cp_commit(); loadA((it + 1) * 32); }

        const uint32_t asc = as0 + cur * (64 * KS2 * 4);
        const uint32_t wsc = ws0 + cur * (64 * KS2 * 4);
#pragma unroll
        for (int kb = 0; kb < 2; kb++) {
            uint32_t a[4];
            ldsm_x4(a, asc + kb * 8 * 4);
#pragma unroll
            for (int p = 0; p < 2; p++) {
                uint32_t bf[4];
                ldsm_x4(bf, wsc + (p * 16 * KS2 + kb * 8) * 4);
                mma_f16(acc[2 * p    ], a, bf[0], bf[1]);
                mma_f16(acc[2 * p + 1], a, bf[2], bf[3]);
            }
        }

        if (more) stsA(cur ^ 1);
        cp_wait0();
        __syncthreads();
    }

    const int row = bm + wm + gid;
#pragma unroll
    for (int nb = 0; nb < 4; nb++) {
        const int col = bn + wn + nb * 8 + 2 * tig;
        const float b0 = bias[col], b1 = bias[col + 1];
        *(float2*)(C + (size_t)row * Dm + col) =
            make_float2(acc[nb][0] + b0, acc[nb][1] + b1);
        *(float2*)(C + (size_t)(row + 8) * Dm + col) =
            make_float2(acc[nb][2] + b0, acc[nb][3] + b1);
    }
}

// ---------------------------------------------------------------------------
// fp16 flash attention, split-KV x4; K and Vt tiles via pure cp.async copies.
// ---------------------------------------------------------------------------
__global__ __launch_bounds__(128)
void attn_mma(const __half* __restrict__ Qh, const __half* __restrict__ K,
              const __half* __restrict__ Vt, float* __restrict__ Po,
              float* __restrict__ Pm, float* __restrict__ Pl)
{
    const int h  = blockIdx.y;
    const int bz = blockIdx.z;
    const int b  = bz >> 2;
    const int sp = bz & 3;
    const int q0 = blockIdx.x * 64;

    __shared__ uint32_t Ks2[2][64][KS2];   // [key][d2]
    __shared__ uint32_t Vs2[2][32][VS2];   // [d][key2]

    const int tid  = threadIdx.x;
    const int warp = tid >> 5;
    const int lane = tid & 31;
    const int gid  = lane >> 2;
    const int tig  = lane & 3;

    const int brow = ((lane >> 4) & 1) * 8 + (lane & 7);
    const int bchk = ((lane >> 3) & 1) * 4;
    const uint32_t ksbase = cvta_s(&Ks2[0][0][0]);
    const uint32_t vsbase = cvta_s(&Vs2[0][0][0]);
    const uint32_t ks0 = ksbase + (brow * KS2 + bchk) * 4;
    const uint32_t vs0 = vsbase + (brow * VS2 + bchk) * 4;

    // Q a-fragments (half, pre-scaled by proj)
    uint32_t qa[2][4];
    {
        const __half* Qb = Qh + ((size_t)(b * Sq + q0 + warp * 16)) * Dm + h * HD;
#pragma unroll
        for (int kb = 0; kb < 2; kb++) {
            const int d0 = kb * 16 + 2 * tig;
            qa[kb][0] = *(const uint32_t*)(Qb + (size_t)gid       * Dm + d0);
            qa[kb][1] = *(const uint32_t*)(Qb + (size_t)(gid + 8) * Dm + d0);
            qa[kb][2] = *(const uint32_t*)(Qb + (size_t)gid       * Dm + d0 + 8);
            qa[kb][3] = *(const uint32_t*)(Qb + (size_t)(gid + 8) * Dm + d0 + 8);
        }
    }

    float m_lo = -1e30f, m_hi = -1e30f;
    float l_lo = 0.f,    l_hi = 0.f;
    float o[4][4];
#pragma unroll
    for (int nb = 0; nb < 4; nb++)
#pragma unroll
        for (int i = 0; i < 4; i++) o[nb][i] = 0.f;

    const __half* Kb = K  + (size_t)b * HWk * Dm + h * HD;
    const __half* Vb = Vt + ((size_t)b * Dm + h * HD) * HWk;

    const int jbeg = sp * (HWk / NSPLIT);
    const int jend = jbeg + (HWk / NSPLIT);

    auto issueKV = [&](int st, int j0) {
        // K: 64 rows x 64B; thread: row=tid>>1, 32B at (tid&1)*32
        const uint32_t dk = ksbase + st * (64 * KS2 * 4) + (tid >> 1) * (KS2 * 4) + (tid & 1) * 32;
        const __half* sk = Kb + (size_t)(j0 + (tid >> 1)) * Dm + (tid & 1) * 16;
        cp16(dk, sk); cp16(dk + 16, sk + 8);
        // V: 32 rows (d) x 128B; thread: d=tid>>2, 32B at (tid&3)*32
        const uint32_t dv = vsbase + st * (32 * VS2 * 4) + (tid >> 2) * (VS2 * 4) + (tid & 3) * 32;
        const __half* sv = Vb + (size_t)(tid >> 2) * HWk + j0 + (tid & 3) * 16;
        cp16(dv, sv); cp16(dv + 16, sv + 8);
    };

    issueKV(0, jbeg);
    cp_commit();
    cp_wait0();
    __syncthreads();

    int stage = 0;
    for (int j0 = jbeg; j0 < jend; j0 += 64) {
        const bool more = (j0 + 64) < jend;
        if (more) { issueKV(stage ^ 1, j0 + 64); cp_commit(); }

        // ---- S = Q K^T (log2 domain) ----
        float s[8][4];
#pragma unroll
        for (int nb = 0; nb < 8; nb++)
#pragma unroll
            for (int i = 0; i < 4; i++) s[nb][i] = 0.f;

        const uint32_t ksb = ks0 + stage * (64 * KS2 * 4);
#pragma unroll
        for (int kb = 0; kb < 2; kb++) {
#pragma unroll
            for (int p = 0; p < 4; p++) {
                uint32_t bf[4];
                ldsm_x4(bf, ksb + (p * 16 * KS2 + kb * 8) * 4);
                mma_f16(s[2 * p    ], qa[kb], bf[0], bf[1]);
                mma_f16(s[2 * p + 1], qa[kb], bf[2], bf[3]);
            }
        }

        // ---- online softmax (exp2) ----
        float tmax_lo = -1e30f, tmax_hi = -1e30f;
#pragma unroll
        for (int nb = 0; nb < 8; nb++) {
            tmax_lo = fmaxf(tmax_lo, fmaxf(s[nb][0], s[nb][1]));
            tmax_hi = fmaxf(tmax_hi, fmaxf(s[nb][2], s[nb][3]));
        }
        tmax_lo = fmaxf(tmax_lo, __shfl_xor_sync(0xffffffffu, tmax_lo, 1));
        tmax_lo = fmaxf(tmax_lo, __shfl_xor_sync(0xffffffffu, tmax_lo, 2));
        tmax_hi = fmaxf(tmax_hi, __shfl_xor_sync(0xffffffffu, tmax_hi, 1));
        tmax_hi = fmaxf(tmax_hi, __shfl_xor_sync(0xffffffffu, tmax_hi, 2));

        const float mn_lo = fmaxf(m_lo, tmax_lo);
        const float mn_hi = fmaxf(m_hi, tmax_hi);
        const float al_lo = ex2f(m_lo - mn_lo);
        const float al_hi = ex2f(m_hi - mn_hi);
        m_lo = mn_lo; m_hi = mn_hi;
        l_lo *= al_lo; l_hi *= al_hi;
#pragma unroll
        for (int nb = 0; nb < 4; nb++) {
            o[nb][0] *= al_lo; o[nb][1] *= al_lo;
            o[nb][2] *= al_hi; o[nb][3] *= al_hi;
        }

        // ---- exp2 + O += P V ----
        const uint32_t vsb = vs0 + stage * (32 * VS2 * 4);
#pragma unroll
        for (int kb = 0; kb < 4; kb++) {
            const float p0 = ex2f(s[2 * kb    ][0] - mn_lo);
            const float p1 = ex2f(s[2 * kb    ][1] - mn_lo);
            const float p2 = ex2f(s[2 * kb    ][2] - mn_hi);
            const float p3 = ex2f(s[2 * kb    ][3] - mn_hi);
            const float r0 = ex2f(s[2 * kb + 1][0] - mn_lo);
            const float r1 = ex2f(s[2 * kb + 1][1] - mn_lo);
            const float r2 = ex2f(s[2 * kb + 1][2] - mn_hi);
            const float r3 = ex2f(s[2 * kb + 1][3] - mn_hi);
            l_lo += p0 + p1 + r0 + r1;
            l_hi += p2 + p3 + r2 + r3;
            uint32_t pa[4];
            pa[0] = f2h2(p0, p1);
            pa[1] = f2h2(p2, p3);
            pa[2] = f2h2(r0, r1);
            pa[3] = f2h2(r2, r3);
#pragma unroll
            for (int p = 0; p < 2; p++) {
                uint32_t bf[4];
                ldsm_x4(bf, vsb + (p * 16 * VS2 + kb * 8) * 4);
                mma_f16(o[2 * p    ], pa, bf[0], bf[1]);
                mma_f16(o[2 * p + 1], pa, bf[2], bf[3]);
            }
        }

        cp_wait0();
        __syncthreads();
        stage ^= 1;
    }

    l_lo += __shfl_xor_sync(0xffffffffu, l_lo, 1);
    l_lo += __shfl_xor_sync(0xffffffffu, l_lo, 2);
    l_hi += __shfl_xor_sync(0xffffffffu, l_hi, 1);
    l_hi += __shfl_xor_sync(0xffffffffu, l_hi, 2);

    const int row0 = (((b * NH + h) * NSPLIT) + sp) * Sq + q0 + warp * 16;
#pragma unroll
    for (int nb = 0; nb < 4; nb++) {
        *(float2*)(Po + (size_t)(row0 + gid)     * HD + nb * 8 + 2 * tig) =
            make_float2(o[nb][0], o[nb][1]);
        *(float2*)(Po + (size_t)(row0 + gid + 8) * HD + nb * 8 + 2 * tig) =
            make_float2(o[nb][2], o[nb][3]);
    }
    if (tig == 0) {
        Pm[row0 + gid]     = m_lo;  Pl[row0 + gid]     = l_lo;
        Pm[row0 + gid + 8] = m_hi;  Pl[row0 + gid + 8] = l_hi;
    }
}

// ---------------------------------------------------------------------------
// Launch
// ---------------------------------------------------------------------------
extern "C" void kernel_launch(void* const* d_in, const int* in_sizes, int n_in,
                              void* d_out, int out_size)
{
    const float* query = (const float*)d_in[0];
    const float* keyv  = (const float*)d_in[1];
    const float* Wq    = (const float*)d_in[2];
    const float* bq    = (const float*)d_in[3];
    const float* Wk    = (const float*)d_in[4];
    const float* bk    = (const float*)d_in[5];
    const float* Wv    = (const float*)d_in[6];
    const float* bv    = (const float*)d_in[7];
    const float* Wo    = (const float*)d_in[8];
    const float* bo    = (const float*)d_in[9];
    float* out = (float*)d_out;

    __half *dKVh, *dQih, *dWh, *dQh, *dK, *dVt;
    float *dPo, *dPm, *dPl;
    cudaGetSymbolAddress((void**)&dKVh, g_KVh);
    cudaGetSymbolAddress((void**)&dQih, g_Qih);
    cudaGetSymbolAddress((void**)&dWh,  g_Wh);
    cudaGetSymbolAddress((void**)&dQh,  g_Qh);
    cudaGetSymbolAddress((void**)&dK,   g_K);
    cudaGetSymbolAddress((void**)&dVt,  g_Vt);
    cudaGetSymbolAddress((void**)&dPo,  g_Po);
    cudaGetSymbolAddress((void**)&dPm,  g_Pm);
    cudaGetSymbolAddress((void**)&dPl,  g_Pl);

    // 0) fp32 -> fp16 conversions
    prep_half<<<1024, 256>>>(keyv, query, Wq, Wk, Wv, Wo);

    // 1) fused Q + K + V projections (one launch)
    {
        dim3 grid(HWk / 128, Dm / 128, Bsz * 2 + 1);
        gemm_proj_fused<<<grid, 256>>>(dKVh, dQih, dWh, bq, bk, bv, dK, dVt, dQh);
    }
    // 2) attention (split-KV x4)
    {
        dim3 grid(Sq / 64, NH, Bsz * NSPLIT);
        attn_mma<<<grid, 128>>>(dQh, dK, dVt, dPo, dPm, dPl);
    }
    // 3) output projection with fused 4-way combine -> d_out
    {
        dim3 grid((Bsz * Sq) / 64, Dm / 64);
        gemm_out_f16<<<grid, 256>>>(dPo, dPm, dPl, dWh + 3 * Dm * Dm, bo, out);
    }
}

// round 13
// speedup vs baseline: 2.5743x; 1.0064x over previous
#include <cuda_runtime.h>
#include <cuda_fp16.h>
#include <cstdint>

// Problem dims (fixed)
#define Dm   256
#define Bsz  4
#define Sq   512
#define HWk  4096
#define NH   8
#define HD   32
#define NSPLIT 4

// Scratch (no cudaMalloc allowed)
__device__ __half g_KVh[Bsz * Dm * HWk];          // kv half [b][k][m]
__device__ __half g_Qih[Bsz * Sq * Dm];           // query half
__device__ __half g_Wh[4 * Dm * Dm];              // Wq,Wk,Wv,Wo half
__device__ __half g_Qh[Bsz * Sq * Dm];            // projected Q (half, pre-scaled)
__device__ __half g_K [Bsz * HWk * Dm];           // projected K [b][hw][d]
__device__ __half g_Vt[Bsz * Dm * HWk];           // projected V transposed [b][d][hw]
__device__ __half g_Ah[Bsz * Sq * Dm];            // combined attention output (half)
__device__ float  g_Po[Bsz * NH * NSPLIT * Sq * HD];
__device__ float  g_Pm[Bsz * NH * NSPLIT * Sq];
__device__ float  g_Pl[Bsz * NH * NSPLIT * Sq];

__device__ __forceinline__ uint32_t f2h2(float x, float y) {
    __half2 h = __floats2half2_rn(x, y);
    return *reinterpret_cast<uint32_t*>(&h);
}
__device__ __forceinline__ float ex2f(float x) {
    float r;
    asm("ex2.approx.f32 %0, %1;" : "=f"(r) : "f"(x));
    return r;
}
__device__ __forceinline__ void mma_f16(float c[4], const uint32_t a[4],
                                        uint32_t b0, uint32_t b1) {
    asm volatile(
        "mma.sync.aligned.m16n8k16.row.col.f32.f16.f16.f32 "
        "{%0,%1,%2,%3}, {%4,%5,%6,%7}, {%8,%9}, {%0,%1,%2,%3};"
        : "+f"(c[0]), "+f"(c[1]), "+f"(c[2]), "+f"(c[3])
        : "r"(a[0]), "r"(a[1]), "r"(a[2]), "r"(a[3]), "r"(b0), "r"(b1));
}
__device__ __forceinline__ void ldsm_x4(uint32_t r[4], uint32_t addr) {
    asm volatile(
        "ldmatrix.sync.aligned.m8n8.x4.shared.b16 {%0,%1,%2,%3}, [%4];"
        : "=r"(r[0]), "=r"(r[1]), "=r"(r[2]), "=r"(r[3]) : "r"(addr));
}
__device__ __forceinline__ void ldsm_x4_t(uint32_t r[4], uint32_t addr) {
    asm volatile(
        "ldmatrix.sync.aligned.m8n8.x4.trans.shared.b16 {%0,%1,%2,%3}, [%4];"
        : "=r"(r[0]), "=r"(r[1]), "=r"(r[2]), "=r"(r[3]) : "r"(addr));
}
__device__ __forceinline__ uint32_t cvta_s(const void* p) {
    return (uint32_t)__cvta_generic_to_shared(p);
}
__device__ __forceinline__ void cp16(uint32_t dst, const void* src) {
    asm volatile("cp.async.cg.shared.global [%0], [%1], 16;"
                 :: "r"(dst), "l"(src));
}
__device__ __forceinline__ void cp_commit() {
    asm volatile("cp.async.commit_group;");
}
__device__ __forceinline__ void cp_wait0() {
    asm volatile("cp.async.wait_group 0;");
}

#define KS2 20    // [row][k2] half2 tiles
#define ATW 68    // proj KV A tile [k][m]
#define AQW 20    // proj Q A tile [m][k2]
#define VS2 36    // attn V [d][key] tile

// ---------------------------------------------------------------------------
// prep: fp32 -> fp16 conversions
// ---------------------------------------------------------------------------
__global__ void prep_half(const float* __restrict__ kv,
                          const float* __restrict__ query,
                          const float* __restrict__ Wq, const float* __restrict__ Wk,
                          const float* __restrict__ Wv, const float* __restrict__ Wo)
{
    const int idx = blockIdx.x * blockDim.x + threadIdx.x;
    const int stride = gridDim.x * blockDim.x;

    const int N1 = Bsz * Dm * HWk / 4;
    uint2* kvh = (uint2*)g_KVh;
    for (int i = idx; i < N1; i += stride) {
        float4 v = ((const float4*)kv)[i];
        kvh[i] = make_uint2(f2h2(v.x, v.y), f2h2(v.z, v.w));
    }
    const int N2 = Bsz * Sq * Dm / 4;
    uint2* qh = (uint2*)g_Qih;
    for (int i = idx; i < N2; i += stride) {
        float4 v = ((const float4*)query)[i];
        qh[i] = make_uint2(f2h2(v.x, v.y), f2h2(v.z, v.w));
    }
    const int N3 = Dm * Dm / 4;
    const float* Ws[4] = {Wq, Wk, Wv, Wo};
    for (int w = 0; w < 4; w++) {
        uint2* wh = (uint2*)(g_Wh + w * Dm * Dm);
        for (int i = idx; i < N3; i += stride) {
            float4 v = ((const float4*)Ws[w])[i];
            wh[i] = make_uint2(f2h2(v.x, v.y), f2h2(v.z, v.w));
        }
    }
}

// ---------------------------------------------------------------------------
// FUSED projections (unchanged from R12)
// ---------------------------------------------------------------------------
__global__ __launch_bounds__(256, 2)
void gemm_proj_fused(const __half* __restrict__ KVh, const __half* __restrict__ Qih,
                     const __half* __restrict__ Wh,
                     const float* __restrict__ bq, const float* __restrict__ bk,
                     const float* __restrict__ bv,
                     __half* __restrict__ Kout, __half* __restrict__ Vt,
                     __half* __restrict__ Qout)
{
    const int z = blockIdx.z;
    const bool isq = (z == 8);
    if (isq && blockIdx.x >= (Bsz * Sq) / 128) return;

    const int b = z >> 1;
    const int isv = z & 1;
    const __half* A;
    const __half* Wm;
    const float* bias;
    if (isq) { A = Qih; Wm = Wh; bias = bq; }
    else {
        A    = KVh + (size_t)b * Dm * HWk;
        Wm   = Wh + (size_t)(isv ? 2 : 1) * Dm * Dm;
        bias = isv ? bv : bk;
    }

    __shared__ uint32_t As2[2][2560];
    __shared__ uint32_t Ws2[2][128 * KS2];

    const int bm = blockIdx.x * 128;
    const int bn = blockIdx.y * 128;
    const int tid  = threadIdx.x;
    const int warp = tid >> 5;
    const int lane = tid & 31;
    const int gid  = lane >> 2;
    const int tig  = lane & 3;
    const int wm = (warp >> 1) * 32;
    const int wn = (warp & 1) * 64;

    const uint32_t asb = cvta_s(&As2[0][0]);
    const uint32_t wsb = cvta_s(&Ws2[0][0]);

    const int brow = ((lane >> 4) & 1) * 8 + (lane & 7);
    const int bchk = ((lane >> 3) & 1) * 4;
    const uint32_t ws0 = wsb + ((wn + brow) * KS2 + bchk) * 4;
    const int at_row = (lane & 7) + ((lane >> 4) & 1) * 8;
    const int at_mo  = ((lane >> 3) & 1) * 16;
    const int aq_row = (lane & 7) + ((lane >> 3) & 1) * 8;
    const int aq_co  = ((lane >> 4) & 1) * 16;

    float acc[2][8][4];
#pragma unroll
    for (int mf = 0; mf < 2; mf++)
#pragma unroll
        for (int nb = 0; nb < 8; nb++)
#pragma unroll
            for (int j = 0; j < 4; j++) acc[mf][nb][j] = 0.f;

    auto issueT = [&](int st, int k0) {
        const uint32_t stA = asb + st * 2560 * 4;
        const uint32_t stW = wsb + st * (128 * KS2 * 4);
        if (isq) {
            const uint32_t d = stA + (tid >> 1) * (AQW * 4) + (tid & 1) * 32;
            const __half* s = A + (size_t)(bm + (tid >> 1)) * Dm + k0 + (tid & 1) * 16;
            cp16(d, s); cp16(d + 16, s + 8);
        } else {
            const uint32_t d = stA + (tid >> 3) * (ATW * 4) + (tid & 7) * 32;
            const __half* s = A + (size_t)(k0 + (tid >> 3)) * HWk + bm + (tid & 7) * 16;
            cp16(d, s); cp16(d + 16, s + 8);
        }
        const uint32_t dw = stW + (tid >> 1) * (KS2 * 4) + (tid & 1) * 32;
        const __half* sw = Wm + (size_t)(bn + (tid >> 1)) * Dm + k0 + (tid & 1) * 16;
        cp16(dw, sw); cp16(dw + 16, sw + 8);
    };

    issueT(0, 0);
    cp_commit();
    cp_wait0();
    __syncthreads();

#pragma unroll
    for (int it = 0; it < 8; it++) {
        const int cur = it & 1;
        const bool more = (it + 1) < 8;
        if (more) { issueT(cur ^ 1, (it + 1) * 32); cp_commit(); }

        const uint32_t asc = asb + cur * 2560 * 4;
        const uint32_t wsc = ws0 + cur * (128 * KS2 * 4);
#pragma unroll
        for (int kb = 0; kb < 2; kb++) {
            uint32_t a[2][4];
            if (isq) {
#pragma unroll
                for (int mf = 0; mf < 2; mf++)
                    ldsm_x4(a[mf], asc + (wm + mf * 16 + aq_row) * (AQW * 4)
                                       + kb * 32 + aq_co);
            } else {
#pragma unroll
                for (int mf = 0; mf < 2; mf++)
                    ldsm_x4_t(a[mf], asc + (kb * 16 + at_row) * (ATW * 4)
                                         + (wm + mf * 16) * 2 + at_mo);
            }
#pragma unroll
            for (int p = 0; p < 4; p++) {
                uint32_t bf[4];
                ldsm_x4(bf, wsc + (p * 16 * KS2 + kb * 8) * 4);
                mma_f16(acc[0][2 * p    ], a[0], bf[0], bf[1]);
                mma_f16(acc[1][2 * p    ], a[1], bf[0], bf[1]);
                mma_f16(acc[0][2 * p + 1], a[0], bf[2], bf[3]);
                mma_f16(acc[1][2 * p + 1], a[1], bf[2], bf[3]);
            }
        }

        cp_wait0();
        __syncthreads();
    }

    if (isq) {
        const float scl = 0.17677669529663687f * 1.4426950408889634f;
#pragma unroll
        for (int mf = 0; mf < 2; mf++) {
            const int row = bm + wm + mf * 16 + gid;
#pragma unroll
            for (int nb = 0; nb < 8; nb++) {
                const int col = bn + wn + nb * 8 + 2 * tig;
                const float b0 = bias[col], b1 = bias[col + 1];
                *(uint32_t*)(Qout + (size_t)row * Dm + col) =
                    f2h2((acc[mf][nb][0] + b0) * scl, (acc[mf][nb][1] + b1) * scl);
                *(uint32_t*)(Qout + (size_t)(row + 8) * Dm + col) =
                    f2h2((acc[mf][nb][2] + b0) * scl, (acc[mf][nb][3] + b1) * scl);
            }
        }
    } else if (!isv) {
        __half* C = Kout + (size_t)b * HWk * Dm;
#pragma unroll
        for (int mf = 0; mf < 2; mf++) {
            const int row = bm + wm + mf * 16 + gid;
#pragma unroll
            for (int nb = 0; nb < 8; nb++) {
                const int col = bn + wn + nb * 8 + 2 * tig;
                const float b0 = bias[col], b1 = bias[col + 1];
                *(uint32_t*)(C + (size_t)row * Dm + col) =
                    f2h2(acc[mf][nb][0] + b0, acc[mf][nb][1] + b1);
                *(uint32_t*)(C + (size_t)(row + 8) * Dm + col) =
                    f2h2(acc[mf][nb][2] + b0, acc[mf][nb][3] + b1);
            }
        }
    } else {
        __half* C = Vt + (size_t)b * Dm * HWk;
#pragma unroll
        for (int mf = 0; mf < 2; mf++) {
            const int row = bm + wm + mf * 16 + gid;
#pragma unroll
            for (int nb = 0; nb < 8; nb++) {
                const int col = bn + wn + nb * 8 + 2 * tig;
                const float b0 = bias[col], b1 = bias[col + 1];
                C[(size_t)col       * HWk + row]     = __float2half_rn(acc[mf][nb][0] + b0);
                C[(size_t)(col + 1) * HWk + row]     = __float2half_rn(acc[mf][nb][1] + b1);
                C[(size_t)col       * HWk + row + 8] = __float2half_rn(acc[mf][nb][2] + b0);
                C[(size_t)(col + 1) * HWk + row + 8] = __float2half_rn(acc[mf][nb][3] + b1);
            }
        }
    }
}

// ---------------------------------------------------------------------------
// combine: 4-way split-softmax merge -> Ah (half, B*S x 256)
// thread handles 8 dims of one row.
// ---------------------------------------------------------------------------
__global__ __launch_bounds__(256)
void attn_combine(const float* __restrict__ Po, const float* __restrict__ Pm,
                  const float* __restrict__ Pl, __half* __restrict__ Ah)
{
    const int t = blockIdx.x * 256 + threadIdx.x;   // 2048*32 threads
    const int row = t >> 5;             // 0..2047
    const int dc  = (t & 31) * 8;       // dim offset 0..248
    const int b = row >> 9;
    const int q = row & (Sq - 1);
    const int h = dc >> 5;
    const int dof = dc & 31;

    const size_t i0 = (size_t)((b * NH + h) * NSPLIT) * Sq + q;
    float mv[NSPLIT], lv[NSPLIT];
    float m = -1e30f;
#pragma unroll
    for (int s = 0; s < NSPLIT; s++) {
        mv[s] = Pm[i0 + (size_t)s * Sq];
        lv[s] = Pl[i0 + (size_t)s * Sq];
        m = fmaxf(m, mv[s]);
    }
    float denom = 0.f;
    float wc[NSPLIT];
#pragma unroll
    for (int s = 0; s < NSPLIT; s++) {
        wc[s] = ex2f(mv[s] - m);
        denom += lv[s] * wc[s];
    }
    const float inv = 1.f / denom;
#pragma unroll
    for (int s = 0; s < NSPLIT; s++) wc[s] *= inv;

    float av[8];
#pragma unroll
    for (int j = 0; j < 8; j++) av[j] = 0.f;
#pragma unroll
    for (int s = 0; s < NSPLIT; s++) {
        const float* p = Po + (i0 + (size_t)s * Sq) * HD + dof;
        float4 v0 = *(const float4*)(p);
        float4 v1 = *(const float4*)(p + 4);
        av[0] += v0.x * wc[s]; av[1] += v0.y * wc[s];
        av[2] += v0.z * wc[s]; av[3] += v0.w * wc[s];
        av[4] += v1.x * wc[s]; av[5] += v1.y * wc[s];
        av[6] += v1.z * wc[s]; av[7] += v1.w * wc[s];
    }
    uint4 u;
    u.x = f2h2(av[0], av[1]); u.y = f2h2(av[2], av[3]);
    u.z = f2h2(av[4], av[5]); u.w = f2h2(av[6], av[7]);
    *(uint4*)(Ah + (size_t)row * Dm + dc) = u;
}

// ---------------------------------------------------------------------------
// O projection: pure cp.async half GEMM. BM=32, BN=64, 128 threads (4 warps,
// 2m x 2n, warp tile 16x32). Grid (64, 4) = 256 CTAs.
// ---------------------------------------------------------------------------
__global__ __launch_bounds__(128)
void gemm_out_f16(const __half* __restrict__ Ah, const __half* __restrict__ Woh,
                  const float* __restrict__ bias, float* __restrict__ C)
{
    __shared__ uint32_t As2[2][32 * KS2];
    __shared__ uint32_t Ws2[2][64 * KS2];

    const int bm = blockIdx.x * 32;
    const int bn = blockIdx.y * 64;
    const int tid  = threadIdx.x;
    const int warp = tid >> 5;
    const int lane = tid & 31;
    const int gid  = lane >> 2;
    const int tig  = lane & 3;
    const int wm = (warp >> 1) * 16;
    const int wn = (warp & 1) * 32;

    const uint32_t asbase = cvta_s(&As2[0][0]);
    const uint32_t wsbase = cvta_s(&Ws2[0][0]);
    const int brow = ((lane >> 4) & 1) * 8 + (lane & 7);
    const int bchk = ((lane >> 3) & 1) * 4;
    const int arow = ((lane >> 3) & 1) * 8 + (lane & 7);
    const int achk = ((lane >> 4) & 1) * 4;
    const uint32_t as0 = asbase + ((wm + arow) * KS2 + achk) * 4;
    const uint32_t ws0 = wsbase + ((wn + brow) * KS2 + bchk) * 4;

    float acc[4][4];
#pragma unroll
    for (int nb = 0; nb < 4; nb++)
#pragma unroll
        for (int j = 0; j < 4; j++) acc[nb][j] = 0.f;

    auto issueT = [&](int st, int k0) {
        // A: 32 rows x 64B; thread: row=tid>>2, 16B at (tid&3)*16
        const uint32_t da = asbase + st * (32 * KS2 * 4) + (tid >> 2) * (KS2 * 4) + (tid & 3) * 16;
        const __half* sa = Ah + (size_t)(bm + (tid >> 2)) * Dm + k0 + (tid & 3) * 8;
        cp16(da, sa);
        // W: 64 rows x 64B; thread: row=tid>>1, 32B at (tid&1)*32
        const uint32_t dw = wsbase + st * (64 * KS2 * 4) + (tid >> 1) * (KS2 * 4) + (tid & 1) * 32;
        const __half* sw = Woh + (size_t)(bn + (tid >> 1)) * Dm + k0 + (tid & 1) * 16;
        cp16(dw, sw); cp16(dw + 16, sw + 8);
    };

    issueT(0, 0);
    cp_commit();
    cp_wait0();
    __syncthreads();

#pragma unroll
    for (int it = 0; it < 8; it++) {
        const int cur = it & 1;
        const bool more = (it + 1) < 8;
        if (more) { issueT(cur ^ 1, (it + 1) * 32); cp_commit(); }

        const uint32_t asc = as0 + cur * (32 * KS2 * 4);
        const uint32_t wsc = ws0 + cur * (64 * KS2 * 4);
#pragma unroll
        for (int kb = 0; kb < 2; kb++) {
            uint32_t a[4];
            ldsm_x4(a, asc + kb * 8 * 4);
#pragma unroll
            for (int p = 0; p < 2; p++) {
                uint32_t bf[4];
                ldsm_x4(bf, wsc + (p * 16 * KS2 + kb * 8) * 4);
                mma_f16(acc[2 * p    ], a, bf[0], bf[1]);
                mma_f16(acc[2 * p + 1], a, bf[2], bf[3]);
            }
        }

        cp_wait0();
        __syncthreads();
    }

    const int row = bm + wm + gid;
#pragma unroll
    for (int nb = 0; nb < 4; nb++) {
        const int col = bn + wn + nb * 8 + 2 * tig;
        const float b0 = bias[col], b1 = bias[col + 1];
        *(float2*)(C + (size_t)row * Dm + col) =
            make_float2(acc[nb][0] + b0, acc[nb][1] + b1);
        *(float2*)(C + (size_t)(row + 8) * Dm + col) =
            make_float2(acc[nb][2] + b0, acc[nb][3] + b1);
    }
}

// ---------------------------------------------------------------------------
// fp16 flash attention, split-KV x4 (unchanged from R12)
// ---------------------------------------------------------------------------
__global__ __launch_bounds__(128)
void attn_mma(const __half* __restrict__ Qh, const __half* __restrict__ K,
              const __half* __restrict__ Vt, float* __restrict__ Po,
              float* __restrict__ Pm, float* __restrict__ Pl)
{
    const int h  = blockIdx.y;
    const int bz = blockIdx.z;
    const int b  = bz >> 2;
    const int sp = bz & 3;
    const int q0 = blockIdx.x * 64;

    __shared__ uint32_t Ks2[2][64][KS2];
    __shared__ uint32_t Vs2[2][32][VS2];

    const int tid  = threadIdx.x;
    const int warp = tid >> 5;
    const int lane = tid & 31;
    const int gid  = lane >> 2;
    const int tig  = lane & 3;

    const int brow = ((lane >> 4) & 1) * 8 + (lane & 7);
    const int bchk = ((lane >> 3) & 1) * 4;
    const uint32_t ksbase = cvta_s(&Ks2[0][0][0]);
    const uint32_t vsbase = cvta_s(&Vs2[0][0][0]);
    const uint32_t ks0 = ksbase + (brow * KS2 + bchk) * 4;
    const uint32_t vs0 = vsbase + (brow * VS2 + bchk) * 4;

    uint32_t qa[2][4];
    {
        const __half* Qb = Qh + ((size_t)(b * Sq + q0 + warp * 16)) * Dm + h * HD;
#pragma unroll
        for (int kb = 0; kb < 2; kb++) {
            const int d0 = kb * 16 + 2 * tig;
            qa[kb][0] = *(const uint32_t*)(Qb + (size_t)gid       * Dm + d0);
            qa[kb][1] = *(const uint32_t*)(Qb + (size_t)(gid + 8) * Dm + d0);
            qa[kb][2] = *(const uint32_t*)(Qb + (size_t)gid       * Dm + d0 + 8);
            qa[kb][3] = *(const uint32_t*)(Qb + (size_t)(gid + 8) * Dm + d0 + 8);
        }
    }

    float m_lo = -1e30f, m_hi = -1e30f;
    float l_lo = 0.f,    l_hi = 0.f;
    float o[4][4];
#pragma unroll
    for (int nb = 0; nb < 4; nb++)
#pragma unroll
        for (int i = 0; i < 4; i++) o[nb][i] = 0.f;

    const __half* Kb = K  + (size_t)b * HWk * Dm + h * HD;
    const __half* Vb = Vt + ((size_t)b * Dm + h * HD) * HWk;

    const int jbeg = sp * (HWk / NSPLIT);
    const int jend = jbeg + (HWk / NSPLIT);

    auto issueKV = [&](int st, int j0) {
        const uint32_t dk = ksbase + st * (64 * KS2 * 4) + (tid >> 1) * (KS2 * 4) + (tid & 1) * 32;
        const __half* sk = Kb + (size_t)(j0 + (tid >> 1)) * Dm + (tid & 1) * 16;
        cp16(dk, sk); cp16(dk + 16, sk + 8);
        const uint32_t dv = vsbase + st * (32 * VS2 * 4) + (tid >> 2) * (VS2 * 4) + (tid & 3) * 32;
        const __half* sv = Vb + (size_t)(tid >> 2) * HWk + j0 + (tid & 3) * 16;
        cp16(dv, sv); cp16(dv + 16, sv + 8);
    };

    issueKV(0, jbeg);
    cp_commit();
    cp_wait0();
    __syncthreads();

    int stage = 0;
    for (int j0 = jbeg; j0 < jend; j0 += 64) {
        const bool more = (j0 + 64) < jend;
        if (more) { issueKV(stage ^ 1, j0 + 64); cp_commit(); }

        float s[8][4];
#pragma unroll
        for (int nb = 0; nb < 8; nb++)
#pragma unroll
            for (int i = 0; i < 4; i++) s[nb][i] = 0.f;

        const uint32_t ksb = ks0 + stage * (64 * KS2 * 4);
#pragma unroll
        for (int kb = 0; kb < 2; kb++) {
#pragma unroll
            for (int p = 0; p < 4; p++) {
                uint32_t bf[4];
                ldsm_x4(bf, ksb + (p * 16 * KS2 + kb * 8) * 4);
                mma_f16(s[2 * p    ], qa[kb], bf[0], bf[1]);
                mma_f16(s[2 * p + 1], qa[kb], bf[2], bf[3]);
            }
        }

        float tmax_lo = -1e30f, tmax_hi = -1e30f;
#pragma unroll
        for (int nb = 0; nb < 8; nb++) {
            tmax_lo = fmaxf(tmax_lo, fmaxf(s[nb][0], s[nb][1]));
            tmax_hi = fmaxf(tmax_hi, fmaxf(s[nb][2], s[nb][3]));
        }
        tmax_lo = fmaxf(tmax_lo, __shfl_xor_sync(0xffffffffu, tmax_lo, 1));
        tmax_lo = fmaxf(tmax_lo, __shfl_xor_sync(0xffffffffu, tmax_lo, 2));
        tmax_hi = fmaxf(tmax_hi, __shfl_xor_sync(0xffffffffu, tmax_hi, 1));
        tmax_hi = fmaxf(tmax_hi, __shfl_xor_sync(0xffffffffu, tmax_hi, 2));

        const float mn_lo = fmaxf(m_lo, tmax_lo);
        const float mn_hi = fmaxf(m_hi, tmax_hi);
        const float al_lo = ex2f(m_lo - mn_lo);
        const float al_hi = ex2f(m_hi - mn_hi);
        m_lo = mn_lo; m_hi = mn_hi;
        l_lo *= al_lo; l_hi *= al_hi;
#pragma unroll
        for (int nb = 0; nb < 4; nb++) {
            o[nb][0] *= al_lo; o[nb][1] *= al_lo;
            o[nb][2] *= al_hi; o[nb][3] *= al_hi;
        }

        const uint32_t vsb = vs0 + stage * (32 * VS2 * 4);
#pragma unroll
        for (int kb = 0; kb < 4; kb++) {
            const float p0 = ex2f(s[2 * kb    ][0] - mn_lo);
            const float p1 = ex2f(s[2 * kb    ][1] - mn_lo);
            const float p2 = ex2f(s[2 * kb    ][2] - mn_hi);
            const float p3 = ex2f(s[2 * kb    ][3] - mn_hi);
            const float r0 = ex2f(s[2 * kb + 1][0] - mn_lo);
            const float r1 = ex2f(s[2 * kb + 1][1] - mn_lo);
            const float r2 = ex2f(s[2 * kb + 1][2] - mn_hi);
            const float r3 = ex2f(s[2 * kb + 1][3] - mn_hi);
            l_lo += p0 + p1 + r0 + r1;
            l_hi += p2 + p3 + r2 + r3;
            uint32_t pa[4];
            pa[0] = f2h2(p0, p1);
            pa[1] = f2h2(p2, p3);
            pa[2] = f2h2(r0, r1);
            pa[3] = f2h2(r2, r3);
#pragma unroll
            for (int p = 0; p < 2; p++) {
                uint32_t bf[4];
                ldsm_x4(bf, vsb + (p * 16 * VS2 + kb * 8) * 4);
                mma_f16(o[2 * p    ], pa, bf[0], bf[1]);
                mma_f16(o[2 * p + 1], pa, bf[2], bf[3]);
            }
        }

        cp_wait0();
        __syncthreads();
        stage ^= 1;
    }

    l_lo += __shfl_xor_sync(0xffffffffu, l_lo, 1);
    l_lo += __shfl_xor_sync(0xffffffffu, l_lo, 2);
    l_hi += __shfl_xor_sync(0xffffffffu, l_hi, 1);
    l_hi += __shfl_xor_sync(0xffffffffu, l_hi, 2);

    const int row0 = (((b * NH + h) * NSPLIT) + sp) * Sq + q0 + warp * 16;
#pragma unroll
    for (int nb = 0; nb < 4; nb++) {
        *(float2*)(Po + (size_t)(row0 + gid)     * HD + nb * 8 + 2 * tig) =
            make_float2(o[nb][0], o[nb][1]);
        *(float2*)(Po + (size_t)(row0 + gid + 8) * HD + nb * 8 + 2 * tig) =
            make_float2(o[nb][2], o[nb][3]);
    }
    if (tig == 0) {
        Pm[row0 + gid]     = m_lo;  Pl[row0 + gid]     = l_lo;
        Pm[row0 + gid + 8] = m_hi;  Pl[row0 + gid + 8] = l_hi;
    }
}

// ---------------------------------------------------------------------------
// Launch
// ---------------------------------------------------------------------------
extern "C" void kernel_launch(void* const* d_in, const int* in_sizes, int n_in,
                              void* d_out, int out_size)
{
    const float* query = (const float*)d_in[0];
    const float* keyv  = (const float*)d_in[1];
    const float* Wq    = (const float*)d_in[2];
    const float* bq    = (const float*)d_in[3];
    const float* Wk    = (const float*)d_in[4];
    const float* bk    = (const float*)d_in[5];
    const float* Wv    = (const float*)d_in[6];
    const float* bv    = (const float*)d_in[7];
    const float* Wo    = (const float*)d_in[8];
    const float* bo    = (const float*)d_in[9];
    float* out = (float*)d_out;

    __half *dKVh, *dQih, *dWh, *dQh, *dK, *dVt, *dAh;
    float *dPo, *dPm, *dPl;
    cudaGetSymbolAddress((void**)&dKVh, g_KVh);
    cudaGetSymbolAddress((void**)&dQih, g_Qih);
    cudaGetSymbolAddress((void**)&dWh,  g_Wh);
    cudaGetSymbolAddress((void**)&dQh,  g_Qh);
    cudaGetSymbolAddress((void**)&dK,   g_K);
    cudaGetSymbolAddress((void**)&dVt,  g_Vt);
    cudaGetSymbolAddress((void**)&dAh,  g_Ah);
    cudaGetSymbolAddress((void**)&dPo,  g_Po);
    cudaGetSymbolAddress((void**)&dPm,  g_Pm);
    cudaGetSymbolAddress((void**)&dPl,  g_Pl);

    prep_half<<<1024, 256>>>(keyv, query, Wq, Wk, Wv, Wo);
    {
        dim3 grid(HWk / 128, Dm / 128, Bsz * 2 + 1);
        gemm_proj_fused<<<grid, 256>>>(dKVh, dQih, dWh, bq, bk, bv, dK, dVt, dQh);
    }
    {
        dim3 grid(Sq / 64, NH, Bsz * NSPLIT);
        attn_mma<<<grid, 128>>>(dQh, dK, dVt, dPo, dPm, dPl);
    }
    attn_combine<<<(Bsz * Sq * 32) / 256, 256>>>(dPo, dPm, dPl, dAh);
    {
        dim3 grid((Bsz * Sq) / 32, Dm / 64);
        gemm_out_f16<<<grid, 128>>>(dAh, dWh + 3 * Dm * Dm, bo, out);
    }
}